// round 4
// baseline (speedup 1.0000x reference)
#include <cuda_runtime.h>
#include <cuda_bf16.h>
#include <math.h>

// Problem constants (fixed by setup_inputs)
#define NN 50000
#define EE 400000
#define CC 128
#define HH 4
#define GG 64
#define LL 4
#define HC 512   // H*C
#define MIDD 256 // C*(H/2)

#define NEG_SLOPE 0.2f
#define EPSN 1e-5f
#define INV_SQRT_C 0.08838834764831845f

// ---------------- scratch (static device globals; no allocation) ----------------
__device__ float d_h[(size_t)NN * CC];
__device__ float d_mask[NN];
__device__ float d_xin[(size_t)NN * CC];
__device__ float d_xl[(size_t)NN * HC];
__device__ float d_xr[(size_t)NN * HC];
__device__ float d_eattr[(size_t)EE * CC];   // edge_attr permuted to dst-sorted order
__device__ float d_ea[(size_t)EE * HC];
__device__ float d_esc[(size_t)EE * HH];     // scores -> normalized alphas in place
__device__ float g_out[(size_t)NN * HC];
__device__ float g_cr1[(size_t)NN * MIDD];
__device__ float g_cr[(size_t)NN * CC];
__device__ float g_s[NN];
__device__ float g_WmI[GG * CC];
__device__ float g_gmax[GG];
__device__ float g_gsum[GG];
__device__ float g_meanAcc[GG * CC];
__device__ float g_mean[GG * CC];
__device__ float g_varAcc[GG * CC];
__device__ float g_var[GG * CC];
__device__ float g_cntf[GG];
__device__ int g_deg[NN];
__device__ int g_fill[NN];
__device__ int g_rowptr[NN + 1];
__device__ int g_esrc[EE];
__device__ int g_edst[EE];
__device__ int g_eid[EE];
__device__ int g_blocksums[256];

// ---------------- helpers ----------------
__device__ __forceinline__ float warpRedSum(float v) {
#pragma unroll
    for (int o = 16; o; o >>= 1) v += __shfl_xor_sync(0xffffffffu, v, o);
    return v;
}
__device__ __forceinline__ float warpRedMax(float v) {
#pragma unroll
    for (int o = 16; o; o >>= 1) v = fmaxf(v, __shfl_xor_sync(0xffffffffu, v, o));
    return v;
}
__device__ __forceinline__ float geluf(float x) {
    float x3 = x * x * x;
    return 0.5f * x * (1.0f + tanhf(0.7978845608028654f * (x + 0.044715f * x3)));
}
__device__ __forceinline__ float lreluf(float x) {
    return x > 0.0f ? x : NEG_SLOPE * x;
}
__device__ __forceinline__ void atomicMaxF(float* a, float v) {
    if (v >= 0.0f) atomicMax((int*)a, __float_as_int(v));
    else atomicMin((unsigned int*)a, __float_as_uint(v));
}

// ---------------- init / utility kernels ----------------
__global__ void k_zero_int(int* p, int n) {
    int i = blockIdx.x * blockDim.x + threadIdx.x;
    if (i < n) p[i] = 0;
}
__global__ void k_zero_float(float* p, int n) {
    int i = blockIdx.x * blockDim.x + threadIdx.x;
    if (i < n) p[i] = 0.0f;
}
__global__ void k_copy4(float* __restrict__ dst, const float* __restrict__ src, int n4) {
    int i = blockIdx.x * blockDim.x + threadIdx.x;
    if (i < n4) ((float4*)dst)[i] = ((const float4*)src)[i];
}

// ---------------- CSR build ----------------
__global__ void k_deg(const int* __restrict__ dst) {
    int e = blockIdx.x * blockDim.x + threadIdx.x;
    if (e < EE) atomicAdd(&g_deg[dst[e]], 1);
}
__global__ void k_scanA() {
    __shared__ float s[256];
    int tid = threadIdx.x;
    int n = blockIdx.x * 256 + tid;
    float v = (n < NN) ? (float)g_deg[n] : 0.0f;
    s[tid] = v;
    __syncthreads();
#pragma unroll
    for (int off = 1; off < 256; off <<= 1) {
        float t = (tid >= off) ? s[tid - off] : 0.0f;
        __syncthreads();
        s[tid] += t;
        __syncthreads();
    }
    if (n < NN) g_rowptr[n + 1] = (int)s[tid];
    if (tid == 255) g_blocksums[blockIdx.x] = (int)s[255];
}
__global__ void k_scanB(int nb) {
    if (threadIdx.x == 0) {
        int run = 0;
        for (int b = 0; b < nb; b++) { int t = g_blocksums[b]; g_blocksums[b] = run; run += t; }
    }
}
__global__ void k_scanC() {
    int n = blockIdx.x * blockDim.x + threadIdx.x;
    if (n < NN) g_rowptr[n + 1] += g_blocksums[n / 256];
    if (n == 0) g_rowptr[0] = 0;
}
__global__ void k_scatter(const int* __restrict__ src, const int* __restrict__ dst) {
    int e = blockIdx.x * blockDim.x + threadIdx.x;
    if (e >= EE) return;
    int d = dst[e];
    int p = g_rowptr[d] + atomicAdd(&g_fill[d], 1);
    g_esrc[p] = src[e];
    g_edst[p] = d;
    g_eid[p] = e;
}
__global__ void k_permute_eattr(const float* __restrict__ eattr) {
    int idx = blockIdx.x * blockDim.x + threadIdx.x;  // over EE*32 float4s
    if (idx >= EE * 32) return;
    int j = idx >> 5, q = idx & 31;
    ((float4*)d_eattr)[(size_t)j * 32 + q] =
        ((const float4*)eattr)[(size_t)g_eid[j] * 32 + q];
}
__global__ void k_cnt(const int* __restrict__ batch) {
    int n = blockIdx.x * blockDim.x + threadIdx.x;
    if (n < NN) atomicAdd(&g_cntf[batch[n]], 1.0f);
}

// ---------------- SGEMM (128x128x8 tiling, fused bias + activation) ----------------
// ACT: 0=none, 1=gelu
template <int ACT>
__global__ void __launch_bounds__(256, 2)
sgemm_k(const float* __restrict__ A, const float* __restrict__ B,
        const float* __restrict__ bias, float* __restrict__ Cm,
        int M, int Nn, int K) {
    const int BM = 128, BN = 128, BK = 8, AT = BM + 4;
    __shared__ float As[BK * AT];
    __shared__ float Bs[BK * BN];
    int tid = threadIdx.x;
    int mBase = blockIdx.y * BM;
    int nBase = blockIdx.x * BN;
    int ty = tid >> 4, tx = tid & 15;
    int arow = tid >> 1, acol = (tid & 1) * 4;
    int brow = tid >> 5, bcol = (tid & 31) * 4;
    float acc[8][8];
#pragma unroll
    for (int i = 0; i < 8; i++)
#pragma unroll
        for (int j = 0; j < 8; j++) acc[i][j] = 0.0f;

    for (int k0 = 0; k0 < K; k0 += BK) {
        float4 av = make_float4(0.f, 0.f, 0.f, 0.f);
        int gr = mBase + arow;
        if (gr < M) av = *(const float4*)&A[(size_t)gr * K + k0 + acol];
        As[(acol + 0) * AT + arow] = av.x;
        As[(acol + 1) * AT + arow] = av.y;
        As[(acol + 2) * AT + arow] = av.z;
        As[(acol + 3) * AT + arow] = av.w;
        float4 bv = *(const float4*)&B[(size_t)(k0 + brow) * Nn + nBase + bcol];
        *(float4*)&Bs[brow * BN + bcol] = bv;
        __syncthreads();
#pragma unroll
        for (int k = 0; k < BK; k++) {
            float a[8], b[8];
#pragma unroll
            for (int i = 0; i < 8; i++) a[i] = As[k * AT + ty * 8 + i];
#pragma unroll
            for (int j = 0; j < 8; j++) b[j] = Bs[k * BN + tx * 8 + j];
#pragma unroll
            for (int i = 0; i < 8; i++)
#pragma unroll
                for (int j = 0; j < 8; j++) acc[i][j] += a[i] * b[j];
        }
        __syncthreads();
    }
#pragma unroll
    for (int i = 0; i < 8; i++) {
        int r = mBase + ty * 8 + i;
        if (r >= M) continue;
#pragma unroll
        for (int j = 0; j < 8; j++) {
            int c = nBase + tx * 8 + j;
            float v = acc[i][j];
            if (bias) v += bias[c];
            if (ACT == 1) v = geluf(v);
            Cm[(size_t)r * Nn + c] = v;
        }
    }
}

// ---------------- per-layer kernels ----------------
// WmI[g][k] = sum_c Wm[k][c] * instr[g][c]
__global__ void k_wmI(const float* __restrict__ Wm, const float* __restrict__ instr) {
    int g = blockIdx.x, k = threadIdx.x;
    const float* wr = Wm + (size_t)k * CC;
    const float* iv = instr + (size_t)g * CC;
    float s = 0.0f;
    for (int c = 0; c < CC; c++) s += wr[c] * iv[c];
    g_WmI[g * CC + k] = s;
}

// mask + x_in (warp per node)
__global__ void k_mask_xin(const int* __restrict__ batch) {
    int w = (blockIdx.x * blockDim.x + threadIdx.x) >> 5;
    int lane = threadIdx.x & 31;
    if (w >= NN) return;
    int g = batch[w];
    float4 hv = ((const float4*)&d_h[(size_t)w * CC])[lane];
    float4 wv = ((const float4*)&g_WmI[g * CC])[lane];
    float p = hv.x * wv.x + hv.y * wv.y + hv.z * wv.z + hv.w * wv.w;
    p = warpRedSum(p);
    float mk = 1.0f / (1.0f + expf(-p * INV_SQRT_C));
    if (lane == 0) d_mask[w] = mk;
    float4 o = make_float4(mk * hv.x, mk * hv.y, mk * hv.z, mk * hv.w);
    ((float4*)&d_xin[(size_t)w * CC])[lane] = o;
}

// edge attention scores (warp per sorted edge)
__global__ void k_edge_score(const float* __restrict__ att) {
    __shared__ float satt[HH * CC];
    int tid = threadIdx.x;
    for (int i = tid; i < HH * CC; i += blockDim.x) satt[i] = att[i];
    __syncthreads();
    int w = tid >> 5, lane = tid & 31;
    int j = blockIdx.x * 8 + w;
    if (j >= EE) return;
    int s = g_esrc[j], d = g_edst[j];
    const float4* xl4 = (const float4*)&d_xl[(size_t)s * HC];
    const float4* xr4 = (const float4*)&d_xr[(size_t)d * HC];
    const float4* ea4 = (const float4*)&d_ea[(size_t)j * HC];
#pragma unroll
    for (int h = 0; h < HH; h++) {
        int q = h * 32 + lane;
        float4 a = xl4[q], b = xr4[q], c = ea4[q];
        float4 at = *(const float4*)&satt[h * CC + lane * 4];
        float p = lreluf(a.x + b.x + c.x) * at.x + lreluf(a.y + b.y + c.y) * at.y +
                  lreluf(a.z + b.z + c.z) * at.z + lreluf(a.w + b.w + c.w) * at.w;
        p = warpRedSum(p);
        if (lane == 0) d_esc[(size_t)j * HH + h] = p;
    }
}

// per-dst-node softmax over incident edges (warp per node), normalizes d_esc in place
__global__ void k_edge_softmax() {
    int w = (blockIdx.x * blockDim.x + threadIdx.x) >> 5;
    int lane = threadIdx.x & 31;
    if (w >= NN) return;
    int j0 = g_rowptr[w], j1 = g_rowptr[w + 1];
    float m0 = -1e30f, m1 = -1e30f, m2 = -1e30f, m3 = -1e30f;
    for (int j = j0 + lane; j < j1; j += 32) {
        float4 e = *(const float4*)&d_esc[(size_t)j * 4];
        m0 = fmaxf(m0, e.x); m1 = fmaxf(m1, e.y); m2 = fmaxf(m2, e.z); m3 = fmaxf(m3, e.w);
    }
    m0 = warpRedMax(m0); m1 = warpRedMax(m1); m2 = warpRedMax(m2); m3 = warpRedMax(m3);
    float s0 = 0.f, s1 = 0.f, s2 = 0.f, s3 = 0.f;
    for (int j = j0 + lane; j < j1; j += 32) {
        float4 e = *(const float4*)&d_esc[(size_t)j * 4];
        e.x = expf(e.x - m0); e.y = expf(e.y - m1);
        e.z = expf(e.z - m2); e.w = expf(e.w - m3);
        s0 += e.x; s1 += e.y; s2 += e.z; s3 += e.w;
        *(float4*)&d_esc[(size_t)j * 4] = e;
    }
    s0 = warpRedSum(s0); s1 = warpRedSum(s1); s2 = warpRedSum(s2); s3 = warpRedSum(s3);
    float i0 = 1.0f / (s0 + 1e-16f), i1 = 1.0f / (s1 + 1e-16f);
    float i2 = 1.0f / (s2 + 1e-16f), i3 = 1.0f / (s3 + 1e-16f);
    for (int j = j0 + lane; j < j1; j += 32) {
        float4 e = *(const float4*)&d_esc[(size_t)j * 4];
        e.x *= i0; e.y *= i1; e.z *= i2; e.w *= i3;
        *(float4*)&d_esc[(size_t)j * 4] = e;
    }
}

// aggregate: out[n,h,c] = sum_j alpha[j,h] * xl[src_j, h, c]  (block=128 threads per node)
__global__ void k_aggregate() {
    int n = blockIdx.x;
    int c = threadIdx.x;
    int j0 = g_rowptr[n], j1 = g_rowptr[n + 1];
    float a0 = 0.f, a1 = 0.f, a2 = 0.f, a3 = 0.f;
    for (int j = j0; j < j1; j++) {
        float4 wgt = *(const float4*)&d_esc[(size_t)j * 4];
        const float* xl = &d_xl[(size_t)g_esrc[j] * HC];
        a0 += wgt.x * xl[c];
        a1 += wgt.y * xl[128 + c];
        a2 += wgt.z * xl[256 + c];
        a3 += wgt.w * xl[384 + c];
    }
    size_t o = (size_t)n * HC;
    g_out[o + c] = a0;
    g_out[o + 128 + c] = a1;
    g_out[o + 256 + c] = a2;
    g_out[o + 384 + c] = a3;
}

// per-layer graph-scope accumulator init
__global__ void k_init_graph() {
    int i = blockIdx.x * blockDim.x + threadIdx.x;
    if (i < GG * CC) { g_meanAcc[i] = 0.0f; g_varAcc[i] = 0.0f; }
    if (i < GG) { g_gmax[i] = -__int_as_float(0x7f800000); g_gsum[i] = 0.0f; }
}

// s[n] = dot(instr[batch[n]], cr[n]) * inv_sqrt_c ; atomicMax per graph
__global__ void k_sdpa_score(const float* __restrict__ instr, const int* __restrict__ batch) {
    int w = (blockIdx.x * blockDim.x + threadIdx.x) >> 5;
    int lane = threadIdx.x & 31;
    if (w >= NN) return;
    int g = batch[w];
    float4 iv = ((const float4*)&instr[(size_t)g * CC])[lane];
    float4 cv = ((const float4*)&g_cr[(size_t)w * CC])[lane];
    float p = iv.x * cv.x + iv.y * cv.y + iv.z * cv.z + iv.w * cv.w;
    p = warpRedSum(p) * INV_SQRT_C;
    if (lane == 0) {
        g_s[w] = p;
        atomicMaxF(&g_gmax[g], p);
    }
}
__global__ void k_sdpa_exp(const int* __restrict__ batch) {
    int n = blockIdx.x * blockDim.x + threadIdx.x;
    if (n >= NN) return;
    int g = batch[n];
    float e = expf(g_s[n] - g_gmax[g]);
    g_s[n] = e;
    atomicAdd(&g_gsum[g], e);
}
__global__ void k_sdpa_norm(const int* __restrict__ batch) {
    int n = blockIdx.x * blockDim.x + threadIdx.x;
    if (n >= NN) return;
    g_s[n] = g_s[n] / (g_gsum[batch[n]] + 1e-16f);
}

// scale cr by attention weight + accumulate per-graph mean (exploits sorted batch)
__global__ void k_scale_mean(const int* __restrict__ batch) {
    int c = threadIdx.x;  // 128
    int n0 = blockIdx.x * 64;
    int n1 = min(n0 + 64, NN);
    float acc = 0.0f;
    int curg = batch[n0];
    for (int n = n0; n < n1; n++) {
        int g = batch[n];
        float v = g_cr[(size_t)n * CC + c] * g_s[n];
        g_cr[(size_t)n * CC + c] = v;
        if (g != curg) { atomicAdd(&g_meanAcc[curg * CC + c], acc); acc = 0.0f; curg = g; }
        acc += v;
    }
    atomicAdd(&g_meanAcc[curg * CC + c], acc);
}
__global__ void k_mean_div() {
    int i = blockIdx.x * blockDim.x + threadIdx.x;
    if (i < GG * CC) g_mean[i] = g_meanAcc[i] / fmaxf(g_cntf[i / CC], 1.0f);
}
__global__ void k_var_acc(const int* __restrict__ batch, const float* __restrict__ alpha) {
    int c = threadIdx.x;
    int n0 = blockIdx.x * 64;
    int n1 = min(n0 + 64, NN);
    float al = alpha[c];
    float acc = 0.0f;
    int curg = batch[n0];
    for (int n = n0; n < n1; n++) {
        int g = batch[n];
        float v = g_cr[(size_t)n * CC + c] - al * g_mean[g * CC + c];
        if (g != curg) { atomicAdd(&g_varAcc[curg * CC + c], acc); acc = 0.0f; curg = g; }
        acc += v * v;
    }
    atomicAdd(&g_varAcc[curg * CC + c], acc);
}
__global__ void k_var_div() {
    int i = blockIdx.x * blockDim.x + threadIdx.x;
    if (i < GG * CC) g_var[i] = g_varAcc[i] / fmaxf(g_cntf[i / CC], 1.0f);
}
// normalize + residual + mask gate -> dst (d_h for layers 0..2, d_out on last)
__global__ void k_norm_resid(const int* __restrict__ batch, const float* __restrict__ alpha,
                             const float* __restrict__ gamma, const float* __restrict__ beta,
                             float* __restrict__ dstp) {
    int idx = blockIdx.x * blockDim.x + threadIdx.x;
    if (idx >= NN * CC) return;
    int n = idx >> 7, c = idx & 127;
    int g = batch[n];
    float sub = g_cr[idx] - alpha[c] * g_mean[g * CC + c];
    float v = gamma[c] * sub * rsqrtf(g_var[g * CC + c] + EPSN) + beta[c];
    dstp[idx] = d_mask[n] * (v + d_h[idx]);
}

// ---------------- launch ----------------
extern "C" void kernel_launch(void* const* d_in, const int* in_sizes, int n_in,
                              void* d_out, int out_size) {
    const float* x = (const float*)d_in[0];
    const int* eidx = (const int*)d_in[1];
    const float* instr = (const float*)d_in[2];
    // d_in[3] = global_language_feats (unused by reference)
    const float* eattr = (const float*)d_in[4];
    const int* batch = (const int*)d_in[5];
    const float* Wl = (const float*)d_in[6];
    const float* Wr = (const float*)d_in[7];
    const float* We = (const float*)d_in[8];
    const float* att = (const float*)d_in[9];
    const float* Wm = (const float*)d_in[10];
    const float* p1w = (const float*)d_in[11];
    const float* p1b = (const float*)d_in[12];
    const float* p2w = (const float*)d_in[13];
    const float* p2b = (const float*)d_in[14];
    const float* gng = (const float*)d_in[15];
    const float* gnb = (const float*)d_in[16];
    const float* gna = (const float*)d_in[17];
    const int* src = eidx;
    const int* dst = eidx + EE;
    float* outp = (float*)d_out;

    int* pdeg; cudaGetSymbolAddress((void**)&pdeg, g_deg);
    int* pfill; cudaGetSymbolAddress((void**)&pfill, g_fill);
    float* pcnt; cudaGetSymbolAddress((void**)&pcnt, g_cntf);
    float* ph; cudaGetSymbolAddress((void**)&ph, d_h);

    const int NB256 = (NN + 255) / 256;       // 196
    const int EB256 = (EE + 255) / 256;

    // ---- startup (runs every replay; deterministic) ----
    k_zero_int<<<NB256, 256>>>(pdeg, NN);
    k_zero_int<<<NB256, 256>>>(pfill, NN);
    k_zero_float<<<1, 64>>>(pcnt, GG);
    k_deg<<<EB256, 256>>>(dst);
    k_scanA<<<NB256, 256>>>();
    k_scanB<<<1, 32>>>(NB256);
    k_scanC<<<(NN + 255) / 256, 256>>>();
    k_scatter<<<EB256, 256>>>(src, dst);
    k_permute_eattr<<<(EE * 32 + 255) / 256, 256>>>(eattr);
    k_cnt<<<NB256, 256>>>(batch);
    k_copy4<<<((NN * CC / 4) + 255) / 256, 256>>>(ph, x, NN * CC / 4);

    float* pxin; cudaGetSymbolAddress((void**)&pxin, d_xin);
    float* pxl; cudaGetSymbolAddress((void**)&pxl, d_xl);
    float* pxr; cudaGetSymbolAddress((void**)&pxr, d_xr);
    float* pea; cudaGetSymbolAddress((void**)&pea, d_ea);
    float* peattr; cudaGetSymbolAddress((void**)&peattr, d_eattr);
    float* pout; cudaGetSymbolAddress((void**)&pout, g_out);
    float* pcr1; cudaGetSymbolAddress((void**)&pcr1, g_cr1);
    float* pcr; cudaGetSymbolAddress((void**)&pcr, g_cr);

    for (int i = 0; i < LL; i++) {
        const float* Wm_i = Wm + (size_t)i * CC * CC;
        const float* instr_i = instr + (size_t)i * GG * CC;
        const float* Wl_i = Wl + (size_t)i * CC * HC;
        const float* Wr_i = Wr + (size_t)i * CC * HC;
        const float* We_i = We + (size_t)i * CC * HC;
        const float* att_i = att + (size_t)i * HH * CC;
        const float* p1w_i = p1w + (size_t)i * HC * MIDD;
        const float* p1b_i = p1b + (size_t)i * MIDD;
        const float* p2w_i = p2w + (size_t)i * MIDD * CC;
        const float* p2b_i = p2b + (size_t)i * CC;
        const float* gng_i = gng + (size_t)i * CC;
        const float* gnb_i = gnb + (size_t)i * CC;
        const float* gna_i = gna + (size_t)i * CC;

        // mask + x_in
        k_wmI<<<GG, CC>>>(Wm_i, instr_i);
        k_mask_xin<<<(NN * 32 + 255) / 256, 256>>>(batch);

        // projections
        dim3 gxl(HC / 128, (NN + 127) / 128);
        sgemm_k<0><<<gxl, 256>>>(pxin, Wl_i, nullptr, pxl, NN, HC, CC);
        sgemm_k<0><<<gxl, 256>>>(pxin, Wr_i, nullptr, pxr, NN, HC, CC);
        dim3 gea(HC / 128, (EE + 127) / 128);
        sgemm_k<0><<<gea, 256>>>(peattr, We_i, nullptr, pea, EE, HC, CC);

        // attention
        k_edge_score<<<(EE + 7) / 8, 256>>>(att_i);
        k_edge_softmax<<<(NN * 32 + 255) / 256, 256>>>();
        k_aggregate<<<NN, 128>>>();

        // MLP
        dim3 gp1(MIDD / 128, (NN + 127) / 128);
        sgemm_k<1><<<gp1, 256>>>(pout, p1w_i, p1b_i, pcr1, NN, MIDD, HC);
        dim3 gp2(CC / 128, (NN + 127) / 128);
        sgemm_k<1><<<gp2, 256>>>(pcr1, p2w_i, p2b_i, pcr, NN, CC, MIDD);

        // scatter attention + GraphNorm
        k_init_graph<<<(GG * CC + 255) / 256, 256>>>();
        k_sdpa_score<<<(NN * 32 + 255) / 256, 256>>>(instr_i, batch);
        k_sdpa_exp<<<NB256, 256>>>(batch);
        k_sdpa_norm<<<NB256, 256>>>(batch);
        k_scale_mean<<<(NN + 63) / 64, 128>>>(batch);
        k_mean_div<<<(GG * CC + 255) / 256, 256>>>();
        k_var_acc<<<(NN + 63) / 64, 128>>>(batch, gna_i);
        k_var_div<<<(GG * CC + 255) / 256, 256>>>();
        float* dstp = (i == LL - 1) ? outp : ph;
        k_norm_resid<<<(NN * CC + 255) / 256, 256>>>(batch, gna_i, gng_i, gnb_i, dstp);
    }
    (void)in_sizes; (void)n_in; (void)out_size;
}

// round 5
// speedup vs baseline: 2.0586x; 2.0586x over previous
#include <cuda_runtime.h>
#include <cuda_bf16.h>
#include <math.h>

// Problem constants (fixed by setup_inputs)
#define NN 50000
#define EE 400000
#define CC 128
#define HH 4
#define GG 64
#define LL 4
#define HC 512   // H*C
#define MIDD 256 // C*(H/2)

#define NEG_SLOPE 0.2f
#define EPSN 1e-5f
#define INV_SQRT_C 0.08838834764831845f

// ---------------- scratch (static device globals; no allocation) ----------------
__device__ float d_h[(size_t)NN * CC];
__device__ float d_mask[NN];
__device__ float d_xin[(size_t)NN * CC];
__device__ float d_xl[(size_t)NN * HC];
__device__ float d_xr[(size_t)NN * HC];
__device__ float d_eattr[(size_t)EE * CC];   // edge_attr permuted to dst-sorted order
__device__ float d_ea[(size_t)EE * HC];
__device__ float d_esc[(size_t)EE * HH];     // scores -> normalized alphas in place
__device__ float g_out[(size_t)NN * HC];
__device__ float g_cr1[(size_t)NN * MIDD];
__device__ float g_cr[(size_t)NN * CC];
__device__ float g_s[NN];
__device__ float g_WmI[GG * CC];
__device__ float g_gmax[GG];
__device__ float g_gsum[GG];
__device__ float g_meanAcc[GG * CC];
__device__ float g_mean[GG * CC];
__device__ float g_varAcc[GG * CC];
__device__ float g_var[GG * CC];
__device__ float g_cntf[GG];
__device__ int g_deg[NN];
__device__ int g_fill[NN];
__device__ int g_rowptr[NN + 1];
__device__ int g_esrc[EE];
__device__ int g_edst[EE];
__device__ int g_eid[EE];
__device__ int g_blocksums[256];

// ---------------- helpers ----------------
__device__ __forceinline__ float warpRedSum(float v) {
#pragma unroll
    for (int o = 16; o; o >>= 1) v += __shfl_xor_sync(0xffffffffu, v, o);
    return v;
}
__device__ __forceinline__ float warpRedMax(float v) {
#pragma unroll
    for (int o = 16; o; o >>= 1) v = fmaxf(v, __shfl_xor_sync(0xffffffffu, v, o));
    return v;
}
__device__ __forceinline__ float geluf(float x) {
    float x3 = x * x * x;
    return 0.5f * x * (1.0f + tanhf(0.7978845608028654f * (x + 0.044715f * x3)));
}
__device__ __forceinline__ float lreluf(float x) {
    return x > 0.0f ? x : NEG_SLOPE * x;
}
__device__ __forceinline__ void atomicMaxF(float* a, float v) {
    if (v >= 0.0f) atomicMax((int*)a, __float_as_int(v));
    else atomicMin((unsigned int*)a, __float_as_uint(v));
}
__device__ __forceinline__ unsigned f2tf32(float x) {
    unsigned r;
    asm("cvt.rna.tf32.f32 %0, %1;" : "=r"(r) : "f"(x));
    return r;
}
__device__ __forceinline__ void mma_tf32(float* d, const unsigned* a, const unsigned* b) {
    asm volatile(
        "mma.sync.aligned.m16n8k8.row.col.f32.tf32.tf32.f32 "
        "{%0,%1,%2,%3}, {%4,%5,%6,%7}, {%8,%9}, {%0,%1,%2,%3};\n"
        : "+f"(d[0]), "+f"(d[1]), "+f"(d[2]), "+f"(d[3])
        : "r"(a[0]), "r"(a[1]), "r"(a[2]), "r"(a[3]), "r"(b[0]), "r"(b[1]));
}

// ---------------- init / utility kernels ----------------
__global__ void k_zero_int(int* p, int n) {
    int i = blockIdx.x * blockDim.x + threadIdx.x;
    if (i < n) p[i] = 0;
}
__global__ void k_zero_float(float* p, int n) {
    int i = blockIdx.x * blockDim.x + threadIdx.x;
    if (i < n) p[i] = 0.0f;
}
__global__ void k_copy4(float* __restrict__ dst, const float* __restrict__ src, int n4) {
    int i = blockIdx.x * blockDim.x + threadIdx.x;
    if (i < n4) ((float4*)dst)[i] = ((const float4*)src)[i];
}

// ---------------- CSR build ----------------
__global__ void k_deg(const int* __restrict__ dst) {
    int e = blockIdx.x * blockDim.x + threadIdx.x;
    if (e < EE) atomicAdd(&g_deg[dst[e]], 1);
}
__global__ void k_scanA() {
    __shared__ float s[256];
    int tid = threadIdx.x;
    int n = blockIdx.x * 256 + tid;
    float v = (n < NN) ? (float)g_deg[n] : 0.0f;
    s[tid] = v;
    __syncthreads();
#pragma unroll
    for (int off = 1; off < 256; off <<= 1) {
        float t = (tid >= off) ? s[tid - off] : 0.0f;
        __syncthreads();
        s[tid] += t;
        __syncthreads();
    }
    if (n < NN) g_rowptr[n + 1] = (int)s[tid];
    if (tid == 255) g_blocksums[blockIdx.x] = (int)s[255];
}
__global__ void k_scanB(int nb) {
    if (threadIdx.x == 0) {
        int run = 0;
        for (int b = 0; b < nb; b++) { int t = g_blocksums[b]; g_blocksums[b] = run; run += t; }
    }
}
__global__ void k_scanC() {
    int n = blockIdx.x * blockDim.x + threadIdx.x;
    if (n < NN) g_rowptr[n + 1] += g_blocksums[n / 256];
    if (n == 0) g_rowptr[0] = 0;
}
__global__ void k_scatter(const int* __restrict__ src, const int* __restrict__ dst) {
    int e = blockIdx.x * blockDim.x + threadIdx.x;
    if (e >= EE) return;
    int d = dst[e];
    int p = g_rowptr[d] + atomicAdd(&g_fill[d], 1);
    g_esrc[p] = src[e];
    g_edst[p] = d;
    g_eid[p] = e;
}
__global__ void k_permute_eattr(const float* __restrict__ eattr) {
    int idx = blockIdx.x * blockDim.x + threadIdx.x;  // over EE*32 float4s
    if (idx >= EE * 32) return;
    int j = idx >> 5, q = idx & 31;
    ((float4*)d_eattr)[(size_t)j * 32 + q] =
        ((const float4*)eattr)[(size_t)g_eid[j] * 32 + q];
}
__global__ void k_cnt(const int* __restrict__ batch) {
    int n = blockIdx.x * blockDim.x + threadIdx.x;
    if (n < NN) atomicAdd(&g_cntf[batch[n]], 1.0f);
}

// ---------------- TF32 tensor-core GEMM ----------------
// C[M,Nn] = A[M,K] @ B[K,Nn]  (row-major), fused bias + optional gelu.
// Block tile 128x128x32. 8 warps, each 64x32 warp tile, mma.m16n8k8.tf32.
// Requires: Nn % 128 == 0, K % 32 == 0. M guarded.
template <int ACT>
__global__ void __launch_bounds__(256, 2)
tgemm_k(const float* __restrict__ A, const float* __restrict__ B,
        const float* __restrict__ bias, float* __restrict__ Cm,
        int M, int Nn, int K) {
    __shared__ unsigned As[32][132];  // [k][m], pad 4
    __shared__ unsigned Bs[32][132];  // [k][n], pad 4

    const int tid = threadIdx.x;
    const int warpId = tid >> 5;
    const int lane = tid & 31;
    const int g = lane >> 2, tig = lane & 3;
    const int mBase = blockIdx.y * 128;
    const int nBase = blockIdx.x * 128;
    const int mW = (warpId >> 2) * 64;  // 0 or 64
    const int nW = (warpId & 3) * 32;   // 0..96

    float acc[4][4][4];
#pragma unroll
    for (int mt = 0; mt < 4; mt++)
#pragma unroll
        for (int nt = 0; nt < 4; nt++)
#pragma unroll
            for (int q = 0; q < 4; q++) acc[mt][nt][q] = 0.0f;

    for (int k0 = 0; k0 < K; k0 += 32) {
        // load A tile (128 rows x 32 k) -> As[k][m], converting to tf32
#pragma unroll
        for (int p = 0; p < 4; p++) {
            int f4 = tid + p * 256;          // 1024 float4s
            int row = f4 >> 3;               // 0..127
            int c4 = f4 & 7;                 // 0..7
            int gr = mBase + row;
            float4 av = make_float4(0.f, 0.f, 0.f, 0.f);
            if (gr < M) av = *(const float4*)&A[(size_t)gr * K + k0 + c4 * 4];
            As[c4 * 4 + 0][row] = f2tf32(av.x);
            As[c4 * 4 + 1][row] = f2tf32(av.y);
            As[c4 * 4 + 2][row] = f2tf32(av.z);
            As[c4 * 4 + 3][row] = f2tf32(av.w);
        }
        // load B tile (32 k x 128 n) -> Bs[k][n]
#pragma unroll
        for (int p = 0; p < 4; p++) {
            int f4 = tid + p * 256;
            int krow = f4 >> 5;              // 0..31
            int c4 = f4 & 31;                // 0..31
            float4 bv = *(const float4*)&B[(size_t)(k0 + krow) * Nn + nBase + c4 * 4];
            Bs[krow][c4 * 4 + 0] = f2tf32(bv.x);
            Bs[krow][c4 * 4 + 1] = f2tf32(bv.y);
            Bs[krow][c4 * 4 + 2] = f2tf32(bv.z);
            Bs[krow][c4 * 4 + 3] = f2tf32(bv.w);
        }
        __syncthreads();

#pragma unroll
        for (int oct = 0; oct < 4; oct++) {
            int kb = oct * 8;
            unsigned bf[4][2];
#pragma unroll
            for (int nt = 0; nt < 4; nt++) {
                int nc = nW + nt * 8 + g;
                bf[nt][0] = Bs[kb + tig][nc];
                bf[nt][1] = Bs[kb + tig + 4][nc];
            }
            unsigned af[4][4];
#pragma unroll
            for (int mt = 0; mt < 4; mt++) {
                int m0 = mW + mt * 16 + g;
                af[mt][0] = As[kb + tig][m0];
                af[mt][1] = As[kb + tig][m0 + 8];
                af[mt][2] = As[kb + tig + 4][m0];
                af[mt][3] = As[kb + tig + 4][m0 + 8];
            }
#pragma unroll
            for (int mt = 0; mt < 4; mt++)
#pragma unroll
                for (int nt = 0; nt < 4; nt++)
                    mma_tf32(acc[mt][nt], af[mt], bf[nt]);
        }
        __syncthreads();
    }

    // epilogue
#pragma unroll
    for (int mt = 0; mt < 4; mt++) {
        int r0 = mBase + mW + mt * 16 + g;
        int r1 = r0 + 8;
#pragma unroll
        for (int nt = 0; nt < 4; nt++) {
            int c0 = nBase + nW + nt * 8 + 2 * tig;
            float b0 = 0.f, b1 = 0.f;
            if (bias) { b0 = bias[c0]; b1 = bias[c0 + 1]; }
            float v0 = acc[mt][nt][0] + b0, v1 = acc[mt][nt][1] + b1;
            float v2 = acc[mt][nt][2] + b0, v3 = acc[mt][nt][3] + b1;
            if (ACT == 1) { v0 = geluf(v0); v1 = geluf(v1); v2 = geluf(v2); v3 = geluf(v3); }
            if (r0 < M) *(float2*)&Cm[(size_t)r0 * Nn + c0] = make_float2(v0, v1);
            if (r1 < M) *(float2*)&Cm[(size_t)r1 * Nn + c0] = make_float2(v2, v3);
        }
    }
}

// ---------------- per-layer kernels ----------------
// WmI[g][k] = sum_c Wm[k][c] * instr[g][c]
__global__ void k_wmI(const float* __restrict__ Wm, const float* __restrict__ instr) {
    int g = blockIdx.x, k = threadIdx.x;
    const float* wr = Wm + (size_t)k * CC;
    const float* iv = instr + (size_t)g * CC;
    float s = 0.0f;
    for (int c = 0; c < CC; c++) s += wr[c] * iv[c];
    g_WmI[g * CC + k] = s;
}

// mask + x_in (warp per node)
__global__ void k_mask_xin(const int* __restrict__ batch) {
    int w = (blockIdx.x * blockDim.x + threadIdx.x) >> 5;
    int lane = threadIdx.x & 31;
    if (w >= NN) return;
    int g = batch[w];
    float4 hv = ((const float4*)&d_h[(size_t)w * CC])[lane];
    float4 wv = ((const float4*)&g_WmI[g * CC])[lane];
    float p = hv.x * wv.x + hv.y * wv.y + hv.z * wv.z + hv.w * wv.w;
    p = warpRedSum(p);
    float mk = 1.0f / (1.0f + expf(-p * INV_SQRT_C));
    if (lane == 0) d_mask[w] = mk;
    float4 o = make_float4(mk * hv.x, mk * hv.y, mk * hv.z, mk * hv.w);
    ((float4*)&d_xin[(size_t)w * CC])[lane] = o;
}

// edge attention scores (warp per sorted edge)
__global__ void k_edge_score(const float* __restrict__ att) {
    __shared__ float satt[HH * CC];
    int tid = threadIdx.x;
    for (int i = tid; i < HH * CC; i += blockDim.x) satt[i] = att[i];
    __syncthreads();
    int w = tid >> 5, lane = tid & 31;
    int j = blockIdx.x * 8 + w;
    if (j >= EE) return;
    int s = g_esrc[j], d = g_edst[j];
    const float4* xl4 = (const float4*)&d_xl[(size_t)s * HC];
    const float4* xr4 = (const float4*)&d_xr[(size_t)d * HC];
    const float4* ea4 = (const float4*)&d_ea[(size_t)j * HC];
#pragma unroll
    for (int h = 0; h < HH; h++) {
        int q = h * 32 + lane;
        float4 a = xl4[q], b = xr4[q], c = ea4[q];
        float4 at = *(const float4*)&satt[h * CC + lane * 4];
        float p = lreluf(a.x + b.x + c.x) * at.x + lreluf(a.y + b.y + c.y) * at.y +
                  lreluf(a.z + b.z + c.z) * at.z + lreluf(a.w + b.w + c.w) * at.w;
        p = warpRedSum(p);
        if (lane == 0) d_esc[(size_t)j * HH + h] = p;
    }
}

// per-dst-node softmax over incident edges (warp per node), normalizes d_esc in place
__global__ void k_edge_softmax() {
    int w = (blockIdx.x * blockDim.x + threadIdx.x) >> 5;
    int lane = threadIdx.x & 31;
    if (w >= NN) return;
    int j0 = g_rowptr[w], j1 = g_rowptr[w + 1];
    float m0 = -1e30f, m1 = -1e30f, m2 = -1e30f, m3 = -1e30f;
    for (int j = j0 + lane; j < j1; j += 32) {
        float4 e = *(const float4*)&d_esc[(size_t)j * 4];
        m0 = fmaxf(m0, e.x); m1 = fmaxf(m1, e.y); m2 = fmaxf(m2, e.z); m3 = fmaxf(m3, e.w);
    }
    m0 = warpRedMax(m0); m1 = warpRedMax(m1); m2 = warpRedMax(m2); m3 = warpRedMax(m3);
    float s0 = 0.f, s1 = 0.f, s2 = 0.f, s3 = 0.f;
    for (int j = j0 + lane; j < j1; j += 32) {
        float4 e = *(const float4*)&d_esc[(size_t)j * 4];
        e.x = expf(e.x - m0); e.y = expf(e.y - m1);
        e.z = expf(e.z - m2); e.w = expf(e.w - m3);
        s0 += e.x; s1 += e.y; s2 += e.z; s3 += e.w;
        *(float4*)&d_esc[(size_t)j * 4] = e;
    }
    s0 = warpRedSum(s0); s1 = warpRedSum(s1); s2 = warpRedSum(s2); s3 = warpRedSum(s3);
    float i0 = 1.0f / (s0 + 1e-16f), i1 = 1.0f / (s1 + 1e-16f);
    float i2 = 1.0f / (s2 + 1e-16f), i3 = 1.0f / (s3 + 1e-16f);
    for (int j = j0 + lane; j < j1; j += 32) {
        float4 e = *(const float4*)&d_esc[(size_t)j * 4];
        e.x *= i0; e.y *= i1; e.z *= i2; e.w *= i3;
        *(float4*)&d_esc[(size_t)j * 4] = e;
    }
}

// aggregate: out[n,h,c] = sum_j alpha[j,h] * xl[src_j, h, c]  (block=128 threads per node)
__global__ void k_aggregate() {
    int n = blockIdx.x;
    int c = threadIdx.x;
    int j0 = g_rowptr[n], j1 = g_rowptr[n + 1];
    float a0 = 0.f, a1 = 0.f, a2 = 0.f, a3 = 0.f;
    for (int j = j0; j < j1; j++) {
        float4 wgt = *(const float4*)&d_esc[(size_t)j * 4];
        const float* xl = &d_xl[(size_t)g_esrc[j] * HC];
        a0 += wgt.x * xl[c];
        a1 += wgt.y * xl[128 + c];
        a2 += wgt.z * xl[256 + c];
        a3 += wgt.w * xl[384 + c];
    }
    size_t o = (size_t)n * HC;
    g_out[o + c] = a0;
    g_out[o + 128 + c] = a1;
    g_out[o + 256 + c] = a2;
    g_out[o + 384 + c] = a3;
}

// per-layer graph-scope accumulator init
__global__ void k_init_graph() {
    int i = blockIdx.x * blockDim.x + threadIdx.x;
    if (i < GG * CC) { g_meanAcc[i] = 0.0f; g_varAcc[i] = 0.0f; }
    if (i < GG) { g_gmax[i] = -__int_as_float(0x7f800000); g_gsum[i] = 0.0f; }
}

// s[n] = dot(instr[batch[n]], cr[n]) * inv_sqrt_c ; atomicMax per graph
__global__ void k_sdpa_score(const float* __restrict__ instr, const int* __restrict__ batch) {
    int w = (blockIdx.x * blockDim.x + threadIdx.x) >> 5;
    int lane = threadIdx.x & 31;
    if (w >= NN) return;
    int g = batch[w];
    float4 iv = ((const float4*)&instr[(size_t)g * CC])[lane];
    float4 cv = ((const float4*)&g_cr[(size_t)w * CC])[lane];
    float p = iv.x * cv.x + iv.y * cv.y + iv.z * cv.z + iv.w * cv.w;
    p = warpRedSum(p) * INV_SQRT_C;
    if (lane == 0) {
        g_s[w] = p;
        atomicMaxF(&g_gmax[g], p);
    }
}
__global__ void k_sdpa_exp(const int* __restrict__ batch) {
    int n = blockIdx.x * blockDim.x + threadIdx.x;
    if (n >= NN) return;
    int g = batch[n];
    float e = expf(g_s[n] - g_gmax[g]);
    g_s[n] = e;
    atomicAdd(&g_gsum[g], e);
}
__global__ void k_sdpa_norm(const int* __restrict__ batch) {
    int n = blockIdx.x * blockDim.x + threadIdx.x;
    if (n >= NN) return;
    g_s[n] = g_s[n] / (g_gsum[batch[n]] + 1e-16f);
}

// scale cr by attention weight + accumulate per-graph mean (exploits sorted batch)
__global__ void k_scale_mean(const int* __restrict__ batch) {
    int c = threadIdx.x;  // 128
    int n0 = blockIdx.x * 64;
    int n1 = min(n0 + 64, NN);
    float acc = 0.0f;
    int curg = batch[n0];
    for (int n = n0; n < n1; n++) {
        int g = batch[n];
        float v = g_cr[(size_t)n * CC + c] * g_s[n];
        g_cr[(size_t)n * CC + c] = v;
        if (g != curg) { atomicAdd(&g_meanAcc[curg * CC + c], acc); acc = 0.0f; curg = g; }
        acc += v;
    }
    atomicAdd(&g_meanAcc[curg * CC + c], acc);
}
__global__ void k_mean_div() {
    int i = blockIdx.x * blockDim.x + threadIdx.x;
    if (i < GG * CC) g_mean[i] = g_meanAcc[i] / fmaxf(g_cntf[i / CC], 1.0f);
}
__global__ void k_var_acc(const int* __restrict__ batch, const float* __restrict__ alpha) {
    int c = threadIdx.x;
    int n0 = blockIdx.x * 64;
    int n1 = min(n0 + 64, NN);
    float al = alpha[c];
    float acc = 0.0f;
    int curg = batch[n0];
    for (int n = n0; n < n1; n++) {
        int g = batch[n];
        float v = g_cr[(size_t)n * CC + c] - al * g_mean[g * CC + c];
        if (g != curg) { atomicAdd(&g_varAcc[curg * CC + c], acc); acc = 0.0f; curg = g; }
        acc += v * v;
    }
    atomicAdd(&g_varAcc[curg * CC + c], acc);
}
__global__ void k_var_div() {
    int i = blockIdx.x * blockDim.x + threadIdx.x;
    if (i < GG * CC) g_var[i] = g_varAcc[i] / fmaxf(g_cntf[i / CC], 1.0f);
}
// normalize + residual + mask gate -> dst (d_h for layers 0..2, d_out on last)
__global__ void k_norm_resid(const int* __restrict__ batch, const float* __restrict__ alpha,
                             const float* __restrict__ gamma, const float* __restrict__ beta,
                             float* __restrict__ dstp) {
    int idx = blockIdx.x * blockDim.x + threadIdx.x;
    if (idx >= NN * CC) return;
    int n = idx >> 7, c = idx & 127;
    int g = batch[n];
    float sub = g_cr[idx] - alpha[c] * g_mean[g * CC + c];
    float v = gamma[c] * sub * rsqrtf(g_var[g * CC + c] + EPSN) + beta[c];
    dstp[idx] = d_mask[n] * (v + d_h[idx]);
}

// ---------------- launch ----------------
extern "C" void kernel_launch(void* const* d_in, const int* in_sizes, int n_in,
                              void* d_out, int out_size) {
    const float* x = (const float*)d_in[0];
    const int* eidx = (const int*)d_in[1];
    const float* instr = (const float*)d_in[2];
    // d_in[3] = global_language_feats (unused by reference)
    const float* eattr = (const float*)d_in[4];
    const int* batch = (const int*)d_in[5];
    const float* Wl = (const float*)d_in[6];
    const float* Wr = (const float*)d_in[7];
    const float* We = (const float*)d_in[8];
    const float* att = (const float*)d_in[9];
    const float* Wm = (const float*)d_in[10];
    const float* p1w = (const float*)d_in[11];
    const float* p1b = (const float*)d_in[12];
    const float* p2w = (const float*)d_in[13];
    const float* p2b = (const float*)d_in[14];
    const float* gng = (const float*)d_in[15];
    const float* gnb = (const float*)d_in[16];
    const float* gna = (const float*)d_in[17];
    const int* src = eidx;
    const int* dst = eidx + EE;
    float* outp = (float*)d_out;

    int* pdeg; cudaGetSymbolAddress((void**)&pdeg, g_deg);
    int* pfill; cudaGetSymbolAddress((void**)&pfill, g_fill);
    float* pcnt; cudaGetSymbolAddress((void**)&pcnt, g_cntf);
    float* ph; cudaGetSymbolAddress((void**)&ph, d_h);

    const int NB256 = (NN + 255) / 256;       // 196
    const int EB256 = (EE + 255) / 256;

    // ---- startup (runs every replay; deterministic) ----
    k_zero_int<<<NB256, 256>>>(pdeg, NN);
    k_zero_int<<<NB256, 256>>>(pfill, NN);
    k_zero_float<<<1, 64>>>(pcnt, GG);
    k_deg<<<EB256, 256>>>(dst);
    k_scanA<<<NB256, 256>>>();
    k_scanB<<<1, 32>>>(NB256);
    k_scanC<<<(NN + 255) / 256, 256>>>();
    k_scatter<<<EB256, 256>>>(src, dst);
    k_permute_eattr<<<(EE * 32 + 255) / 256, 256>>>(eattr);
    k_cnt<<<NB256, 256>>>(batch);
    k_copy4<<<((NN * CC / 4) + 255) / 256, 256>>>(ph, x, NN * CC / 4);

    float* pxin; cudaGetSymbolAddress((void**)&pxin, d_xin);
    float* pxl; cudaGetSymbolAddress((void**)&pxl, d_xl);
    float* pxr; cudaGetSymbolAddress((void**)&pxr, d_xr);
    float* pea; cudaGetSymbolAddress((void**)&pea, d_ea);
    float* peattr; cudaGetSymbolAddress((void**)&peattr, d_eattr);
    float* pout; cudaGetSymbolAddress((void**)&pout, g_out);
    float* pcr1; cudaGetSymbolAddress((void**)&pcr1, g_cr1);
    float* pcr; cudaGetSymbolAddress((void**)&pcr, g_cr);

    for (int i = 0; i < LL; i++) {
        const float* Wm_i = Wm + (size_t)i * CC * CC;
        const float* instr_i = instr + (size_t)i * GG * CC;
        const float* Wl_i = Wl + (size_t)i * CC * HC;
        const float* Wr_i = Wr + (size_t)i * CC * HC;
        const float* We_i = We + (size_t)i * CC * HC;
        const float* att_i = att + (size_t)i * HH * CC;
        const float* p1w_i = p1w + (size_t)i * HC * MIDD;
        const float* p1b_i = p1b + (size_t)i * MIDD;
        const float* p2w_i = p2w + (size_t)i * MIDD * CC;
        const float* p2b_i = p2b + (size_t)i * CC;
        const float* gng_i = gng + (size_t)i * CC;
        const float* gnb_i = gnb + (size_t)i * CC;
        const float* gna_i = gna + (size_t)i * CC;

        // mask + x_in
        k_wmI<<<GG, CC>>>(Wm_i, instr_i);
        k_mask_xin<<<(NN * 32 + 255) / 256, 256>>>(batch);

        // projections (tf32 tensor cores)
        dim3 gxl(HC / 128, (NN + 127) / 128);
        tgemm_k<0><<<gxl, 256>>>(pxin, Wl_i, nullptr, pxl, NN, HC, CC);
        tgemm_k<0><<<gxl, 256>>>(pxin, Wr_i, nullptr, pxr, NN, HC, CC);
        dim3 gea(HC / 128, (EE + 127) / 128);
        tgemm_k<0><<<gea, 256>>>(peattr, We_i, nullptr, pea, EE, HC, CC);

        // attention
        k_edge_score<<<(EE + 7) / 8, 256>>>(att_i);
        k_edge_softmax<<<(NN * 32 + 255) / 256, 256>>>();
        k_aggregate<<<NN, 128>>>();

        // MLP (tf32 tensor cores)
        dim3 gp1(MIDD / 128, (NN + 127) / 128);
        tgemm_k<1><<<gp1, 256>>>(pout, p1w_i, p1b_i, pcr1, NN, MIDD, HC);
        dim3 gp2(CC / 128, (NN + 127) / 128);
        tgemm_k<1><<<gp2, 256>>>(pcr1, p2w_i, p2b_i, pcr, NN, CC, MIDD);

        // scatter attention + GraphNorm
        k_init_graph<<<(GG * CC + 255) / 256, 256>>>();
        k_sdpa_score<<<(NN * 32 + 255) / 256, 256>>>(instr_i, batch);
        k_sdpa_exp<<<NB256, 256>>>(batch);
        k_sdpa_norm<<<NB256, 256>>>(batch);
        k_scale_mean<<<(NN + 63) / 64, 128>>>(batch);
        k_mean_div<<<(GG * CC + 255) / 256, 256>>>();
        k_var_acc<<<(NN + 63) / 64, 128>>>(batch, gna_i);
        k_var_div<<<(GG * CC + 255) / 256, 256>>>();
        float* dstp = (i == LL - 1) ? outp : ph;
        k_norm_resid<<<(NN * CC + 255) / 256, 256>>>(batch, gna_i, gng_i, gnb_i, dstp);
    }
    (void)in_sizes; (void)n_in; (void)out_size;
}

// round 7
// speedup vs baseline: 2.2213x; 1.0791x over previous
#include <cuda_runtime.h>
#include <cuda_bf16.h>
#include <math.h>

// Problem constants (fixed by setup_inputs)
#define NN 50000
#define EE 400000
#define CC 128
#define HH 4
#define GG 64
#define LL 4
#define HC 512   // H*C
#define MIDD 256 // C*(H/2)

#define NEG_SLOPE 0.2f
#define EPSN 1e-5f
#define INV_SQRT_C 0.08838834764831845f

// ---------------- scratch (static device globals; no allocation) ----------------
__device__ float d_h[(size_t)NN * CC];
__device__ float d_mask[NN];
__device__ float d_xin[(size_t)NN * CC];
__device__ float d_xl[(size_t)NN * HC];
__device__ float d_xr[(size_t)NN * HC];
__device__ float d_eattr[(size_t)EE * CC];   // edge_attr permuted to dst-sorted order
__device__ float d_esc[(size_t)EE * HH];     // scores -> normalized alphas in place
__device__ float g_out[(size_t)NN * HC];
__device__ float g_cr1[(size_t)NN * MIDD];
__device__ float g_cr[(size_t)NN * CC];
__device__ float g_s[NN];
__device__ float g_WmI[GG * CC];
__device__ float g_gmax[GG];
__device__ float g_gsum[GG];
__device__ float g_meanAcc[GG * CC];
__device__ float g_mean[GG * CC];
__device__ float g_varAcc[GG * CC];
__device__ float g_var[GG * CC];
__device__ float g_cntf[GG];
__device__ int g_deg[NN];
__device__ int g_fill[NN];
__device__ int g_rowptr[NN + 1];
__device__ int g_esrc[EE];
__device__ int g_edst[EE];
__device__ int g_eid[EE];
__device__ int g_blocksums[256];

// ---------------- helpers ----------------
__device__ __forceinline__ float warpRedSum(float v) {
#pragma unroll
    for (int o = 16; o; o >>= 1) v += __shfl_xor_sync(0xffffffffu, v, o);
    return v;
}
__device__ __forceinline__ float warpRedMax(float v) {
#pragma unroll
    for (int o = 16; o; o >>= 1) v = fmaxf(v, __shfl_xor_sync(0xffffffffu, v, o));
    return v;
}
__device__ __forceinline__ float geluf(float x) {
    float x3 = x * x * x;
    return 0.5f * x * (1.0f + tanhf(0.7978845608028654f * (x + 0.044715f * x3)));
}
__device__ __forceinline__ float lreluf(float x) {
    return x > 0.0f ? x : NEG_SLOPE * x;
}
__device__ __forceinline__ void atomicMaxF(float* a, float v) {
    if (v >= 0.0f) atomicMax((int*)a, __float_as_int(v));
    else atomicMin((unsigned int*)a, __float_as_uint(v));
}
__device__ __forceinline__ unsigned f2tf32(float x) {
    unsigned r;
    asm("cvt.rna.tf32.f32 %0, %1;" : "=r"(r) : "f"(x));
    return r;
}
__device__ __forceinline__ void mma_tf32(float* d, const unsigned* a, const unsigned* b) {
    asm volatile(
        "mma.sync.aligned.m16n8k8.row.col.f32.tf32.tf32.f32 "
        "{%0,%1,%2,%3}, {%4,%5,%6,%7}, {%8,%9}, {%0,%1,%2,%3};\n"
        : "+f"(d[0]), "+f"(d[1]), "+f"(d[2]), "+f"(d[3])
        : "r"(a[0]), "r"(a[1]), "r"(a[2]), "r"(a[3]), "r"(b[0]), "r"(b[1]));
}

// ---------------- init / utility kernels ----------------
__global__ void k_zero_int(int* p, int n) {
    int i = blockIdx.x * blockDim.x + threadIdx.x;
    if (i < n) p[i] = 0;
}
__global__ void k_zero_float(float* p, int n) {
    int i = blockIdx.x * blockDim.x + threadIdx.x;
    if (i < n) p[i] = 0.0f;
}
__global__ void k_copy4(float* __restrict__ dst, const float* __restrict__ src, int n4) {
    int i = blockIdx.x * blockDim.x + threadIdx.x;
    if (i < n4) ((float4*)dst)[i] = ((const float4*)src)[i];
}

// ---------------- CSR build ----------------
__global__ void k_deg(const int* __restrict__ dst) {
    int e = blockIdx.x * blockDim.x + threadIdx.x;
    if (e < EE) atomicAdd(&g_deg[dst[e]], 1);
}
__global__ void k_scanA() {
    __shared__ float s[256];
    int tid = threadIdx.x;
    int n = blockIdx.x * 256 + tid;
    float v = (n < NN) ? (float)g_deg[n] : 0.0f;
    s[tid] = v;
    __syncthreads();
#pragma unroll
    for (int off = 1; off < 256; off <<= 1) {
        float t = (tid >= off) ? s[tid - off] : 0.0f;
        __syncthreads();
        s[tid] += t;
        __syncthreads();
    }
    if (n < NN) g_rowptr[n + 1] = (int)s[tid];
    if (tid == 255) g_blocksums[blockIdx.x] = (int)s[255];
}
__global__ void k_scanB(int nb) {
    if (threadIdx.x == 0) {
        int run = 0;
        for (int b = 0; b < nb; b++) { int t = g_blocksums[b]; g_blocksums[b] = run; run += t; }
    }
}
__global__ void k_scanC() {
    int n = blockIdx.x * blockDim.x + threadIdx.x;
    if (n < NN) g_rowptr[n + 1] += g_blocksums[n / 256];
    if (n == 0) g_rowptr[0] = 0;
}
__global__ void k_scatter(const int* __restrict__ src, const int* __restrict__ dst) {
    int e = blockIdx.x * blockDim.x + threadIdx.x;
    if (e >= EE) return;
    int d = dst[e];
    int p = g_rowptr[d] + atomicAdd(&g_fill[d], 1);
    g_esrc[p] = src[e];
    g_edst[p] = d;
    g_eid[p] = e;
}
__global__ void k_permute_eattr(const float* __restrict__ eattr) {
    int idx = blockIdx.x * blockDim.x + threadIdx.x;  // over EE*32 float4s
    if (idx >= EE * 32) return;
    int j = idx >> 5, q = idx & 31;
    ((float4*)d_eattr)[(size_t)j * 32 + q] =
        ((const float4*)eattr)[(size_t)g_eid[j] * 32 + q];
}
__global__ void k_cnt(const int* __restrict__ batch) {
    int n = blockIdx.x * blockDim.x + threadIdx.x;
    if (n < NN) atomicAdd(&g_cntf[batch[n]], 1.0f);
}

// ---------------- TF32 tensor-core GEMM ----------------
// C[M,Nn] = A[M,K] @ B[K,Nn]  (row-major), fused bias + optional gelu.
// Block tile 128x128x32. 8 warps, each 64x32 warp tile, mma.m16n8k8.tf32.
// Requires: Nn % 128 == 0, K % 32 == 0. M guarded.
template <int ACT>
__global__ void __launch_bounds__(256, 2)
tgemm_k(const float* __restrict__ A, const float* __restrict__ B,
        const float* __restrict__ bias, float* __restrict__ Cm,
        int M, int Nn, int K) {
    __shared__ unsigned As[32][132];  // [k][m], pad 4
    __shared__ unsigned Bs[32][132];  // [k][n], pad 4

    const int tid = threadIdx.x;
    const int warpId = tid >> 5;
    const int lane = tid & 31;
    const int g = lane >> 2, tig = lane & 3;
    const int mBase = blockIdx.y * 128;
    const int nBase = blockIdx.x * 128;
    const int mW = (warpId >> 2) * 64;  // 0 or 64
    const int nW = (warpId & 3) * 32;   // 0..96

    float acc[4][4][4];
#pragma unroll
    for (int mt = 0; mt < 4; mt++)
#pragma unroll
        for (int nt = 0; nt < 4; nt++)
#pragma unroll
            for (int q = 0; q < 4; q++) acc[mt][nt][q] = 0.0f;

    for (int k0 = 0; k0 < K; k0 += 32) {
        // load A tile (128 rows x 32 k) -> As[k][m], converting to tf32
#pragma unroll
        for (int p = 0; p < 4; p++) {
            int f4 = tid + p * 256;          // 1024 float4s
            int row = f4 >> 3;               // 0..127
            int c4 = f4 & 7;                 // 0..7
            int gr = mBase + row;
            float4 av = make_float4(0.f, 0.f, 0.f, 0.f);
            if (gr < M) av = *(const float4*)&A[(size_t)gr * K + k0 + c4 * 4];
            As[c4 * 4 + 0][row] = f2tf32(av.x);
            As[c4 * 4 + 1][row] = f2tf32(av.y);
            As[c4 * 4 + 2][row] = f2tf32(av.z);
            As[c4 * 4 + 3][row] = f2tf32(av.w);
        }
        // load B tile (32 k x 128 n) -> Bs[k][n]
#pragma unroll
        for (int p = 0; p < 4; p++) {
            int f4 = tid + p * 256;
            int krow = f4 >> 5;              // 0..31
            int c4 = f4 & 31;                // 0..31
            float4 bv = *(const float4*)&B[(size_t)(k0 + krow) * Nn + nBase + c4 * 4];
            Bs[krow][c4 * 4 + 0] = f2tf32(bv.x);
            Bs[krow][c4 * 4 + 1] = f2tf32(bv.y);
            Bs[krow][c4 * 4 + 2] = f2tf32(bv.z);
            Bs[krow][c4 * 4 + 3] = f2tf32(bv.w);
        }
        __syncthreads();

#pragma unroll
        for (int oct = 0; oct < 4; oct++) {
            int kb = oct * 8;
            unsigned bf[4][2];
#pragma unroll
            for (int nt = 0; nt < 4; nt++) {
                int nc = nW + nt * 8 + g;
                bf[nt][0] = Bs[kb + tig][nc];
                bf[nt][1] = Bs[kb + tig + 4][nc];
            }
            unsigned af[4][4];
#pragma unroll
            for (int mt = 0; mt < 4; mt++) {
                int m0 = mW + mt * 16 + g;
                af[mt][0] = As[kb + tig][m0];
                af[mt][1] = As[kb + tig][m0 + 8];
                af[mt][2] = As[kb + tig + 4][m0];
                af[mt][3] = As[kb + tig + 4][m0 + 8];
            }
#pragma unroll
            for (int mt = 0; mt < 4; mt++)
#pragma unroll
                for (int nt = 0; nt < 4; nt++)
                    mma_tf32(acc[mt][nt], af[mt], bf[nt]);
        }
        __syncthreads();
    }

    // epilogue
#pragma unroll
    for (int mt = 0; mt < 4; mt++) {
        int r0 = mBase + mW + mt * 16 + g;
        int r1 = r0 + 8;
#pragma unroll
        for (int nt = 0; nt < 4; nt++) {
            int c0 = nBase + nW + nt * 8 + 2 * tig;
            float b0 = 0.f, b1 = 0.f;
            if (bias) { b0 = bias[c0]; b1 = bias[c0 + 1]; }
            float v0 = acc[mt][nt][0] + b0, v1 = acc[mt][nt][1] + b1;
            float v2 = acc[mt][nt][2] + b0, v3 = acc[mt][nt][3] + b1;
            if (ACT == 1) { v0 = geluf(v0); v1 = geluf(v1); v2 = geluf(v2); v3 = geluf(v3); }
            if (r0 < M) *(float2*)&Cm[(size_t)r0 * Nn + c0] = make_float2(v0, v1);
            if (r1 < M) *(float2*)&Cm[(size_t)r1 * Nn + c0] = make_float2(v2, v3);
        }
    }
}

// ---------------- fused edge GEMM + attention score ----------------
// Computes ea = d_eattr @ We for a 128-edge x 128-channel (one head) tile,
// then immediately reduces e[j,h] = sum_c lrelu(ea + xl[src]+xr[dst]) * att[c]
// without ever materializing ea. Grid: (HH, EE/128). Requires EE % 128 == 0.
__global__ void __launch_bounds__(256, 2)
tgemm_score_k(const float* __restrict__ A, const float* __restrict__ B,
              const float* __restrict__ att) {
    __shared__ unsigned As[32][132];
    __shared__ unsigned Bs[32][132];
    __shared__ float satt[128];
    __shared__ int ssrc[128];
    __shared__ int sdst[128];
    __shared__ float sred[128];

    const int tid = threadIdx.x;
    const int warpId = tid >> 5;
    const int lane = tid & 31;
    const int g = lane >> 2, tig = lane & 3;
    const int nBase = blockIdx.x * 128;   // head * 128
    const int mBase = blockIdx.y * 128;   // edge tile
    const int mW = (warpId >> 2) * 64;
    const int nW = (warpId & 3) * 32;
    const int K = CC, Nn = HC;

    if (tid < 128) {
        satt[tid] = att[nBase + tid];
        ssrc[tid] = g_esrc[mBase + tid];
        sdst[tid] = g_edst[mBase + tid];
        sred[tid] = 0.0f;
    }

    float acc[4][4][4];
#pragma unroll
    for (int mt = 0; mt < 4; mt++)
#pragma unroll
        for (int nt = 0; nt < 4; nt++)
#pragma unroll
            for (int q = 0; q < 4; q++) acc[mt][nt][q] = 0.0f;

    for (int k0 = 0; k0 < K; k0 += 32) {
#pragma unroll
        for (int p = 0; p < 4; p++) {
            int f4 = tid + p * 256;
            int row = f4 >> 3;
            int c4 = f4 & 7;
            float4 av = *(const float4*)&A[(size_t)(mBase + row) * K + k0 + c4 * 4];
            As[c4 * 4 + 0][row] = f2tf32(av.x);
            As[c4 * 4 + 1][row] = f2tf32(av.y);
            As[c4 * 4 + 2][row] = f2tf32(av.z);
            As[c4 * 4 + 3][row] = f2tf32(av.w);
        }
#pragma unroll
        for (int p = 0; p < 4; p++) {
            int f4 = tid + p * 256;
            int krow = f4 >> 5;
            int c4 = f4 & 31;
            float4 bv = *(const float4*)&B[(size_t)(k0 + krow) * Nn + nBase + c4 * 4];
            Bs[krow][c4 * 4 + 0] = f2tf32(bv.x);
            Bs[krow][c4 * 4 + 1] = f2tf32(bv.y);
            Bs[krow][c4 * 4 + 2] = f2tf32(bv.z);
            Bs[krow][c4 * 4 + 3] = f2tf32(bv.w);
        }
        __syncthreads();
#pragma unroll
        for (int oct = 0; oct < 4; oct++) {
            int kb = oct * 8;
            unsigned bf[4][2];
#pragma unroll
            for (int nt = 0; nt < 4; nt++) {
                int nc = nW + nt * 8 + g;
                bf[nt][0] = Bs[kb + tig][nc];
                bf[nt][1] = Bs[kb + tig + 4][nc];
            }
            unsigned af[4][4];
#pragma unroll
            for (int mt = 0; mt < 4; mt++) {
                int m0 = mW + mt * 16 + g;
                af[mt][0] = As[kb + tig][m0];
                af[mt][1] = As[kb + tig][m0 + 8];
                af[mt][2] = As[kb + tig + 4][m0];
                af[mt][3] = As[kb + tig + 4][m0 + 8];
            }
#pragma unroll
            for (int mt = 0; mt < 4; mt++)
#pragma unroll
                for (int nt = 0; nt < 4; nt++)
                    mma_tf32(acc[mt][nt], af[mt], bf[nt]);
        }
        __syncthreads();
    }

    // fused score epilogue: partial over this thread's 8 cols for each of its 8 rows
#pragma unroll
    for (int mt = 0; mt < 4; mt++) {
        int lr0 = mW + mt * 16 + g;
        int lr1 = lr0 + 8;
        int s0 = ssrc[lr0], dd0 = sdst[lr0];
        int s1 = ssrc[lr1], dd1 = sdst[lr1];
        float p0 = 0.0f, p1 = 0.0f;
#pragma unroll
        for (int nt = 0; nt < 4; nt++) {
            int cl = nW + nt * 8 + 2 * tig;
            int cg = nBase + cl;
            float at0 = satt[cl], at1 = satt[cl + 1];
            float2 xa0 = *(const float2*)&d_xl[(size_t)s0 * HC + cg];
            float2 xb0 = *(const float2*)&d_xr[(size_t)dd0 * HC + cg];
            float2 xa1 = *(const float2*)&d_xl[(size_t)s1 * HC + cg];
            float2 xb1 = *(const float2*)&d_xr[(size_t)dd1 * HC + cg];
            p0 += lreluf(acc[mt][nt][0] + xa0.x + xb0.x) * at0 +
                  lreluf(acc[mt][nt][1] + xa0.y + xb0.y) * at1;
            p1 += lreluf(acc[mt][nt][2] + xa1.x + xb1.x) * at0 +
                  lreluf(acc[mt][nt][3] + xa1.y + xb1.y) * at1;
        }
        // quad reduce (lanes 4g..4g+3 share rows lr0/lr1)
        p0 += __shfl_xor_sync(0xffffffffu, p0, 1);
        p0 += __shfl_xor_sync(0xffffffffu, p0, 2);
        p1 += __shfl_xor_sync(0xffffffffu, p1, 1);
        p1 += __shfl_xor_sync(0xffffffffu, p1, 2);
        if (tig == 0) {
            atomicAdd(&sred[lr0], p0);
            atomicAdd(&sred[lr1], p1);
        }
    }
    __syncthreads();
    if (tid < 128)
        d_esc[(size_t)(mBase + tid) * HH + blockIdx.x] = sred[tid];
}

// ---------------- per-layer kernels ----------------
// WmI[g][k] = sum_c Wm[k][c] * instr[g][c]
__global__ void k_wmI(const float* __restrict__ Wm, const float* __restrict__ instr) {
    int g = blockIdx.x, k = threadIdx.x;
    const float* wr = Wm + (size_t)k * CC;
    const float* iv = instr + (size_t)g * CC;
    float s = 0.0f;
    for (int c = 0; c < CC; c++) s += wr[c] * iv[c];
    g_WmI[g * CC + k] = s;
}

// mask + x_in (warp per node)
__global__ void k_mask_xin(const int* __restrict__ batch) {
    int w = (blockIdx.x * blockDim.x + threadIdx.x) >> 5;
    int lane = threadIdx.x & 31;
    if (w >= NN) return;
    int g = batch[w];
    float4 hv = ((const float4*)&d_h[(size_t)w * CC])[lane];
    float4 wv = ((const float4*)&g_WmI[g * CC])[lane];
    float p = hv.x * wv.x + hv.y * wv.y + hv.z * wv.z + hv.w * wv.w;
    p = warpRedSum(p);
    float mk = 1.0f / (1.0f + expf(-p * INV_SQRT_C));
    if (lane == 0) d_mask[w] = mk;
    float4 o = make_float4(mk * hv.x, mk * hv.y, mk * hv.z, mk * hv.w);
    ((float4*)&d_xin[(size_t)w * CC])[lane] = o;
}

// per-dst-node softmax over incident edges (warp per node), normalizes d_esc in place
__global__ void k_edge_softmax() {
    int w = (blockIdx.x * blockDim.x + threadIdx.x) >> 5;
    int lane = threadIdx.x & 31;
    if (w >= NN) return;
    int j0 = g_rowptr[w], j1 = g_rowptr[w + 1];
    float m0 = -1e30f, m1 = -1e30f, m2 = -1e30f, m3 = -1e30f;
    for (int j = j0 + lane; j < j1; j += 32) {
        float4 e = *(const float4*)&d_esc[(size_t)j * 4];
        m0 = fmaxf(m0, e.x); m1 = fmaxf(m1, e.y); m2 = fmaxf(m2, e.z); m3 = fmaxf(m3, e.w);
    }
    m0 = warpRedMax(m0); m1 = warpRedMax(m1); m2 = warpRedMax(m2); m3 = warpRedMax(m3);
    float s0 = 0.f, s1 = 0.f, s2 = 0.f, s3 = 0.f;
    for (int j = j0 + lane; j < j1; j += 32) {
        float4 e = *(const float4*)&d_esc[(size_t)j * 4];
        e.x = expf(e.x - m0); e.y = expf(e.y - m1);
        e.z = expf(e.z - m2); e.w = expf(e.w - m3);
        s0 += e.x; s1 += e.y; s2 += e.z; s3 += e.w;
        *(float4*)&d_esc[(size_t)j * 4] = e;
    }
    s0 = warpRedSum(s0); s1 = warpRedSum(s1); s2 = warpRedSum(s2); s3 = warpRedSum(s3);
    float i0 = 1.0f / (s0 + 1e-16f), i1 = 1.0f / (s1 + 1e-16f);
    float i2 = 1.0f / (s2 + 1e-16f), i3 = 1.0f / (s3 + 1e-16f);
    for (int j = j0 + lane; j < j1; j += 32) {
        float4 e = *(const float4*)&d_esc[(size_t)j * 4];
        e.x *= i0; e.y *= i1; e.z *= i2; e.w *= i3;
        *(float4*)&d_esc[(size_t)j * 4] = e;
    }
}

// aggregate: out[n,h,c] = sum_j alpha[j,h] * xl[src_j, h, c]  (block=128 threads per node)
__global__ void k_aggregate() {
    int n = blockIdx.x;
    int c = threadIdx.x;
    int j0 = g_rowptr[n], j1 = g_rowptr[n + 1];
    float a0 = 0.f, a1 = 0.f, a2 = 0.f, a3 = 0.f;
    for (int j = j0; j < j1; j++) {
        float4 wgt = *(const float4*)&d_esc[(size_t)j * 4];
        const float* xl = &d_xl[(size_t)g_esrc[j] * HC];
        a0 += wgt.x * xl[c];
        a1 += wgt.y * xl[128 + c];
        a2 += wgt.z * xl[256 + c];
        a3 += wgt.w * xl[384 + c];
    }
    size_t o = (size_t)n * HC;
    g_out[o + c] = a0;
    g_out[o + 128 + c] = a1;
    g_out[o + 256 + c] = a2;
    g_out[o + 384 + c] = a3;
}

// per-layer graph-scope accumulator init
__global__ void k_init_graph() {
    int i = blockIdx.x * blockDim.x + threadIdx.x;
    if (i < GG * CC) { g_meanAcc[i] = 0.0f; g_varAcc[i] = 0.0f; }
    if (i < GG) { g_gmax[i] = -__int_as_float(0x7f800000); g_gsum[i] = 0.0f; }
}

// s[n] = dot(instr[batch[n]], cr[n]) * inv_sqrt_c ; atomicMax per graph
__global__ void k_sdpa_score(const float* __restrict__ instr, const int* __restrict__ batch) {
    int w = (blockIdx.x * blockDim.x + threadIdx.x) >> 5;
    int lane = threadIdx.x & 31;
    if (w >= NN) return;
    int g = batch[w];
    float4 iv = ((const float4*)&instr[(size_t)g * CC])[lane];
    float4 cv = ((const float4*)&g_cr[(size_t)w * CC])[lane];
    float p = iv.x * cv.x + iv.y * cv.y + iv.z * cv.z + iv.w * cv.w;
    p = warpRedSum(p) * INV_SQRT_C;
    if (lane == 0) {
        g_s[w] = p;
        atomicMaxF(&g_gmax[g], p);
    }
}
__global__ void k_sdpa_exp(const int* __restrict__ batch) {
    int n = blockIdx.x * blockDim.x + threadIdx.x;
    if (n >= NN) return;
    int g = batch[n];
    float e = expf(g_s[n] - g_gmax[g]);
    g_s[n] = e;
    atomicAdd(&g_gsum[g], e);
}
__global__ void k_sdpa_norm(const int* __restrict__ batch) {
    int n = blockIdx.x * blockDim.x + threadIdx.x;
    if (n >= NN) return;
    g_s[n] = g_s[n] / (g_gsum[batch[n]] + 1e-16f);
}

// scale cr by attention weight + accumulate per-graph mean (exploits sorted batch)
__global__ void k_scale_mean(const int* __restrict__ batch) {
    int c = threadIdx.x;  // 128
    int n0 = blockIdx.x * 64;
    int n1 = min(n0 + 64, NN);
    float acc = 0.0f;
    int curg = batch[n0];
    for (int n = n0; n < n1; n++) {
        int g = batch[n];
        float v = g_cr[(size_t)n * CC + c] * g_s[n];
        g_cr[(size_t)n * CC + c] = v;
        if (g != curg) { atomicAdd(&g_meanAcc[curg * CC + c], acc); acc = 0.0f; curg = g; }
        acc += v;
    }
    atomicAdd(&g_meanAcc[curg * CC + c], acc);
}
__global__ void k_mean_div() {
    int i = blockIdx.x * blockDim.x + threadIdx.x;
    if (i < GG * CC) g_mean[i] = g_meanAcc[i] / fmaxf(g_cntf[i / CC], 1.0f);
}
__global__ void k_var_acc(const int* __restrict__ batch, const float* __restrict__ alpha) {
    int c = threadIdx.x;
    int n0 = blockIdx.x * 64;
    int n1 = min(n0 + 64, NN);
    float al = alpha[c];
    float acc = 0.0f;
    int curg = batch[n0];
    for (int n = n0; n < n1; n++) {
        int g = batch[n];
        float v = g_cr[(size_t)n * CC + c] - al * g_mean[g * CC + c];
        if (g != curg) { atomicAdd(&g_varAcc[curg * CC + c], acc); acc = 0.0f; curg = g; }
        acc += v * v;
    }
    atomicAdd(&g_varAcc[curg * CC + c], acc);
}
__global__ void k_var_div() {
    int i = blockIdx.x * blockDim.x + threadIdx.x;
    if (i < GG * CC) g_var[i] = g_varAcc[i] / fmaxf(g_cntf[i / CC], 1.0f);
}
// normalize + residual + mask gate -> dst (d_h for layers 0..2, d_out on last)
__global__ void k_norm_resid(const int* __restrict__ batch, const float* __restrict__ alpha,
                             const float* __restrict__ gamma, const float* __restrict__ beta,
                             float* __restrict__ dstp) {
    int idx = blockIdx.x * blockDim.x + threadIdx.x;
    if (idx >= NN * CC) return;
    int n = idx >> 7, c = idx & 127;
    int g = batch[n];
    float sub = g_cr[idx] - alpha[c] * g_mean[g * CC + c];
    float v = gamma[c] * sub * rsqrtf(g_var[g * CC + c] + EPSN) + beta[c];
    dstp[idx] = d_mask[n] * (v + d_h[idx]);
}

// ---------------- launch ----------------
extern "C" void kernel_launch(void* const* d_in, const int* in_sizes, int n_in,
                              void* d_out, int out_size) {
    const float* x = (const float*)d_in[0];
    const int* eidx = (const int*)d_in[1];
    const float* instr = (const float*)d_in[2];
    // d_in[3] = global_language_feats (unused by reference)
    const float* eattr = (const float*)d_in[4];
    const int* batch = (const int*)d_in[5];
    const float* Wl = (const float*)d_in[6];
    const float* Wr = (const float*)d_in[7];
    const float* We = (const float*)d_in[8];
    const float* att = (const float*)d_in[9];
    const float* Wm = (const float*)d_in[10];
    const float* p1w = (const float*)d_in[11];
    const float* p1b = (const float*)d_in[12];
    const float* p2w = (const float*)d_in[13];
    const float* p2b = (const float*)d_in[14];
    const float* gng = (const float*)d_in[15];
    const float* gnb = (const float*)d_in[16];
    const float* gna = (const float*)d_in[17];
    const int* src = eidx;
    const int* dst = eidx + EE;
    float* outp = (float*)d_out;

    int* pdeg; cudaGetSymbolAddress((void**)&pdeg, g_deg);
    int* pfill; cudaGetSymbolAddress((void**)&pfill, g_fill);
    float* pcnt; cudaGetSymbolAddress((void**)&pcnt, g_cntf);
    float* ph; cudaGetSymbolAddress((void**)&ph, d_h);

    const int NB256 = (NN + 255) / 256;       // 196
    const int EB256 = (EE + 255) / 256;

    // ---- startup (runs every replay; deterministic) ----
    k_zero_int<<<NB256, 256>>>(pdeg, NN);
    k_zero_int<<<NB256, 256>>>(pfill, NN);
    k_zero_float<<<1, 64>>>(pcnt, GG);
    k_deg<<<EB256, 256>>>(dst);
    k_scanA<<<NB256, 256>>>();
    k_scanB<<<1, 32>>>(NB256);
    k_scanC<<<(NN + 255) / 256, 256>>>();
    k_scatter<<<EB256, 256>>>(src, dst);
    k_permute_eattr<<<(EE * 32 + 255) / 256, 256>>>(eattr);
    k_cnt<<<NB256, 256>>>(batch);
    k_copy4<<<((NN * CC / 4) + 255) / 256, 256>>>(ph, x, NN * CC / 4);

    float* pxin; cudaGetSymbolAddress((void**)&pxin, d_xin);
    float* pxl; cudaGetSymbolAddress((void**)&pxl, d_xl);
    float* pxr; cudaGetSymbolAddress((void**)&pxr, d_xr);
    float* peattr; cudaGetSymbolAddress((void**)&peattr, d_eattr);
    float* pout; cudaGetSymbolAddress((void**)&pout, g_out);
    float* pcr1; cudaGetSymbolAddress((void**)&pcr1, g_cr1);
    float* pcr; cudaGetSymbolAddress((void**)&pcr, g_cr);

    for (int i = 0; i < LL; i++) {
        const float* Wm_i = Wm + (size_t)i * CC * CC;
        const float* instr_i = instr + (size_t)i * GG * CC;
        const float* Wl_i = Wl + (size_t)i * CC * HC;
        const float* Wr_i = Wr + (size_t)i * CC * HC;
        const float* We_i = We + (size_t)i * CC * HC;
        const float* att_i = att + (size_t)i * HH * CC;
        const float* p1w_i = p1w + (size_t)i * HC * MIDD;
        const float* p1b_i = p1b + (size_t)i * MIDD;
        const float* p2w_i = p2w + (size_t)i * MIDD * CC;
        const float* p2b_i = p2b + (size_t)i * CC;
        const float* gng_i = gng + (size_t)i * CC;
        const float* gnb_i = gnb + (size_t)i * CC;
        const float* gna_i = gna + (size_t)i * CC;

        // mask + x_in
        k_wmI<<<GG, CC>>>(Wm_i, instr_i);
        k_mask_xin<<<(NN * 32 + 255) / 256, 256>>>(batch);

        // node projections (tf32 tensor cores)
        dim3 gxl(HC / 128, (NN + 127) / 128);
        tgemm_k<0><<<gxl, 256>>>(pxin, Wl_i, nullptr, pxl, NN, HC, CC);
        tgemm_k<0><<<gxl, 256>>>(pxin, Wr_i, nullptr, pxr, NN, HC, CC);

        // fused edge GEMM + attention score (never materializes ea)
        dim3 gsc(HH, EE / 128);
        tgemm_score_k<<<gsc, 256>>>(peattr, We_i, att_i);

        // attention softmax + aggregation
        k_edge_softmax<<<(NN * 32 + 255) / 256, 256>>>();
        k_aggregate<<<NN, 128>>>();

        // MLP (tf32 tensor cores)
        dim3 gp1(MIDD / 128, (NN + 127) / 128);
        tgemm_k<1><<<gp1, 256>>>(pout, p1w_i, p1b_i, pcr1, NN, MIDD, HC);
        dim3 gp2(CC / 128, (NN + 127) / 128);
        tgemm_k<1><<<gp2, 256>>>(pcr1, p2w_i, p2b_i, pcr, NN, CC, MIDD);

        // scatter attention + GraphNorm
        k_init_graph<<<(GG * CC + 255) / 256, 256>>>();
        k_sdpa_score<<<(NN * 32 + 255) / 256, 256>>>(instr_i, batch);
        k_sdpa_exp<<<NB256, 256>>>(batch);
        k_sdpa_norm<<<NB256, 256>>>(batch);
        k_scale_mean<<<(NN + 63) / 64, 128>>>(batch);
        k_mean_div<<<(GG * CC + 255) / 256, 256>>>();
        k_var_acc<<<(NN + 63) / 64, 128>>>(batch, gna_i);
        k_var_div<<<(GG * CC + 255) / 256, 256>>>();
        float* dstp = (i == LL - 1) ? outp : ph;
        k_norm_resid<<<(NN * CC + 255) / 256, 256>>>(batch, gna_i, gng_i, gnb_i, dstp);
    }
    (void)in_sizes; (void)n_in; (void)out_size;
}

// round 9
// speedup vs baseline: 2.8674x; 1.2909x over previous
#include <cuda_runtime.h>
#include <cuda_bf16.h>
#include <math.h>

// Problem constants (fixed by setup_inputs)
#define NN 50000
#define EE 400000
#define CC 128
#define HH 4
#define GG 64
#define LL 4
#define HC 512   // H*C
#define MIDD 256 // C*(H/2)

#define NEG_SLOPE 0.2f
#define EPSN 1e-5f
#define INV_SQRT_C 0.08838834764831845f

// ---------------- scratch (static device globals; no allocation) ----------------
__device__ float d_h[(size_t)NN * CC];
__device__ float d_mask[NN];
__device__ float d_xin[(size_t)NN * CC];
__device__ float d_xl[(size_t)NN * HC];
__device__ float d_xr[(size_t)NN * HC];
__device__ float d_eattr[(size_t)EE * CC];   // edge_attr permuted to dst-sorted order
__device__ float d_esc[(size_t)EE * HH];     // scores -> normalized alphas in place
__device__ float g_out[(size_t)NN * HC];
__device__ float g_cr1[(size_t)NN * MIDD];
__device__ float g_cr[(size_t)NN * CC];
__device__ float g_s[NN];
__device__ float g_WmI[GG * CC];
__device__ float g_gmax[GG];
__device__ float g_gsum[GG];
__device__ float g_meanAcc[GG * CC];
__device__ float g_mean[GG * CC];
__device__ float g_varAcc[GG * CC];
__device__ float g_var[GG * CC];
__device__ float g_cntf[GG];
__device__ int g_deg[NN];
__device__ int g_fill[NN];
__device__ int g_rowptr[NN + 1];
__device__ int g_esrc[EE];
__device__ int g_edst[EE];
__device__ int g_eid[EE];
__device__ int g_blocksums[256];

// ---------------- helpers ----------------
__device__ __forceinline__ float warpRedSum(float v) {
#pragma unroll
    for (int o = 16; o; o >>= 1) v += __shfl_xor_sync(0xffffffffu, v, o);
    return v;
}
__device__ __forceinline__ float warpRedMax(float v) {
#pragma unroll
    for (int o = 16; o; o >>= 1) v = fmaxf(v, __shfl_xor_sync(0xffffffffu, v, o));
    return v;
}
__device__ __forceinline__ float geluf(float x) {
    float x3 = x * x * x;
    return 0.5f * x * (1.0f + tanhf(0.7978845608028654f * (x + 0.044715f * x3)));
}
__device__ __forceinline__ float lreluf(float x) {
    return x > 0.0f ? x : NEG_SLOPE * x;
}
__device__ __forceinline__ void atomicMaxF(float* a, float v) {
    if (v >= 0.0f) atomicMax((int*)a, __float_as_int(v));
    else atomicMin((unsigned int*)a, __float_as_uint(v));
}
__device__ __forceinline__ void mma_tf32(float* d, const unsigned* a, const unsigned* b) {
    asm volatile(
        "mma.sync.aligned.m16n8k8.row.col.f32.tf32.tf32.f32 "
        "{%0,%1,%2,%3}, {%4,%5,%6,%7}, {%8,%9}, {%0,%1,%2,%3};\n"
        : "+f"(d[0]), "+f"(d[1]), "+f"(d[2]), "+f"(d[3])
        : "r"(a[0]), "r"(a[1]), "r"(a[2]), "r"(a[3]), "r"(b[0]), "r"(b[1]));
}
__device__ __forceinline__ void cpasync16(void* s, const void* g) {
    unsigned saddr = (unsigned)__cvta_generic_to_shared(s);
    asm volatile("cp.async.cg.shared.global [%0], [%1], 16;\n" :: "r"(saddr), "l"(g));
}
__device__ __forceinline__ void cp_commit() {
    asm volatile("cp.async.commit_group;\n");
}
__device__ __forceinline__ void cp_wait1() {
    asm volatile("cp.async.wait_group 1;\n");
}

// smem stage geometry (fp32 words)
#define AS_STRIDE 36    // 32 k + pad4 per m-row
#define BS_STRIDE 132   // 128 n + pad4 per k-row
#define AS_WORDS (128 * AS_STRIDE)          // 4608
#define BS_WORDS (32 * BS_STRIDE)           // 4224
#define GEMM_SMEM_WORDS (2 * AS_WORDS + 2 * BS_WORDS)   // 17664 words = 70656 B
#define SCORE_EXTRA_WORDS (4 * 128)
#define SCORE_SMEM_WORDS (GEMM_SMEM_WORDS + SCORE_EXTRA_WORDS)

// ---------------- init / utility kernels ----------------
__global__ void k_zero_int(int* p, int n) {
    int i = blockIdx.x * blockDim.x + threadIdx.x;
    if (i < n) p[i] = 0;
}
__global__ void k_zero_float(float* p, int n) {
    int i = blockIdx.x * blockDim.x + threadIdx.x;
    if (i < n) p[i] = 0.0f;
}
__global__ void k_copy4(float* __restrict__ dst, const float* __restrict__ src, int n4) {
    int i = blockIdx.x * blockDim.x + threadIdx.x;
    if (i < n4) ((float4*)dst)[i] = ((const float4*)src)[i];
}

// ---------------- CSR build ----------------
__global__ void k_deg(const int* __restrict__ dst) {
    int e = blockIdx.x * blockDim.x + threadIdx.x;
    if (e < EE) atomicAdd(&g_deg[dst[e]], 1);
}
__global__ void k_scanA() {
    __shared__ float s[256];
    int tid = threadIdx.x;
    int n = blockIdx.x * 256 + tid;
    float v = (n < NN) ? (float)g_deg[n] : 0.0f;
    s[tid] = v;
    __syncthreads();
#pragma unroll
    for (int off = 1; off < 256; off <<= 1) {
        float t = (tid >= off) ? s[tid - off] : 0.0f;
        __syncthreads();
        s[tid] += t;
        __syncthreads();
    }
    if (n < NN) g_rowptr[n + 1] = (int)s[tid];
    if (tid == 255) g_blocksums[blockIdx.x] = (int)s[255];
}
__global__ void k_scanB(int nb) {
    if (threadIdx.x == 0) {
        int run = 0;
        for (int b = 0; b < nb; b++) { int t = g_blocksums[b]; g_blocksums[b] = run; run += t; }
    }
}
__global__ void k_scanC() {
    int n = blockIdx.x * blockDim.x + threadIdx.x;
    if (n < NN) g_rowptr[n + 1] += g_blocksums[n / 256];
    if (n == 0) g_rowptr[0] = 0;
}
__global__ void k_scatter(const int* __restrict__ src, const int* __restrict__ dst) {
    int e = blockIdx.x * blockDim.x + threadIdx.x;
    if (e >= EE) return;
    int d = dst[e];
    int p = g_rowptr[d] + atomicAdd(&g_fill[d], 1);
    g_esrc[p] = src[e];
    g_edst[p] = d;
    g_eid[p] = e;
}
__global__ void k_permute_eattr(const float* __restrict__ eattr) {
    int idx = blockIdx.x * blockDim.x + threadIdx.x;  // over EE*32 float4s
    if (idx >= EE * 32) return;
    int j = idx >> 5, q = idx & 31;
    ((float4*)d_eattr)[(size_t)j * 32 + q] =
        ((const float4*)eattr)[(size_t)g_eid[j] * 32 + q];
}
__global__ void k_cnt(const int* __restrict__ batch) {
    int n = blockIdx.x * blockDim.x + threadIdx.x;
    if (n < NN) atomicAdd(&g_cntf[batch[n]], 1.0f);
}

// ---------------- TF32 tensor-core GEMM (cp.async double-buffered) ----------------
// C[M,Nn] = A[M,K] @ B[K,Nn]  (row-major), fused bias + optional gelu.
// Block tile 128x128x32, 2-stage cp.async pipeline. fp32 bits fed to mma.tf32
// directly (HW truncation). Requires: Nn % 128 == 0, K % 32 == 0. M guarded.
template <int ACT>
__global__ void __launch_bounds__(256, 2)
tgemm_k(const float* __restrict__ A, const float* __restrict__ B,
        const float* __restrict__ bias, float* __restrict__ Cm,
        int M, int Nn, int K) {
    extern __shared__ float smem[];
    float* AsBase = smem;                       // 2 stages of [128][AS_STRIDE]
    float* BsBase = smem + 2 * AS_WORDS;        // 2 stages of [32][BS_STRIDE]

    const int tid = threadIdx.x;
    const int warpId = tid >> 5;
    const int lane = tid & 31;
    const int g = lane >> 2, tig = lane & 3;
    const int mBase = blockIdx.y * 128;
    const int nBase = blockIdx.x * 128;
    const int mW = (warpId >> 2) * 64;
    const int nW = (warpId & 3) * 32;

    float acc[4][4][4];
#pragma unroll
    for (int mt = 0; mt < 4; mt++)
#pragma unroll
        for (int nt = 0; nt < 4; nt++)
#pragma unroll
            for (int q = 0; q < 4; q++) acc[mt][nt][q] = 0.0f;

    const int nIter = K >> 5;

    // prefetch chunk kt into stage s
    auto prefetch = [&](int kt, int s) {
        int k0 = kt << 5;
        float* As = AsBase + s * AS_WORDS;
        float* Bs = BsBase + s * BS_WORDS;
#pragma unroll
        for (int p = 0; p < 4; p++) {
            int chunk = tid + p * 256;
            int row = chunk >> 3;
            int kc = (chunk & 7) * 4;
            int gr = mBase + row;
            if (gr >= M) gr = M - 1;   // clamp: garbage rows feed discarded outputs
            cpasync16(&As[row * AS_STRIDE + kc], &A[(size_t)gr * K + k0 + kc]);
        }
#pragma unroll
        for (int p = 0; p < 4; p++) {
            int chunk = tid + p * 256;
            int krow = chunk >> 5;
            int nc = (chunk & 31) * 4;
            cpasync16(&Bs[krow * BS_STRIDE + nc], &B[(size_t)(k0 + krow) * Nn + nBase + nc]);
        }
        cp_commit();
    };

    prefetch(0, 0);
    for (int kt = 0; kt < nIter; kt++) {
        int s = kt & 1;
        if (kt + 1 < nIter) prefetch(kt + 1, (kt + 1) & 1);
        else cp_commit();   // empty group keeps wait count consistent
        cp_wait1();
        __syncthreads();
        const unsigned* Asu = (const unsigned*)(AsBase + s * AS_WORDS);
        const unsigned* Bsu = (const unsigned*)(BsBase + s * BS_WORDS);
#pragma unroll
        for (int oct = 0; oct < 4; oct++) {
            int kb = oct * 8;
            unsigned bf[4][2];
#pragma unroll
            for (int nt = 0; nt < 4; nt++) {
                int nc = nW + nt * 8 + g;
                bf[nt][0] = Bsu[(kb + tig) * BS_STRIDE + nc];
                bf[nt][1] = Bsu[(kb + tig + 4) * BS_STRIDE + nc];
            }
            unsigned af[4][4];
#pragma unroll
            for (int mt = 0; mt < 4; mt++) {
                int m0 = mW + mt * 16 + g;
                af[mt][0] = Asu[m0 * AS_STRIDE + kb + tig];
                af[mt][1] = Asu[(m0 + 8) * AS_STRIDE + kb + tig];
                af[mt][2] = Asu[m0 * AS_STRIDE + kb + tig + 4];
                af[mt][3] = Asu[(m0 + 8) * AS_STRIDE + kb + tig + 4];
            }
#pragma unroll
            for (int mt = 0; mt < 4; mt++)
#pragma unroll
                for (int nt = 0; nt < 4; nt++)
                    mma_tf32(acc[mt][nt], af[mt], bf[nt]);
        }
        __syncthreads();
    }

    // epilogue
#pragma unroll
    for (int mt = 0; mt < 4; mt++) {
        int r0 = mBase + mW + mt * 16 + g;
        int r1 = r0 + 8;
#pragma unroll
        for (int nt = 0; nt < 4; nt++) {
            int c0 = nBase + nW + nt * 8 + 2 * tig;
            float b0 = 0.f, b1 = 0.f;
            if (bias) { b0 = bias[c0]; b1 = bias[c0 + 1]; }
            float v0 = acc[mt][nt][0] + b0, v1 = acc[mt][nt][1] + b1;
            float v2 = acc[mt][nt][2] + b0, v3 = acc[mt][nt][3] + b1;
            if (ACT == 1) { v0 = geluf(v0); v1 = geluf(v1); v2 = geluf(v2); v3 = geluf(v3); }
            if (r0 < M) *(float2*)&Cm[(size_t)r0 * Nn + c0] = make_float2(v0, v1);
            if (r1 < M) *(float2*)&Cm[(size_t)r1 * Nn + c0] = make_float2(v2, v3);
        }
    }
}

// ---------------- fused edge GEMM + attention score (cp.async) ----------------
// ea tile (128 edges x 128 ch, one head) stays in registers; reduces
// e[j,h] = sum_c lrelu(ea + xl[src]+xr[dst]) * att[c]. Grid: (HH, EE/128).
__global__ void __launch_bounds__(256, 2)
tgemm_score_k(const float* __restrict__ A, const float* __restrict__ B,
              const float* __restrict__ att) {
    extern __shared__ float smem[];
    float* AsBase = smem;
    float* BsBase = smem + 2 * AS_WORDS;
    float* satt = smem + GEMM_SMEM_WORDS;
    int* ssrc = (int*)(satt + 128);
    int* sdst = ssrc + 128;
    float* sred = (float*)(sdst + 128);

    const int tid = threadIdx.x;
    const int warpId = tid >> 5;
    const int lane = tid & 31;
    const int g = lane >> 2, tig = lane & 3;
    const int nBase = blockIdx.x * 128;   // head * 128
    const int mBase = blockIdx.y * 128;   // edge tile
    const int mW = (warpId >> 2) * 64;
    const int nW = (warpId & 3) * 32;
    const int K = CC, Nn = HC;

    if (tid < 128) {
        satt[tid] = att[nBase + tid];
        ssrc[tid] = g_esrc[mBase + tid];
        sdst[tid] = g_edst[mBase + tid];
        sred[tid] = 0.0f;
    }

    float acc[4][4][4];
#pragma unroll
    for (int mt = 0; mt < 4; mt++)
#pragma unroll
        for (int nt = 0; nt < 4; nt++)
#pragma unroll
            for (int q = 0; q < 4; q++) acc[mt][nt][q] = 0.0f;

    const int nIter = K >> 5;   // 4

    auto prefetch = [&](int kt, int s) {
        int k0 = kt << 5;
        float* As = AsBase + s * AS_WORDS;
        float* Bs = BsBase + s * BS_WORDS;
#pragma unroll
        for (int p = 0; p < 4; p++) {
            int chunk = tid + p * 256;
            int row = chunk >> 3;
            int kc = (chunk & 7) * 4;
            cpasync16(&As[row * AS_STRIDE + kc], &A[(size_t)(mBase + row) * K + k0 + kc]);
        }
#pragma unroll
        for (int p = 0; p < 4; p++) {
            int chunk = tid + p * 256;
            int krow = chunk >> 5;
            int nc = (chunk & 31) * 4;
            cpasync16(&Bs[krow * BS_STRIDE + nc], &B[(size_t)(k0 + krow) * Nn + nBase + nc]);
        }
        cp_commit();
    };

    prefetch(0, 0);
    for (int kt = 0; kt < nIter; kt++) {
        int s = kt & 1;
        if (kt + 1 < nIter) prefetch(kt + 1, (kt + 1) & 1);
        else cp_commit();
        cp_wait1();
        __syncthreads();
        const unsigned* Asu = (const unsigned*)(AsBase + s * AS_WORDS);
        const unsigned* Bsu = (const unsigned*)(BsBase + s * BS_WORDS);
#pragma unroll
        for (int oct = 0; oct < 4; oct++) {
            int kb = oct * 8;
            unsigned bf[4][2];
#pragma unroll
            for (int nt = 0; nt < 4; nt++) {
                int nc = nW + nt * 8 + g;
                bf[nt][0] = Bsu[(kb + tig) * BS_STRIDE + nc];
                bf[nt][1] = Bsu[(kb + tig + 4) * BS_STRIDE + nc];
            }
            unsigned af[4][4];
#pragma unroll
            for (int mt = 0; mt < 4; mt++) {
                int m0 = mW + mt * 16 + g;
                af[mt][0] = Asu[m0 * AS_STRIDE + kb + tig];
                af[mt][1] = Asu[(m0 + 8) * AS_STRIDE + kb + tig];
                af[mt][2] = Asu[m0 * AS_STRIDE + kb + tig + 4];
                af[mt][3] = Asu[(m0 + 8) * AS_STRIDE + kb + tig + 4];
            }
#pragma unroll
            for (int mt = 0; mt < 4; mt++)
#pragma unroll
                for (int nt = 0; nt < 4; nt++)
                    mma_tf32(acc[mt][nt], af[mt], bf[nt]);
        }
        __syncthreads();
    }

    // fused score epilogue
#pragma unroll
    for (int mt = 0; mt < 4; mt++) {
        int lr0 = mW + mt * 16 + g;
        int lr1 = lr0 + 8;
        int s0 = ssrc[lr0], dd0 = sdst[lr0];
        int s1 = ssrc[lr1], dd1 = sdst[lr1];
        float p0 = 0.0f, p1 = 0.0f;
#pragma unroll
        for (int nt = 0; nt < 4; nt++) {
            int cl = nW + nt * 8 + 2 * tig;
            int cg = nBase + cl;
            float at0 = satt[cl], at1 = satt[cl + 1];
            float2 xa0 = *(const float2*)&d_xl[(size_t)s0 * HC + cg];
            float2 xb0 = *(const float2*)&d_xr[(size_t)dd0 * HC + cg];
            float2 xa1 = *(const float2*)&d_xl[(size_t)s1 * HC + cg];
            float2 xb1 = *(const float2*)&d_xr[(size_t)dd1 * HC + cg];
            p0 += lreluf(acc[mt][nt][0] + xa0.x + xb0.x) * at0 +
                  lreluf(acc[mt][nt][1] + xa0.y + xb0.y) * at1;
            p1 += lreluf(acc[mt][nt][2] + xa1.x + xb1.x) * at0 +
                  lreluf(acc[mt][nt][3] + xa1.y + xb1.y) * at1;
        }
        p0 += __shfl_xor_sync(0xffffffffu, p0, 1);
        p0 += __shfl_xor_sync(0xffffffffu, p0, 2);
        p1 += __shfl_xor_sync(0xffffffffu, p1, 1);
        p1 += __shfl_xor_sync(0xffffffffu, p1, 2);
        if (tig == 0) {
            atomicAdd(&sred[lr0], p0);
            atomicAdd(&sred[lr1], p1);
        }
    }
    __syncthreads();
    if (tid < 128)
        d_esc[(size_t)(mBase + tid) * HH + blockIdx.x] = sred[tid];
}

// ---------------- per-layer kernels ----------------
// WmI[g][k] = sum_c Wm[k][c] * instr[g][c]
__global__ void k_wmI(const float* __restrict__ Wm, const float* __restrict__ instr) {
    int g = blockIdx.x, k = threadIdx.x;
    const float* wr = Wm + (size_t)k * CC;
    const float* iv = instr + (size_t)g * CC;
    float s = 0.0f;
    for (int c = 0; c < CC; c++) s += wr[c] * iv[c];
    g_WmI[g * CC + k] = s;
}

// mask + x_in (warp per node)
__global__ void k_mask_xin(const int* __restrict__ batch) {
    int w = (blockIdx.x * blockDim.x + threadIdx.x) >> 5;
    int lane = threadIdx.x & 31;
    if (w >= NN) return;
    int g = batch[w];
    float4 hv = ((const float4*)&d_h[(size_t)w * CC])[lane];
    float4 wv = ((const float4*)&g_WmI[g * CC])[lane];
    float p = hv.x * wv.x + hv.y * wv.y + hv.z * wv.z + hv.w * wv.w;
    p = warpRedSum(p);
    float mk = 1.0f / (1.0f + expf(-p * INV_SQRT_C));
    if (lane == 0) d_mask[w] = mk;
    float4 o = make_float4(mk * hv.x, mk * hv.y, mk * hv.z, mk * hv.w);
    ((float4*)&d_xin[(size_t)w * CC])[lane] = o;
}

// per-dst-node softmax over incident edges (warp per node), normalizes d_esc in place
__global__ void k_edge_softmax() {
    int w = (blockIdx.x * blockDim.x + threadIdx.x) >> 5;
    int lane = threadIdx.x & 31;
    if (w >= NN) return;
    int j0 = g_rowptr[w], j1 = g_rowptr[w + 1];
    float m0 = -1e30f, m1 = -1e30f, m2 = -1e30f, m3 = -1e30f;
    for (int j = j0 + lane; j < j1; j += 32) {
        float4 e = *(const float4*)&d_esc[(size_t)j * 4];
        m0 = fmaxf(m0, e.x); m1 = fmaxf(m1, e.y); m2 = fmaxf(m2, e.z); m3 = fmaxf(m3, e.w);
    }
    m0 = warpRedMax(m0); m1 = warpRedMax(m1); m2 = warpRedMax(m2); m3 = warpRedMax(m3);
    float s0 = 0.f, s1 = 0.f, s2 = 0.f, s3 = 0.f;
    for (int j = j0 + lane; j < j1; j += 32) {
        float4 e = *(const float4*)&d_esc[(size_t)j * 4];
        e.x = expf(e.x - m0); e.y = expf(e.y - m1);
        e.z = expf(e.z - m2); e.w = expf(e.w - m3);
        s0 += e.x; s1 += e.y; s2 += e.z; s3 += e.w;
        *(float4*)&d_esc[(size_t)j * 4] = e;
    }
    s0 = warpRedSum(s0); s1 = warpRedSum(s1); s2 = warpRedSum(s2); s3 = warpRedSum(s3);
    float i0 = 1.0f / (s0 + 1e-16f), i1 = 1.0f / (s1 + 1e-16f);
    float i2 = 1.0f / (s2 + 1e-16f), i3 = 1.0f / (s3 + 1e-16f);
    for (int j = j0 + lane; j < j1; j += 32) {
        float4 e = *(const float4*)&d_esc[(size_t)j * 4];
        e.x *= i0; e.y *= i1; e.z *= i2; e.w *= i3;
        *(float4*)&d_esc[(size_t)j * 4] = e;
    }
}

// aggregate: out[n,h,c] = sum_j alpha[j,h] * xl[src_j, h, c]  (block=128 threads per node)
__global__ void k_aggregate() {
    int n = blockIdx.x;
    int c = threadIdx.x;
    int j0 = g_rowptr[n], j1 = g_rowptr[n + 1];
    float a0 = 0.f, a1 = 0.f, a2 = 0.f, a3 = 0.f;
    for (int j = j0; j < j1; j++) {
        float4 wgt = *(const float4*)&d_esc[(size_t)j * 4];
        const float* xl = &d_xl[(size_t)g_esrc[j] * HC];
        a0 += wgt.x * xl[c];
        a1 += wgt.y * xl[128 + c];
        a2 += wgt.z * xl[256 + c];
        a3 += wgt.w * xl[384 + c];
    }
    size_t o = (size_t)n * HC;
    g_out[o + c] = a0;
    g_out[o + 128 + c] = a1;
    g_out[o + 256 + c] = a2;
    g_out[o + 384 + c] = a3;
}

// per-layer graph-scope accumulator init
__global__ void k_init_graph() {
    int i = blockIdx.x * blockDim.x + threadIdx.x;
    if (i < GG * CC) { g_meanAcc[i] = 0.0f; g_varAcc[i] = 0.0f; }
    if (i < GG) { g_gmax[i] = -__int_as_float(0x7f800000); g_gsum[i] = 0.0f; }
}

// s[n] = dot(instr[batch[n]], cr[n]) * inv_sqrt_c ; atomicMax per graph
__global__ void k_sdpa_score(const float* __restrict__ instr, const int* __restrict__ batch) {
    int w = (blockIdx.x * blockDim.x + threadIdx.x) >> 5;
    int lane = threadIdx.x & 31;
    if (w >= NN) return;
    int g = batch[w];
    float4 iv = ((const float4*)&instr[(size_t)g * CC])[lane];
    float4 cv = ((const float4*)&g_cr[(size_t)w * CC])[lane];
    float p = iv.x * cv.x + iv.y * cv.y + iv.z * cv.z + iv.w * cv.w;
    p = warpRedSum(p) * INV_SQRT_C;
    if (lane == 0) {
        g_s[w] = p;
        atomicMaxF(&g_gmax[g], p);
    }
}
__global__ void k_sdpa_exp(const int* __restrict__ batch) {
    int n = blockIdx.x * blockDim.x + threadIdx.x;
    if (n >= NN) return;
    int g = batch[n];
    float e = expf(g_s[n] - g_gmax[g]);
    g_s[n] = e;
    atomicAdd(&g_gsum[g], e);
}
__global__ void k_sdpa_norm(const int* __restrict__ batch) {
    int n = blockIdx.x * blockDim.x + threadIdx.x;
    if (n >= NN) return;
    g_s[n] = g_s[n] / (g_gsum[batch[n]] + 1e-16f);
}

// scale cr by attention weight + accumulate per-graph mean (exploits sorted batch)
__global__ void k_scale_mean(const int* __restrict__ batch) {
    int c = threadIdx.x;  // 128
    int n0 = blockIdx.x * 64;
    int n1 = min(n0 + 64, NN);
    float acc = 0.0f;
    int curg = batch[n0];
    for (int n = n0; n < n1; n++) {
        int g = batch[n];
        float v = g_cr[(size_t)n * CC + c] * g_s[n];
        g_cr[(size_t)n * CC + c] = v;
        if (g != curg) { atomicAdd(&g_meanAcc[curg * CC + c], acc); acc = 0.0f; curg = g; }
        acc += v;
    }
    atomicAdd(&g_meanAcc[curg * CC + c], acc);
}
__global__ void k_mean_div() {
    int i = blockIdx.x * blockDim.x + threadIdx.x;
    if (i < GG * CC) g_mean[i] = g_meanAcc[i] / fmaxf(g_cntf[i / CC], 1.0f);
}
__global__ void k_var_acc(const int* __restrict__ batch, const float* __restrict__ alpha) {
    int c = threadIdx.x;
    int n0 = blockIdx.x * 64;
    int n1 = min(n0 + 64, NN);
    float al = alpha[c];
    float acc = 0.0f;
    int curg = batch[n0];
    for (int n = n0; n < n1; n++) {
        int g = batch[n];
        float v = g_cr[(size_t)n * CC + c] - al * g_mean[g * CC + c];
        if (g != curg) { atomicAdd(&g_varAcc[curg * CC + c], acc); acc = 0.0f; curg = g; }
        acc += v * v;
    }
    atomicAdd(&g_varAcc[curg * CC + c], acc);
}
__global__ void k_var_div() {
    int i = blockIdx.x * blockDim.x + threadIdx.x;
    if (i < GG * CC) g_var[i] = g_varAcc[i] / fmaxf(g_cntf[i / CC], 1.0f);
}
// normalize + residual + mask gate -> dst (d_h for layers 0..2, d_out on last)
__global__ void k_norm_resid(const int* __restrict__ batch, const float* __restrict__ alpha,
                             const float* __restrict__ gamma, const float* __restrict__ beta,
                             float* __restrict__ dstp) {
    int idx = blockIdx.x * blockDim.x + threadIdx.x;
    if (idx >= NN * CC) return;
    int n = idx >> 7, c = idx & 127;
    int g = batch[n];
    float sub = g_cr[idx] - alpha[c] * g_mean[g * CC + c];
    float v = gamma[c] * sub * rsqrtf(g_var[g * CC + c] + EPSN) + beta[c];
    dstp[idx] = d_mask[n] * (v + d_h[idx]);
}

// ---------------- launch ----------------
extern "C" void kernel_launch(void* const* d_in, const int* in_sizes, int n_in,
                              void* d_out, int out_size) {
    const float* x = (const float*)d_in[0];
    const int* eidx = (const int*)d_in[1];
    const float* instr = (const float*)d_in[2];
    // d_in[3] = global_language_feats (unused by reference)
    const float* eattr = (const float*)d_in[4];
    const int* batch = (const int*)d_in[5];
    const float* Wl = (const float*)d_in[6];
    const float* Wr = (const float*)d_in[7];
    const float* We = (const float*)d_in[8];
    const float* att = (const float*)d_in[9];
    const float* Wm = (const float*)d_in[10];
    const float* p1w = (const float*)d_in[11];
    const float* p1b = (const float*)d_in[12];
    const float* p2w = (const float*)d_in[13];
    const float* p2b = (const float*)d_in[14];
    const float* gng = (const float*)d_in[15];
    const float* gnb = (const float*)d_in[16];
    const float* gna = (const float*)d_in[17];
    const int* src = eidx;
    const int* dst = eidx + EE;
    float* outp = (float*)d_out;

    const int GEMM_SMEM = GEMM_SMEM_WORDS * 4;     // 70656 B
    const int SCORE_SMEM = SCORE_SMEM_WORDS * 4;   // 72704 B
    cudaFuncSetAttribute(tgemm_k<0>, cudaFuncAttributeMaxDynamicSharedMemorySize, GEMM_SMEM);
    cudaFuncSetAttribute(tgemm_k<1>, cudaFuncAttributeMaxDynamicSharedMemorySize, GEMM_SMEM);
    cudaFuncSetAttribute(tgemm_score_k, cudaFuncAttributeMaxDynamicSharedMemorySize, SCORE_SMEM);

    int* pdeg; cudaGetSymbolAddress((void**)&pdeg, g_deg);
    int* pfill; cudaGetSymbolAddress((void**)&pfill, g_fill);
    float* pcnt; cudaGetSymbolAddress((void**)&pcnt, g_cntf);
    float* ph; cudaGetSymbolAddress((void**)&ph, d_h);

    const int NB256 = (NN + 255) / 256;       // 196
    const int EB256 = (EE + 255) / 256;

    // ---- startup (runs every replay; deterministic) ----
    k_zero_int<<<NB256, 256>>>(pdeg, NN);
    k_zero_int<<<NB256, 256>>>(pfill, NN);
    k_zero_float<<<1, 64>>>(pcnt, GG);
    k_deg<<<EB256, 256>>>(dst);
    k_scanA<<<NB256, 256>>>();
    k_scanB<<<1, 32>>>(NB256);
    k_scanC<<<(NN + 255) / 256, 256>>>();
    k_scatter<<<EB256, 256>>>(src, dst);
    k_permute_eattr<<<(EE * 32 + 255) / 256, 256>>>(eattr);
    k_cnt<<<NB256, 256>>>(batch);
    k_copy4<<<((NN * CC / 4) + 255) / 256, 256>>>(ph, x, NN * CC / 4);

    float* pxin; cudaGetSymbolAddress((void**)&pxin, d_xin);
    float* pxl; cudaGetSymbolAddress((void**)&pxl, d_xl);
    float* pxr; cudaGetSymbolAddress((void**)&pxr, d_xr);
    float* peattr; cudaGetSymbolAddress((void**)&peattr, d_eattr);
    float* pout; cudaGetSymbolAddress((void**)&pout, g_out);
    float* pcr1; cudaGetSymbolAddress((void**)&pcr1, g_cr1);
    float* pcr; cudaGetSymbolAddress((void**)&pcr, g_cr);

    for (int i = 0; i < LL; i++) {
        const float* Wm_i = Wm + (size_t)i * CC * CC;
        const float* instr_i = instr + (size_t)i * GG * CC;
        const float* Wl_i = Wl + (size_t)i * CC * HC;
        const float* Wr_i = Wr + (size_t)i * CC * HC;
        const float* We_i = We + (size_t)i * CC * HC;
        const float* att_i = att + (size_t)i * HH * CC;
        const float* p1w_i = p1w + (size_t)i * HC * MIDD;
        const float* p1b_i = p1b + (size_t)i * MIDD;
        const float* p2w_i = p2w + (size_t)i * MIDD * CC;
        const float* p2b_i = p2b + (size_t)i * CC;
        const float* gng_i = gng + (size_t)i * CC;
        const float* gnb_i = gnb + (size_t)i * CC;
        const float* gna_i = gna + (size_t)i * CC;

        // mask + x_in
        k_wmI<<<GG, CC>>>(Wm_i, instr_i);
        k_mask_xin<<<(NN * 32 + 255) / 256, 256>>>(batch);

        // node projections (tf32 tensor cores, cp.async pipelined)
        dim3 gxl(HC / 128, (NN + 127) / 128);
        tgemm_k<0><<<gxl, 256, GEMM_SMEM>>>(pxin, Wl_i, nullptr, pxl, NN, HC, CC);
        tgemm_k<0><<<gxl, 256, GEMM_SMEM>>>(pxin, Wr_i, nullptr, pxr, NN, HC, CC);

        // fused edge GEMM + attention score (never materializes ea)
        dim3 gsc(HH, EE / 128);
        tgemm_score_k<<<gsc, 256, SCORE_SMEM>>>(peattr, We_i, att_i);

        // attention softmax + aggregation
        k_edge_softmax<<<(NN * 32 + 255) / 256, 256>>>();
        k_aggregate<<<NN, 128>>>();

        // MLP (tf32 tensor cores)
        dim3 gp1(MIDD / 128, (NN + 127) / 128);
        tgemm_k<1><<<gp1, 256, GEMM_SMEM>>>(pout, p1w_i, p1b_i, pcr1, NN, MIDD, HC);
        dim3 gp2(CC / 128, (NN + 127) / 128);
        tgemm_k<1><<<gp2, 256, GEMM_SMEM>>>(pcr1, p2w_i, p2b_i, pcr, NN, CC, MIDD);

        // scatter attention + GraphNorm
        k_init_graph<<<(GG * CC + 255) / 256, 256>>>();
        k_sdpa_score<<<(NN * 32 + 255) / 256, 256>>>(instr_i, batch);
        k_sdpa_exp<<<NB256, 256>>>(batch);
        k_sdpa_norm<<<NB256, 256>>>(batch);
        k_scale_mean<<<(NN + 63) / 64, 128>>>(batch);
        k_mean_div<<<(GG * CC + 255) / 256, 256>>>();
        k_var_acc<<<(NN + 63) / 64, 128>>>(batch, gna_i);
        k_var_div<<<(GG * CC + 255) / 256, 256>>>();
        float* dstp = (i == LL - 1) ? outp : ph;
        k_norm_resid<<<(NN * CC + 255) / 256, 256>>>(batch, gna_i, gng_i, gnb_i, dstp);
    }
    (void)in_sizes; (void)n_in; (void)out_size;
}

// round 10
// speedup vs baseline: 3.7691x; 1.3144x over previous
#include <cuda_runtime.h>
#include <cuda_bf16.h>
#include <math.h>

// Problem constants (fixed by setup_inputs)
#define NN 50000
#define EE 400000
#define CC 128
#define HH 4
#define GG 64
#define LL 4
#define HC 512   // H*C
#define MIDD 256 // C*(H/2)

#define NEG_SLOPE 0.2f
#define EPSN 1e-5f
#define INV_SQRT_C 0.08838834764831845f

// ---------------- scratch (static device globals; no allocation) ----------------
__device__ float d_h[(size_t)NN * CC];
__device__ float d_mask[NN];
__device__ float d_esc[(size_t)EE * HH];     // scores -> normalized alphas in place
__device__ float g_cr[(size_t)NN * CC];
__device__ float g_s[NN];
__device__ float g_WmI[GG * CC];
__device__ float g_gmax[GG];
__device__ float g_gsum[GG];
__device__ float g_meanAcc[GG * CC];
__device__ float g_mean[GG * CC];
__device__ float g_varAcc[GG * CC];
__device__ float g_var[GG * CC];
__device__ float g_cntf[GG];
__device__ int g_deg[NN];
__device__ int g_fill[NN];
__device__ int g_rowptr[NN + 1];
__device__ int g_esrc[EE];
__device__ int g_edst[EE];
__device__ int g_eid[EE];
__device__ int g_blocksums[256];

// bf16 activation / weight buffers
__device__ __nv_bfloat16 b_xin[(size_t)NN * CC];
__device__ __nv_bfloat16 b_eattr[(size_t)EE * CC];
__device__ __nv_bfloat16 b_xl[(size_t)NN * HC];
__device__ __nv_bfloat16 b_xr[(size_t)NN * HC];
__device__ __nv_bfloat16 b_out[(size_t)NN * HC];
__device__ __nv_bfloat16 b_cr1[(size_t)NN * MIDD];
__device__ __nv_bfloat16 b_wtl[(size_t)LL * HC * CC];
__device__ __nv_bfloat16 b_wtr[(size_t)LL * HC * CC];
__device__ __nv_bfloat16 b_wte[(size_t)LL * HC * CC];
__device__ __nv_bfloat16 b_wtp1[(size_t)LL * MIDD * HC];
__device__ __nv_bfloat16 b_wtp2[(size_t)LL * CC * MIDD];

// ---------------- helpers ----------------
__device__ __forceinline__ float warpRedSum(float v) {
#pragma unroll
    for (int o = 16; o; o >>= 1) v += __shfl_xor_sync(0xffffffffu, v, o);
    return v;
}
__device__ __forceinline__ float warpRedMax(float v) {
#pragma unroll
    for (int o = 16; o; o >>= 1) v = fmaxf(v, __shfl_xor_sync(0xffffffffu, v, o));
    return v;
}
__device__ __forceinline__ float geluf(float x) {
    float x3 = x * x * x;
    return 0.5f * x * (1.0f + tanhf(0.7978845608028654f * (x + 0.044715f * x3)));
}
__device__ __forceinline__ float lreluf(float x) {
    return x > 0.0f ? x : NEG_SLOPE * x;
}
__device__ __forceinline__ void atomicMaxF(float* a, float v) {
    if (v >= 0.0f) atomicMax((int*)a, __float_as_int(v));
    else atomicMin((unsigned int*)a, __float_as_uint(v));
}
__device__ __forceinline__ void mma_bf16(float* d, const unsigned* a, const unsigned* b) {
    asm volatile(
        "mma.sync.aligned.m16n8k16.row.col.f32.bf16.bf16.f32 "
        "{%0,%1,%2,%3}, {%4,%5,%6,%7}, {%8,%9}, {%0,%1,%2,%3};\n"
        : "+f"(d[0]), "+f"(d[1]), "+f"(d[2]), "+f"(d[3])
        : "r"(a[0]), "r"(a[1]), "r"(a[2]), "r"(a[3]), "r"(b[0]), "r"(b[1]));
}
__device__ __forceinline__ void cpasync16(void* s, const void* g) {
    unsigned saddr = (unsigned)__cvta_generic_to_shared(s);
    asm volatile("cp.async.cg.shared.global [%0], [%1], 16;\n" :: "r"(saddr), "l"(g));
}
__device__ __forceinline__ void cp_commit() {
    asm volatile("cp.async.commit_group;\n");
}
__device__ __forceinline__ void cp_wait1() {
    asm volatile("cp.async.wait_group 1;\n");
}

// smem tile geometry (bf16 units)
#define BST 40                  // bf16 per row (32 k + pad 8)
#define BSTU 20                 // u32 stride
#define TILEBF (128 * BST)      // 5120 bf16 = 10240 B per tile
#define BGEMM_SMEM (4 * TILEBF * 2)           // 2 stages x (A+B) = 40960 B
#define BSCORE_SMEM (BGEMM_SMEM + 2048)       // + satt/ssrc/sdst/sred

// ---------------- init / utility kernels ----------------
__global__ void k_zero_int(int* p, int n) {
    int i = blockIdx.x * blockDim.x + threadIdx.x;
    if (i < n) p[i] = 0;
}
__global__ void k_zero_float(float* p, int n) {
    int i = blockIdx.x * blockDim.x + threadIdx.x;
    if (i < n) p[i] = 0.0f;
}
__global__ void k_copy4(float* __restrict__ dst, const float* __restrict__ src, int n4) {
    int i = blockIdx.x * blockDim.x + threadIdx.x;
    if (i < n4) ((float4*)dst)[i] = ((const float4*)src)[i];
}
// weight transpose+convert: B[K][N] fp32 -> Bt[N][K] bf16 (per layer via blockIdx.y)
__global__ void k_wt(const float* __restrict__ B, __nv_bfloat16* __restrict__ Bt,
                     int K, int N) {
    int i = blockIdx.x * blockDim.x + threadIdx.x;
    if (i >= K * N) return;
    const float* Bl = B + (size_t)blockIdx.y * K * N;
    __nv_bfloat16* Btl = Bt + (size_t)blockIdx.y * K * N;
    int k = i / N, n = i % N;
    Btl[(size_t)n * K + k] = __float2bfloat16(Bl[i]);
}

// ---------------- CSR build ----------------
__global__ void k_deg(const int* __restrict__ dst) {
    int e = blockIdx.x * blockDim.x + threadIdx.x;
    if (e < EE) atomicAdd(&g_deg[dst[e]], 1);
}
__global__ void k_scanA() {
    __shared__ float s[256];
    int tid = threadIdx.x;
    int n = blockIdx.x * 256 + tid;
    float v = (n < NN) ? (float)g_deg[n] : 0.0f;
    s[tid] = v;
    __syncthreads();
#pragma unroll
    for (int off = 1; off < 256; off <<= 1) {
        float t = (tid >= off) ? s[tid - off] : 0.0f;
        __syncthreads();
        s[tid] += t;
        __syncthreads();
    }
    if (n < NN) g_rowptr[n + 1] = (int)s[tid];
    if (tid == 255) g_blocksums[blockIdx.x] = (int)s[255];
}
__global__ void k_scanB(int nb) {
    if (threadIdx.x == 0) {
        int run = 0;
        for (int b = 0; b < nb; b++) { int t = g_blocksums[b]; g_blocksums[b] = run; run += t; }
    }
}
__global__ void k_scanC() {
    int n = blockIdx.x * blockDim.x + threadIdx.x;
    if (n < NN) g_rowptr[n + 1] += g_blocksums[n / 256];
    if (n == 0) g_rowptr[0] = 0;
}
__global__ void k_scatter(const int* __restrict__ src, const int* __restrict__ dst) {
    int e = blockIdx.x * blockDim.x + threadIdx.x;
    if (e >= EE) return;
    int d = dst[e];
    int p = g_rowptr[d] + atomicAdd(&g_fill[d], 1);
    g_esrc[p] = src[e];
    g_edst[p] = d;
    g_eid[p] = e;
}
// permute edge_attr into dst-sorted order, convert to bf16
__global__ void k_permute_eattr(const float* __restrict__ eattr) {
    int idx = blockIdx.x * blockDim.x + threadIdx.x;  // over EE*32 float4s
    if (idx >= EE * 32) return;
    int j = idx >> 5, q = idx & 31;
    float4 v = ((const float4*)eattr)[(size_t)g_eid[j] * 32 + q];
    __nv_bfloat16* o = &b_eattr[(size_t)j * CC + q * 4];
    *(__nv_bfloat162*)&o[0] = __floats2bfloat162_rn(v.x, v.y);
    *(__nv_bfloat162*)&o[2] = __floats2bfloat162_rn(v.z, v.w);
}
__global__ void k_cnt(const int* __restrict__ batch) {
    int n = blockIdx.x * blockDim.x + threadIdx.x;
    if (n < NN) atomicAdd(&g_cntf[batch[n]], 1.0f);
}

// ---------------- BF16 tensor-core GEMM (cp.async double-buffered) ----------------
// C[M,Nn] = A[M,K] @ B[K,Nn], A bf16 row-major, Bt = B^T bf16 [Nn][K] row-major.
// Block tile 128x128x32, mma.m16n8k16.bf16, fp32 accum, fused bias+gelu.
// OUTBF: 1 -> bf16 output, 0 -> fp32 output. Requires Nn%128==0, K%32==0.
template <int ACT, int OUTBF>
__global__ void __launch_bounds__(256, 2)
bgemm_k(const __nv_bfloat16* __restrict__ A, const __nv_bfloat16* __restrict__ Bt,
        const float* __restrict__ bias, void* __restrict__ Cm,
        int M, int Nn, int K) {
    extern __shared__ char smc[];
    __nv_bfloat16* sbase = (__nv_bfloat16*)smc;

    const int tid = threadIdx.x;
    const int warpId = tid >> 5;
    const int lane = tid & 31;
    const int g = lane >> 2, tig = lane & 3;
    const int mBase = blockIdx.y * 128;
    const int nBase = blockIdx.x * 128;
    const int mW = (warpId >> 2) * 64;
    const int nW = (warpId & 3) * 32;

    float acc[4][4][4];
#pragma unroll
    for (int mt = 0; mt < 4; mt++)
#pragma unroll
        for (int nt = 0; nt < 4; nt++)
#pragma unroll
            for (int q = 0; q < 4; q++) acc[mt][nt][q] = 0.0f;

    const int nIter = K >> 5;

    auto prefetch = [&](int kt, int s) {
        int k0 = kt << 5;
        __nv_bfloat16* As = sbase + s * 2 * TILEBF;
        __nv_bfloat16* Bs = As + TILEBF;
#pragma unroll
        for (int p = 0; p < 2; p++) {
            int c = tid + p * 256;              // 512 16B-chunks
            int row = c >> 2, c16 = (c & 3) * 8;
            int gr = mBase + row;
            if (gr >= M) gr = M - 1;            // clamp: rows discarded in epilogue
            cpasync16(&As[row * BST + c16], &A[(size_t)gr * K + k0 + c16]);
        }
#pragma unroll
        for (int p = 0; p < 2; p++) {
            int c = tid + p * 256;
            int row = c >> 2, c16 = (c & 3) * 8;
            cpasync16(&Bs[row * BST + c16], &Bt[(size_t)(nBase + row) * K + k0 + c16]);
        }
        cp_commit();
    };

    prefetch(0, 0);
    for (int kt = 0; kt < nIter; kt++) {
        int s = kt & 1;
        if (kt + 1 < nIter) prefetch(kt + 1, (kt + 1) & 1);
        else cp_commit();
        cp_wait1();
        __syncthreads();
        const unsigned* Asu = (const unsigned*)(sbase + s * 2 * TILEBF);
        const unsigned* Bsu = (const unsigned*)(sbase + s * 2 * TILEBF + TILEBF);
#pragma unroll
        for (int ks = 0; ks < 2; ks++) {
            int k8 = ks * 8;
            unsigned bfr[4][2];
#pragma unroll
            for (int nt = 0; nt < 4; nt++) {
                int nc = nW + nt * 8 + g;
                bfr[nt][0] = Bsu[nc * BSTU + k8 + tig];
                bfr[nt][1] = Bsu[nc * BSTU + k8 + tig + 4];
            }
            unsigned afr[4][4];
#pragma unroll
            for (int mt = 0; mt < 4; mt++) {
                int m0 = mW + mt * 16 + g;
                afr[mt][0] = Asu[m0 * BSTU + k8 + tig];
                afr[mt][1] = Asu[(m0 + 8) * BSTU + k8 + tig];
                afr[mt][2] = Asu[m0 * BSTU + k8 + tig + 4];
                afr[mt][3] = Asu[(m0 + 8) * BSTU + k8 + tig + 4];
            }
#pragma unroll
            for (int mt = 0; mt < 4; mt++)
#pragma unroll
                for (int nt = 0; nt < 4; nt++)
                    mma_bf16(acc[mt][nt], afr[mt], bfr[nt]);
        }
        __syncthreads();
    }

    // epilogue
#pragma unroll
    for (int mt = 0; mt < 4; mt++) {
        int r0 = mBase + mW + mt * 16 + g;
        int r1 = r0 + 8;
#pragma unroll
        for (int nt = 0; nt < 4; nt++) {
            int c0 = nBase + nW + nt * 8 + 2 * tig;
            float b0 = 0.f, b1 = 0.f;
            if (bias) { b0 = bias[c0]; b1 = bias[c0 + 1]; }
            float v0 = acc[mt][nt][0] + b0, v1 = acc[mt][nt][1] + b1;
            float v2 = acc[mt][nt][2] + b0, v3 = acc[mt][nt][3] + b1;
            if (ACT == 1) { v0 = geluf(v0); v1 = geluf(v1); v2 = geluf(v2); v3 = geluf(v3); }
            if (OUTBF) {
                __nv_bfloat16* C = (__nv_bfloat16*)Cm;
                if (r0 < M) *(__nv_bfloat162*)&C[(size_t)r0 * Nn + c0] = __floats2bfloat162_rn(v0, v1);
                if (r1 < M) *(__nv_bfloat162*)&C[(size_t)r1 * Nn + c0] = __floats2bfloat162_rn(v2, v3);
            } else {
                float* C = (float*)Cm;
                if (r0 < M) *(float2*)&C[(size_t)r0 * Nn + c0] = make_float2(v0, v1);
                if (r1 < M) *(float2*)&C[(size_t)r1 * Nn + c0] = make_float2(v2, v3);
            }
        }
    }
}

// ---------------- fused edge GEMM + attention score (bf16) ----------------
// ea tile (128 edges x 128 ch = one head) in registers; reduces
// e[j,h] = sum_c lrelu(ea + xl[src]+xr[dst]) * att[c]. Grid: (HH, EE/128).
__global__ void __launch_bounds__(256, 2)
bscore_k(const __nv_bfloat16* __restrict__ A, const __nv_bfloat16* __restrict__ Bt,
         const float* __restrict__ att) {
    extern __shared__ char smc[];
    __nv_bfloat16* sbase = (__nv_bfloat16*)smc;
    float* satt = (float*)(smc + BGEMM_SMEM);
    int* ssrc = (int*)(satt + 128);
    int* sdst = ssrc + 128;
    float* sred = (float*)(sdst + 128);

    const int tid = threadIdx.x;
    const int warpId = tid >> 5;
    const int lane = tid & 31;
    const int g = lane >> 2, tig = lane & 3;
    const int nBase = blockIdx.x * 128;   // head * 128
    const int mBase = blockIdx.y * 128;   // edge tile
    const int mW = (warpId >> 2) * 64;
    const int nW = (warpId & 3) * 32;
    const int K = CC;

    if (tid < 128) {
        satt[tid] = att[nBase + tid];
        ssrc[tid] = g_esrc[mBase + tid];
        sdst[tid] = g_edst[mBase + tid];
        sred[tid] = 0.0f;
    }

    float acc[4][4][4];
#pragma unroll
    for (int mt = 0; mt < 4; mt++)
#pragma unroll
        for (int nt = 0; nt < 4; nt++)
#pragma unroll
            for (int q = 0; q < 4; q++) acc[mt][nt][q] = 0.0f;

    const int nIter = K >> 5;   // 4

    auto prefetch = [&](int kt, int s) {
        int k0 = kt << 5;
        __nv_bfloat16* As = sbase + s * 2 * TILEBF;
        __nv_bfloat16* Bs = As + TILEBF;
#pragma unroll
        for (int p = 0; p < 2; p++) {
            int c = tid + p * 256;
            int row = c >> 2, c16 = (c & 3) * 8;
            cpasync16(&As[row * BST + c16], &A[(size_t)(mBase + row) * K + k0 + c16]);
        }
#pragma unroll
        for (int p = 0; p < 2; p++) {
            int c = tid + p * 256;
            int row = c >> 2, c16 = (c & 3) * 8;
            cpasync16(&Bs[row * BST + c16], &Bt[(size_t)(nBase + row) * K + k0 + c16]);
        }
        cp_commit();
    };

    prefetch(0, 0);
    for (int kt = 0; kt < nIter; kt++) {
        int s = kt & 1;
        if (kt + 1 < nIter) prefetch(kt + 1, (kt + 1) & 1);
        else cp_commit();
        cp_wait1();
        __syncthreads();
        const unsigned* Asu = (const unsigned*)(sbase + s * 2 * TILEBF);
        const unsigned* Bsu = (const unsigned*)(sbase + s * 2 * TILEBF + TILEBF);
#pragma unroll
        for (int ks = 0; ks < 2; ks++) {
            int k8 = ks * 8;
            unsigned bfr[4][2];
#pragma unroll
            for (int nt = 0; nt < 4; nt++) {
                int nc = nW + nt * 8 + g;
                bfr[nt][0] = Bsu[nc * BSTU + k8 + tig];
                bfr[nt][1] = Bsu[nc * BSTU + k8 + tig + 4];
            }
            unsigned afr[4][4];
#pragma unroll
            for (int mt = 0; mt < 4; mt++) {
                int m0 = mW + mt * 16 + g;
                afr[mt][0] = Asu[m0 * BSTU + k8 + tig];
                afr[mt][1] = Asu[(m0 + 8) * BSTU + k8 + tig];
                afr[mt][2] = Asu[m0 * BSTU + k8 + tig + 4];
                afr[mt][3] = Asu[(m0 + 8) * BSTU + k8 + tig + 4];
            }
#pragma unroll
            for (int mt = 0; mt < 4; mt++)
#pragma unroll
                for (int nt = 0; nt < 4; nt++)
                    mma_bf16(acc[mt][nt], afr[mt], bfr[nt]);
        }
        __syncthreads();
    }

    // fused score epilogue (bf16 gathers)
#pragma unroll
    for (int mt = 0; mt < 4; mt++) {
        int lr0 = mW + mt * 16 + g;
        int lr1 = lr0 + 8;
        int s0 = ssrc[lr0], dd0 = sdst[lr0];
        int s1 = ssrc[lr1], dd1 = sdst[lr1];
        float p0 = 0.0f, p1 = 0.0f;
#pragma unroll
        for (int nt = 0; nt < 4; nt++) {
            int cl = nW + nt * 8 + 2 * tig;
            int cg = nBase + cl;
            float at0 = satt[cl], at1 = satt[cl + 1];
            float2 xa0 = __bfloat1622float2(*(const __nv_bfloat162*)&b_xl[(size_t)s0 * HC + cg]);
            float2 xb0 = __bfloat1622float2(*(const __nv_bfloat162*)&b_xr[(size_t)dd0 * HC + cg]);
            float2 xa1 = __bfloat1622float2(*(const __nv_bfloat162*)&b_xl[(size_t)s1 * HC + cg]);
            float2 xb1 = __bfloat1622float2(*(const __nv_bfloat162*)&b_xr[(size_t)dd1 * HC + cg]);
            p0 += lreluf(acc[mt][nt][0] + xa0.x + xb0.x) * at0 +
                  lreluf(acc[mt][nt][1] + xa0.y + xb0.y) * at1;
            p1 += lreluf(acc[mt][nt][2] + xa1.x + xb1.x) * at0 +
                  lreluf(acc[mt][nt][3] + xa1.y + xb1.y) * at1;
        }
        p0 += __shfl_xor_sync(0xffffffffu, p0, 1);
        p0 += __shfl_xor_sync(0xffffffffu, p0, 2);
        p1 += __shfl_xor_sync(0xffffffffu, p1, 1);
        p1 += __shfl_xor_sync(0xffffffffu, p1, 2);
        if (tig == 0) {
            atomicAdd(&sred[lr0], p0);
            atomicAdd(&sred[lr1], p1);
        }
    }
    __syncthreads();
    if (tid < 128)
        d_esc[(size_t)(mBase + tid) * HH + blockIdx.x] = sred[tid];
}

// ---------------- per-layer kernels ----------------
// WmI[g][k] = sum_c Wm[k][c] * instr[g][c]
__global__ void k_wmI(const float* __restrict__ Wm, const float* __restrict__ instr) {
    int g = blockIdx.x, k = threadIdx.x;
    const float* wr = Wm + (size_t)k * CC;
    const float* iv = instr + (size_t)g * CC;
    float s = 0.0f;
    for (int c = 0; c < CC; c++) s += wr[c] * iv[c];
    g_WmI[g * CC + k] = s;
}

// mask + x_in (warp per node); writes bf16 x_in
__global__ void k_mask_xin(const int* __restrict__ batch) {
    int w = (blockIdx.x * blockDim.x + threadIdx.x) >> 5;
    int lane = threadIdx.x & 31;
    if (w >= NN) return;
    int g = batch[w];
    float4 hv = ((const float4*)&d_h[(size_t)w * CC])[lane];
    float4 wv = ((const float4*)&g_WmI[g * CC])[lane];
    float p = hv.x * wv.x + hv.y * wv.y + hv.z * wv.z + hv.w * wv.w;
    p = warpRedSum(p);
    float mk = 1.0f / (1.0f + expf(-p * INV_SQRT_C));
    if (lane == 0) d_mask[w] = mk;
    __nv_bfloat162* o = (__nv_bfloat162*)&b_xin[(size_t)w * CC];
    o[lane * 2] = __floats2bfloat162_rn(mk * hv.x, mk * hv.y);
    o[lane * 2 + 1] = __floats2bfloat162_rn(mk * hv.z, mk * hv.w);
}

// per-dst-node softmax over incident edges (warp per node), normalizes d_esc in place
__global__ void k_edge_softmax() {
    int w = (blockIdx.x * blockDim.x + threadIdx.x) >> 5;
    int lane = threadIdx.x & 31;
    if (w >= NN) return;
    int j0 = g_rowptr[w], j1 = g_rowptr[w + 1];
    float m0 = -1e30f, m1 = -1e30f, m2 = -1e30f, m3 = -1e30f;
    for (int j = j0 + lane; j < j1; j += 32) {
        float4 e = *(const float4*)&d_esc[(size_t)j * 4];
        m0 = fmaxf(m0, e.x); m1 = fmaxf(m1, e.y); m2 = fmaxf(m2, e.z); m3 = fmaxf(m3, e.w);
    }
    m0 = warpRedMax(m0); m1 = warpRedMax(m1); m2 = warpRedMax(m2); m3 = warpRedMax(m3);
    float s0 = 0.f, s1 = 0.f, s2 = 0.f, s3 = 0.f;
    for (int j = j0 + lane; j < j1; j += 32) {
        float4 e = *(const float4*)&d_esc[(size_t)j * 4];
        e.x = expf(e.x - m0); e.y = expf(e.y - m1);
        e.z = expf(e.z - m2); e.w = expf(e.w - m3);
        s0 += e.x; s1 += e.y; s2 += e.z; s3 += e.w;
        *(float4*)&d_esc[(size_t)j * 4] = e;
    }
    s0 = warpRedSum(s0); s1 = warpRedSum(s1); s2 = warpRedSum(s2); s3 = warpRedSum(s3);
    float i0 = 1.0f / (s0 + 1e-16f), i1 = 1.0f / (s1 + 1e-16f);
    float i2 = 1.0f / (s2 + 1e-16f), i3 = 1.0f / (s3 + 1e-16f);
    for (int j = j0 + lane; j < j1; j += 32) {
        float4 e = *(const float4*)&d_esc[(size_t)j * 4];
        e.x *= i0; e.y *= i1; e.z *= i2; e.w *= i3;
        *(float4*)&d_esc[(size_t)j * 4] = e;
    }
}

// aggregate: out[n,h,c] = sum_j alpha[j,h] * xl[src_j, h, c]  (bf16 in/out, fp32 accum)
__global__ void k_aggregate() {
    int n = blockIdx.x;
    int c = threadIdx.x;
    int j0 = g_rowptr[n], j1 = g_rowptr[n + 1];
    float a0 = 0.f, a1 = 0.f, a2 = 0.f, a3 = 0.f;
    for (int j = j0; j < j1; j++) {
        float4 wgt = *(const float4*)&d_esc[(size_t)j * 4];
        const __nv_bfloat16* xl = &b_xl[(size_t)g_esrc[j] * HC];
        a0 += wgt.x * __bfloat162float(xl[c]);
        a1 += wgt.y * __bfloat162float(xl[128 + c]);
        a2 += wgt.z * __bfloat162float(xl[256 + c]);
        a3 += wgt.w * __bfloat162float(xl[384 + c]);
    }
    size_t o = (size_t)n * HC;
    b_out[o + c] = __float2bfloat16(a0);
    b_out[o + 128 + c] = __float2bfloat16(a1);
    b_out[o + 256 + c] = __float2bfloat16(a2);
    b_out[o + 384 + c] = __float2bfloat16(a3);
}

// per-layer graph-scope accumulator init
__global__ void k_init_graph() {
    int i = blockIdx.x * blockDim.x + threadIdx.x;
    if (i < GG * CC) { g_meanAcc[i] = 0.0f; g_varAcc[i] = 0.0f; }
    if (i < GG) { g_gmax[i] = -__int_as_float(0x7f800000); g_gsum[i] = 0.0f; }
}

// s[n] = dot(instr[batch[n]], cr[n]) * inv_sqrt_c ; atomicMax per graph
__global__ void k_sdpa_score(const float* __restrict__ instr, const int* __restrict__ batch) {
    int w = (blockIdx.x * blockDim.x + threadIdx.x) >> 5;
    int lane = threadIdx.x & 31;
    if (w >= NN) return;
    int g = batch[w];
    float4 iv = ((const float4*)&instr[(size_t)g * CC])[lane];
    float4 cv = ((const float4*)&g_cr[(size_t)w * CC])[lane];
    float p = iv.x * cv.x + iv.y * cv.y + iv.z * cv.z + iv.w * cv.w;
    p = warpRedSum(p) * INV_SQRT_C;
    if (lane == 0) {
        g_s[w] = p;
        atomicMaxF(&g_gmax[g], p);
    }
}
__global__ void k_sdpa_exp(const int* __restrict__ batch) {
    int n = blockIdx.x * blockDim.x + threadIdx.x;
    if (n >= NN) return;
    int g = batch[n];
    float e = expf(g_s[n] - g_gmax[g]);
    g_s[n] = e;
    atomicAdd(&g_gsum[g], e);
}
__global__ void k_sdpa_norm(const int* __restrict__ batch) {
    int n = blockIdx.x * blockDim.x + threadIdx.x;
    if (n >= NN) return;
    g_s[n] = g_s[n] / (g_gsum[batch[n]] + 1e-16f);
}

// scale cr by attention weight + accumulate per-graph mean (exploits sorted batch)
__global__ void k_scale_mean(const int* __restrict__ batch) {
    int c = threadIdx.x;  // 128
    int n0 = blockIdx.x * 64;
    int n1 = min(n0 + 64, NN);
    float acc = 0.0f;
    int curg = batch[n0];
    for (int n = n0; n < n1; n++) {
        int g = batch[n];
        float v = g_cr[(size_t)n * CC + c] * g_s[n];
        g_cr[(size_t)n * CC + c] = v;
        if (g != curg) { atomicAdd(&g_meanAcc[curg * CC + c], acc); acc = 0.0f; curg = g; }
        acc += v;
    }
    atomicAdd(&g_meanAcc[curg * CC + c], acc);
}
__global__ void k_mean_div() {
    int i = blockIdx.x * blockDim.x + threadIdx.x;
    if (i < GG * CC) g_mean[i] = g_meanAcc[i] / fmaxf(g_cntf[i / CC], 1.0f);
}
__global__ void k_var_acc(const int* __restrict__ batch, const float* __restrict__ alpha) {
    int c = threadIdx.x;
    int n0 = blockIdx.x * 64;
    int n1 = min(n0 + 64, NN);
    float al = alpha[c];
    float acc = 0.0f;
    int curg = batch[n0];
    for (int n = n0; n < n1; n++) {
        int g = batch[n];
        float v = g_cr[(size_t)n * CC + c] - al * g_mean[g * CC + c];
        if (g != curg) { atomicAdd(&g_varAcc[curg * CC + c], acc); acc = 0.0f; curg = g; }
        acc += v * v;
    }
    atomicAdd(&g_varAcc[curg * CC + c], acc);
}
__global__ void k_var_div() {
    int i = blockIdx.x * blockDim.x + threadIdx.x;
    if (i < GG * CC) g_var[i] = g_varAcc[i] / fmaxf(g_cntf[i / CC], 1.0f);
}
// normalize + residual + mask gate -> dst (d_h for layers 0..2, d_out on last)
__global__ void k_norm_resid(const int* __restrict__ batch, const float* __restrict__ alpha,
                             const float* __restrict__ gamma, const float* __restrict__ beta,
                             float* __restrict__ dstp) {
    int idx = blockIdx.x * blockDim.x + threadIdx.x;
    if (idx >= NN * CC) return;
    int n = idx >> 7, c = idx & 127;
    int g = batch[n];
    float sub = g_cr[idx] - alpha[c] * g_mean[g * CC + c];
    float v = gamma[c] * sub * rsqrtf(g_var[g * CC + c] + EPSN) + beta[c];
    dstp[idx] = d_mask[n] * (v + d_h[idx]);
}

// ---------------- launch ----------------
extern "C" void kernel_launch(void* const* d_in, const int* in_sizes, int n_in,
                              void* d_out, int out_size) {
    const float* x = (const float*)d_in[0];
    const int* eidx = (const int*)d_in[1];
    const float* instr = (const float*)d_in[2];
    // d_in[3] = global_language_feats (unused by reference)
    const float* eattr = (const float*)d_in[4];
    const int* batch = (const int*)d_in[5];
    const float* Wl = (const float*)d_in[6];
    const float* Wr = (const float*)d_in[7];
    const float* We = (const float*)d_in[8];
    const float* att = (const float*)d_in[9];
    const float* Wm = (const float*)d_in[10];
    const float* p1w = (const float*)d_in[11];
    const float* p1b = (const float*)d_in[12];
    const float* p2w = (const float*)d_in[13];
    const float* p2b = (const float*)d_in[14];
    const float* gng = (const float*)d_in[15];
    const float* gnb = (const float*)d_in[16];
    const float* gna = (const float*)d_in[17];
    const int* src = eidx;
    const int* dst = eidx + EE;
    float* outp = (float*)d_out;

    cudaFuncSetAttribute(bgemm_k<0, 1>, cudaFuncAttributeMaxDynamicSharedMemorySize, BGEMM_SMEM);
    cudaFuncSetAttribute(bgemm_k<1, 1>, cudaFuncAttributeMaxDynamicSharedMemorySize, BGEMM_SMEM);
    cudaFuncSetAttribute(bgemm_k<1, 0>, cudaFuncAttributeMaxDynamicSharedMemorySize, BGEMM_SMEM);
    cudaFuncSetAttribute(bscore_k, cudaFuncAttributeMaxDynamicSharedMemorySize, BSCORE_SMEM);

    int* pdeg; cudaGetSymbolAddress((void**)&pdeg, g_deg);
    int* pfill; cudaGetSymbolAddress((void**)&pfill, g_fill);
    float* pcnt; cudaGetSymbolAddress((void**)&pcnt, g_cntf);
    float* ph; cudaGetSymbolAddress((void**)&ph, d_h);

    __nv_bfloat16* pxin; cudaGetSymbolAddress((void**)&pxin, b_xin);
    __nv_bfloat16* peattr; cudaGetSymbolAddress((void**)&peattr, b_eattr);
    __nv_bfloat16* pxl; cudaGetSymbolAddress((void**)&pxl, b_xl);
    __nv_bfloat16* pxr; cudaGetSymbolAddress((void**)&pxr, b_xr);
    __nv_bfloat16* pout; cudaGetSymbolAddress((void**)&pout, b_out);
    __nv_bfloat16* pcr1; cudaGetSymbolAddress((void**)&pcr1, b_cr1);
    __nv_bfloat16* pwtl; cudaGetSymbolAddress((void**)&pwtl, b_wtl);
    __nv_bfloat16* pwtr; cudaGetSymbolAddress((void**)&pwtr, b_wtr);
    __nv_bfloat16* pwte; cudaGetSymbolAddress((void**)&pwte, b_wte);
    __nv_bfloat16* pwtp1; cudaGetSymbolAddress((void**)&pwtp1, b_wtp1);
    __nv_bfloat16* pwtp2; cudaGetSymbolAddress((void**)&pwtp2, b_wtp2);
    float* pcr; cudaGetSymbolAddress((void**)&pcr, g_cr);

    const int NB256 = (NN + 255) / 256;       // 196
    const int EB256 = (EE + 255) / 256;

    // ---- startup (runs every replay; deterministic) ----
    k_zero_int<<<NB256, 256>>>(pdeg, NN);
    k_zero_int<<<NB256, 256>>>(pfill, NN);
    k_zero_float<<<1, 64>>>(pcnt, GG);
    k_deg<<<EB256, 256>>>(dst);
    k_scanA<<<NB256, 256>>>();
    k_scanB<<<1, 32>>>(NB256);
    k_scanC<<<(NN + 255) / 256, 256>>>();
    k_scatter<<<EB256, 256>>>(src, dst);
    k_permute_eattr<<<(EE * 32 + 255) / 256, 256>>>(eattr);
    k_cnt<<<NB256, 256>>>(batch);
    k_copy4<<<((NN * CC / 4) + 255) / 256, 256>>>(ph, x, NN * CC / 4);
    // weight transpose+convert (all layers)
    k_wt<<<dim3((CC * HC + 255) / 256, LL), 256>>>(Wl, pwtl, CC, HC);
    k_wt<<<dim3((CC * HC + 255) / 256, LL), 256>>>(Wr, pwtr, CC, HC);
    k_wt<<<dim3((CC * HC + 255) / 256, LL), 256>>>(We, pwte, CC, HC);
    k_wt<<<dim3((HC * MIDD + 255) / 256, LL), 256>>>(p1w, pwtp1, HC, MIDD);
    k_wt<<<dim3((MIDD * CC + 255) / 256, LL), 256>>>(p2w, pwtp2, MIDD, CC);

    for (int i = 0; i < LL; i++) {
        const float* Wm_i = Wm + (size_t)i * CC * CC;
        const float* instr_i = instr + (size_t)i * GG * CC;
        const float* att_i = att + (size_t)i * HH * CC;
        const float* p1b_i = p1b + (size_t)i * MIDD;
        const float* p2b_i = p2b + (size_t)i * CC;
        const float* gng_i = gng + (size_t)i * CC;
        const float* gnb_i = gnb + (size_t)i * CC;
        const float* gna_i = gna + (size_t)i * CC;
        __nv_bfloat16* wtl_i = pwtl + (size_t)i * HC * CC;
        __nv_bfloat16* wtr_i = pwtr + (size_t)i * HC * CC;
        __nv_bfloat16* wte_i = pwte + (size_t)i * HC * CC;
        __nv_bfloat16* wtp1_i = pwtp1 + (size_t)i * MIDD * HC;
        __nv_bfloat16* wtp2_i = pwtp2 + (size_t)i * CC * MIDD;

        // mask + x_in (bf16)
        k_wmI<<<GG, CC>>>(Wm_i, instr_i);
        k_mask_xin<<<(NN * 32 + 255) / 256, 256>>>(batch);

        // node projections (bf16 tensor cores) -> bf16 xl/xr
        dim3 gxl(HC / 128, (NN + 127) / 128);
        bgemm_k<0, 1><<<gxl, 256, BGEMM_SMEM>>>(pxin, wtl_i, nullptr, pxl, NN, HC, CC);
        bgemm_k<0, 1><<<gxl, 256, BGEMM_SMEM>>>(pxin, wtr_i, nullptr, pxr, NN, HC, CC);

        // fused edge GEMM + attention score
        dim3 gsc(HH, EE / 128);
        bscore_k<<<gsc, 256, BSCORE_SMEM>>>(peattr, wte_i, att_i);

        // attention softmax + aggregation (bf16 out)
        k_edge_softmax<<<(NN * 32 + 255) / 256, 256>>>();
        k_aggregate<<<NN, 128>>>();

        // MLP (bf16 tensor cores); MLP2 outputs fp32 g_cr
        dim3 gp1(MIDD / 128, (NN + 127) / 128);
        bgemm_k<1, 1><<<gp1, 256, BGEMM_SMEM>>>(pout, wtp1_i, p1b_i, pcr1, NN, MIDD, HC);
        dim3 gp2(CC / 128, (NN + 127) / 128);
        bgemm_k<1, 0><<<gp2, 256, BGEMM_SMEM>>>(pcr1, wtp2_i, p2b_i, pcr, NN, CC, MIDD);

        // scatter attention + GraphNorm
        k_init_graph<<<(GG * CC + 255) / 256, 256>>>();
        k_sdpa_score<<<(NN * 32 + 255) / 256, 256>>>(instr_i, batch);
        k_sdpa_exp<<<NB256, 256>>>(batch);
        k_sdpa_norm<<<NB256, 256>>>(batch);
        k_scale_mean<<<(NN + 63) / 64, 128>>>(batch);
        k_mean_div<<<(GG * CC + 255) / 256, 256>>>();
        k_var_acc<<<(NN + 63) / 64, 128>>>(batch, gna_i);
        k_var_div<<<(GG * CC + 255) / 256, 256>>>();
        float* dstp = (i == LL - 1) ? outp : ph;
        k_norm_resid<<<(NN * CC + 255) / 256, 256>>>(batch, gna_i, gng_i, gnb_i, dstp);
    }
    (void)in_sizes; (void)n_in; (void)out_size;
}

// round 11
// speedup vs baseline: 3.9467x; 1.0471x over previous
#include <cuda_runtime.h>
#include <cuda_bf16.h>
#include <math.h>

// Problem constants (fixed by setup_inputs)
#define NN 50000
#define EE 400000
#define CC 128
#define HH 4
#define GG 64
#define LL 4
#define HC 512   // H*C
#define MIDD 256 // C*(H/2)

#define NEG_SLOPE 0.2f
#define EPSN 1e-5f
#define INV_SQRT_C 0.08838834764831845f

// ---------------- scratch (static device globals; no allocation) ----------------
__device__ float d_h[(size_t)NN * CC];
__device__ float d_mask[NN];
__device__ float d_esc[(size_t)EE * HH];     // scores -> unnormalized exp alphas
__device__ float g_inv[(size_t)NN * HH];     // per-node 1/softmax-sum per head
__device__ float g_cr[(size_t)NN * CC];
__device__ float g_s[NN];
__device__ float g_WmI[GG * CC];
__device__ float g_gmax[GG];
__device__ float g_gsum[GG];
__device__ float g_meanAcc[GG * CC];
__device__ float g_mean[GG * CC];
__device__ float g_varAcc[GG * CC];
__device__ float g_var[GG * CC];
__device__ float g_cntf[GG];
__device__ int g_deg[NN];
__device__ int g_fill[NN];
__device__ int g_rowptr[NN + 1];
__device__ int g_esrc[EE];
__device__ int g_edst[EE];
__device__ int g_eid[EE];
__device__ int g_blocksums[256];

// bf16 activation / weight buffers
__device__ __nv_bfloat16 b_xin[(size_t)NN * CC];
__device__ __nv_bfloat16 b_eattr[(size_t)EE * CC];
__device__ __nv_bfloat16 b_xl[(size_t)NN * HC];
__device__ __nv_bfloat16 b_xr[(size_t)NN * HC];
__device__ __nv_bfloat16 b_out[(size_t)NN * HC];
__device__ __nv_bfloat16 b_cr1[(size_t)NN * MIDD];
__device__ __nv_bfloat16 b_wtl[(size_t)LL * HC * CC];
__device__ __nv_bfloat16 b_wtr[(size_t)LL * HC * CC];
__device__ __nv_bfloat16 b_wte[(size_t)LL * HC * CC];
__device__ __nv_bfloat16 b_wtp1[(size_t)LL * MIDD * HC];
__device__ __nv_bfloat16 b_wtp2[(size_t)LL * CC * MIDD];

// ---------------- helpers ----------------
__device__ __forceinline__ float warpRedSum(float v) {
#pragma unroll
    for (int o = 16; o; o >>= 1) v += __shfl_xor_sync(0xffffffffu, v, o);
    return v;
}
__device__ __forceinline__ float warpRedMax(float v) {
#pragma unroll
    for (int o = 16; o; o >>= 1) v = fmaxf(v, __shfl_xor_sync(0xffffffffu, v, o));
    return v;
}
__device__ __forceinline__ float geluf(float x) {
    float x3 = x * x * x;
    return 0.5f * x * (1.0f + tanhf(0.7978845608028654f * (x + 0.044715f * x3)));
}
__device__ __forceinline__ float lreluf(float x) {
    return x > 0.0f ? x : NEG_SLOPE * x;
}
__device__ __forceinline__ void atomicMaxF(float* a, float v) {
    if (v >= 0.0f) atomicMax((int*)a, __float_as_int(v));
    else atomicMin((unsigned int*)a, __float_as_uint(v));
}
__device__ __forceinline__ void mma_bf16(float* d, const unsigned* a, const unsigned* b) {
    asm volatile(
        "mma.sync.aligned.m16n8k16.row.col.f32.bf16.bf16.f32 "
        "{%0,%1,%2,%3}, {%4,%5,%6,%7}, {%8,%9}, {%0,%1,%2,%3};\n"
        : "+f"(d[0]), "+f"(d[1]), "+f"(d[2]), "+f"(d[3])
        : "r"(a[0]), "r"(a[1]), "r"(a[2]), "r"(a[3]), "r"(b[0]), "r"(b[1]));
}
__device__ __forceinline__ void cpasync16(void* s, const void* g) {
    unsigned saddr = (unsigned)__cvta_generic_to_shared(s);
    asm volatile("cp.async.cg.shared.global [%0], [%1], 16;\n" :: "r"(saddr), "l"(g));
}
__device__ __forceinline__ void cp_commit() {
    asm volatile("cp.async.commit_group;\n");
}
__device__ __forceinline__ void cp_wait1() {
    asm volatile("cp.async.wait_group 1;\n");
}
__device__ __forceinline__ void cp_wait0() {
    asm volatile("cp.async.wait_group 0;\n");
}

// smem tile geometry for bgemm (bf16 units)
#define BST 40                  // bf16 per row (32 k + pad 8)
#define BSTU 20                 // u32 stride
#define TILEBF (128 * BST)      // 5120 bf16 = 10240 B per tile
#define BGEMM_SMEM (4 * TILEBF * 2)           // 2 stages x (A+B) = 40960 B

// smem geometry for bscore (full-K tiles)
#define SC_AST 136              // bf16 per row (128 k + pad 8)
#define SC_ASTU 68              // u32 stride
#define SC_TILE_BYTES (128 * SC_AST * 2)      // 34816 B
#define SCORE_SMEM (2 * SC_TILE_BYTES + 3584) // A + B + satt/ssrc/sdst/sred

// ---------------- init / utility kernels ----------------
__global__ void k_zero_int(int* p, int n) {
    int i = blockIdx.x * blockDim.x + threadIdx.x;
    if (i < n) p[i] = 0;
}
__global__ void k_zero_float(float* p, int n) {
    int i = blockIdx.x * blockDim.x + threadIdx.x;
    if (i < n) p[i] = 0.0f;
}
__global__ void k_copy4(float* __restrict__ dst, const float* __restrict__ src, int n4) {
    int i = blockIdx.x * blockDim.x + threadIdx.x;
    if (i < n4) ((float4*)dst)[i] = ((const float4*)src)[i];
}
// weight transpose+convert: B[K][N] fp32 -> Bt[N][K] bf16 (per layer via blockIdx.y)
__global__ void k_wt(const float* __restrict__ B, __nv_bfloat16* __restrict__ Bt,
                     int K, int N) {
    int i = blockIdx.x * blockDim.x + threadIdx.x;
    if (i >= K * N) return;
    const float* Bl = B + (size_t)blockIdx.y * K * N;
    __nv_bfloat16* Btl = Bt + (size_t)blockIdx.y * K * N;
    int k = i / N, n = i % N;
    Btl[(size_t)n * K + k] = __float2bfloat16(Bl[i]);
}

// ---------------- CSR build ----------------
__global__ void k_deg(const int* __restrict__ dst) {
    int e = blockIdx.x * blockDim.x + threadIdx.x;
    if (e < EE) atomicAdd(&g_deg[dst[e]], 1);
}
__global__ void k_scanA() {
    __shared__ float s[256];
    int tid = threadIdx.x;
    int n = blockIdx.x * 256 + tid;
    float v = (n < NN) ? (float)g_deg[n] : 0.0f;
    s[tid] = v;
    __syncthreads();
#pragma unroll
    for (int off = 1; off < 256; off <<= 1) {
        float t = (tid >= off) ? s[tid - off] : 0.0f;
        __syncthreads();
        s[tid] += t;
        __syncthreads();
    }
    if (n < NN) g_rowptr[n + 1] = (int)s[tid];
    if (tid == 255) g_blocksums[blockIdx.x] = (int)s[255];
}
__global__ void k_scanB(int nb) {
    if (threadIdx.x == 0) {
        int run = 0;
        for (int b = 0; b < nb; b++) { int t = g_blocksums[b]; g_blocksums[b] = run; run += t; }
    }
}
__global__ void k_scanC() {
    int n = blockIdx.x * blockDim.x + threadIdx.x;
    if (n < NN) g_rowptr[n + 1] += g_blocksums[n / 256];
    if (n == 0) g_rowptr[0] = 0;
}
__global__ void k_scatter(const int* __restrict__ src, const int* __restrict__ dst) {
    int e = blockIdx.x * blockDim.x + threadIdx.x;
    if (e >= EE) return;
    int d = dst[e];
    int p = g_rowptr[d] + atomicAdd(&g_fill[d], 1);
    g_esrc[p] = src[e];
    g_edst[p] = d;
    g_eid[p] = e;
}
// permute edge_attr into dst-sorted order, convert to bf16
__global__ void k_permute_eattr(const float* __restrict__ eattr) {
    int idx = blockIdx.x * blockDim.x + threadIdx.x;  // over EE*32 float4s
    if (idx >= EE * 32) return;
    int j = idx >> 5, q = idx & 31;
    float4 v = ((const float4*)eattr)[(size_t)g_eid[j] * 32 + q];
    __nv_bfloat16* o = &b_eattr[(size_t)j * CC + q * 4];
    *(__nv_bfloat162*)&o[0] = __floats2bfloat162_rn(v.x, v.y);
    *(__nv_bfloat162*)&o[2] = __floats2bfloat162_rn(v.z, v.w);
}
__global__ void k_cnt(const int* __restrict__ batch) {
    int n = blockIdx.x * blockDim.x + threadIdx.x;
    if (n < NN) atomicAdd(&g_cntf[batch[n]], 1.0f);
}

// ---------------- BF16 tensor-core GEMM (cp.async double-buffered) ----------------
template <int ACT, int OUTBF>
__global__ void __launch_bounds__(256, 2)
bgemm_k(const __nv_bfloat16* __restrict__ A, const __nv_bfloat16* __restrict__ Bt,
        const float* __restrict__ bias, void* __restrict__ Cm,
        int M, int Nn, int K) {
    extern __shared__ char smc[];
    __nv_bfloat16* sbase = (__nv_bfloat16*)smc;

    const int tid = threadIdx.x;
    const int warpId = tid >> 5;
    const int lane = tid & 31;
    const int g = lane >> 2, tig = lane & 3;
    const int mBase = blockIdx.y * 128;
    const int nBase = blockIdx.x * 128;
    const int mW = (warpId >> 2) * 64;
    const int nW = (warpId & 3) * 32;

    float acc[4][4][4];
#pragma unroll
    for (int mt = 0; mt < 4; mt++)
#pragma unroll
        for (int nt = 0; nt < 4; nt++)
#pragma unroll
            for (int q = 0; q < 4; q++) acc[mt][nt][q] = 0.0f;

    const int nIter = K >> 5;

    auto prefetch = [&](int kt, int s) {
        int k0 = kt << 5;
        __nv_bfloat16* As = sbase + s * 2 * TILEBF;
        __nv_bfloat16* Bs = As + TILEBF;
#pragma unroll
        for (int p = 0; p < 2; p++) {
            int c = tid + p * 256;              // 512 16B-chunks
            int row = c >> 2, c16 = (c & 3) * 8;
            int gr = mBase + row;
            if (gr >= M) gr = M - 1;            // clamp: rows discarded in epilogue
            cpasync16(&As[row * BST + c16], &A[(size_t)gr * K + k0 + c16]);
        }
#pragma unroll
        for (int p = 0; p < 2; p++) {
            int c = tid + p * 256;
            int row = c >> 2, c16 = (c & 3) * 8;
            cpasync16(&Bs[row * BST + c16], &Bt[(size_t)(nBase + row) * K + k0 + c16]);
        }
        cp_commit();
    };

    prefetch(0, 0);
    for (int kt = 0; kt < nIter; kt++) {
        int s = kt & 1;
        if (kt + 1 < nIter) prefetch(kt + 1, (kt + 1) & 1);
        else cp_commit();
        cp_wait1();
        __syncthreads();
        const unsigned* Asu = (const unsigned*)(sbase + s * 2 * TILEBF);
        const unsigned* Bsu = (const unsigned*)(sbase + s * 2 * TILEBF + TILEBF);
#pragma unroll
        for (int ks = 0; ks < 2; ks++) {
            int k8 = ks * 8;
            unsigned bfr[4][2];
#pragma unroll
            for (int nt = 0; nt < 4; nt++) {
                int nc = nW + nt * 8 + g;
                bfr[nt][0] = Bsu[nc * BSTU + k8 + tig];
                bfr[nt][1] = Bsu[nc * BSTU + k8 + tig + 4];
            }
            unsigned afr[4][4];
#pragma unroll
            for (int mt = 0; mt < 4; mt++) {
                int m0 = mW + mt * 16 + g;
                afr[mt][0] = Asu[m0 * BSTU + k8 + tig];
                afr[mt][1] = Asu[(m0 + 8) * BSTU + k8 + tig];
                afr[mt][2] = Asu[m0 * BSTU + k8 + tig + 4];
                afr[mt][3] = Asu[(m0 + 8) * BSTU + k8 + tig + 4];
            }
#pragma unroll
            for (int mt = 0; mt < 4; mt++)
#pragma unroll
                for (int nt = 0; nt < 4; nt++)
                    mma_bf16(acc[mt][nt], afr[mt], bfr[nt]);
        }
        __syncthreads();
    }

    // epilogue
#pragma unroll
    for (int mt = 0; mt < 4; mt++) {
        int r0 = mBase + mW + mt * 16 + g;
        int r1 = r0 + 8;
#pragma unroll
        for (int nt = 0; nt < 4; nt++) {
            int c0 = nBase + nW + nt * 8 + 2 * tig;
            float b0 = 0.f, b1 = 0.f;
            if (bias) { b0 = bias[c0]; b1 = bias[c0 + 1]; }
            float v0 = acc[mt][nt][0] + b0, v1 = acc[mt][nt][1] + b1;
            float v2 = acc[mt][nt][2] + b0, v3 = acc[mt][nt][3] + b1;
            if (ACT == 1) { v0 = geluf(v0); v1 = geluf(v1); v2 = geluf(v2); v3 = geluf(v3); }
            if (OUTBF) {
                __nv_bfloat16* C = (__nv_bfloat16*)Cm;
                if (r0 < M) *(__nv_bfloat162*)&C[(size_t)r0 * Nn + c0] = __floats2bfloat162_rn(v0, v1);
                if (r1 < M) *(__nv_bfloat162*)&C[(size_t)r1 * Nn + c0] = __floats2bfloat162_rn(v2, v3);
            } else {
                float* C = (float*)Cm;
                if (r0 < M) *(float2*)&C[(size_t)r0 * Nn + c0] = make_float2(v0, v1);
                if (r1 < M) *(float2*)&C[(size_t)r1 * Nn + c0] = make_float2(v2, v3);
            }
        }
    }
}

// ---------------- fused edge GEMM + attention score (A-resident, head loop) ----------------
// One block per 128-edge tile. A (128 edges x K=128) loaded ONCE into smem;
// loops over 4 heads, B tile (128n x 128k) prefetched for head h+1 during
// head h's epilogue. Scores e[j,h] = sum_c lrelu(ea + xl[src]+xr[dst]) * att[c].
// Grid: EE/128 blocks.
__global__ void __launch_bounds__(256, 2)
bscore_k(const __nv_bfloat16* __restrict__ A, const __nv_bfloat16* __restrict__ Bt,
         const float* __restrict__ att) {
    extern __shared__ char smc[];
    __nv_bfloat16* As2 = (__nv_bfloat16*)smc;                    // A tile
    __nv_bfloat16* Bs2 = (__nv_bfloat16*)(smc + SC_TILE_BYTES);  // B tile (reused per head)
    float* satt = (float*)(smc + 2 * SC_TILE_BYTES);             // 512
    int* ssrc = (int*)(satt + 512);                              // 128
    int* sdst = ssrc + 128;                                      // 128
    float* sred = (float*)(sdst + 128);                          // 128

    const int tid = threadIdx.x;
    const int warpId = tid >> 5;
    const int lane = tid & 31;
    const int g = lane >> 2, tig = lane & 3;
    const int mBase = blockIdx.x * 128;   // edge tile
    const int mW = (warpId >> 2) * 64;
    const int nW = (warpId & 3) * 32;
    const int K = CC;

    if (tid < 128) {
        ssrc[tid] = g_esrc[mBase + tid];
        sdst[tid] = g_edst[mBase + tid];
        sred[tid] = 0.0f;
    }
    if (tid < 256) {
        satt[tid] = att[tid];
        satt[tid + 256] = att[tid + 256];
    }

    // load full A tile (128 rows x 128 k bf16): 2048 16B chunks
#pragma unroll
    for (int p = 0; p < 8; p++) {
        int c = tid + p * 256;
        int row = c >> 4, c16 = (c & 15) * 8;
        cpasync16(&As2[row * SC_AST + c16], &A[(size_t)(mBase + row) * K + c16]);
    }
    cp_commit();
    // load B for head 0
#pragma unroll
    for (int p = 0; p < 8; p++) {
        int c = tid + p * 256;
        int row = c >> 4, c16 = (c & 15) * 8;
        cpasync16(&Bs2[row * SC_AST + c16], &Bt[(size_t)row * K + c16]);
    }
    cp_commit();
    cp_wait0();
    __syncthreads();

    const unsigned* Asu = (const unsigned*)As2;

    for (int h = 0; h < HH; h++) {
        const unsigned* Bsu = (const unsigned*)Bs2;
        float acc[4][4][4];
#pragma unroll
        for (int mt = 0; mt < 4; mt++)
#pragma unroll
            for (int nt = 0; nt < 4; nt++)
#pragma unroll
                for (int q = 0; q < 4; q++) acc[mt][nt][q] = 0.0f;

        // K=128 -> 8 mma k-steps of 16
#pragma unroll
        for (int ks = 0; ks < 8; ks++) {
            int k8 = ks * 8;   // u32 offset
            unsigned bfr[4][2];
#pragma unroll
            for (int nt = 0; nt < 4; nt++) {
                int nc = nW + nt * 8 + g;
                bfr[nt][0] = Bsu[nc * SC_ASTU + k8 + tig];
                bfr[nt][1] = Bsu[nc * SC_ASTU + k8 + tig + 4];
            }
            unsigned afr[4][4];
#pragma unroll
            for (int mt = 0; mt < 4; mt++) {
                int m0 = mW + mt * 16 + g;
                afr[mt][0] = Asu[m0 * SC_ASTU + k8 + tig];
                afr[mt][1] = Asu[(m0 + 8) * SC_ASTU + k8 + tig];
                afr[mt][2] = Asu[m0 * SC_ASTU + k8 + tig + 4];
                afr[mt][3] = Asu[(m0 + 8) * SC_ASTU + k8 + tig + 4];
            }
#pragma unroll
            for (int mt = 0; mt < 4; mt++)
#pragma unroll
                for (int nt = 0; nt < 4; nt++)
                    mma_bf16(acc[mt][nt], afr[mt], bfr[nt]);
        }
        __syncthreads();   // all MMA reads of B done

        // prefetch next head's B (overlaps epilogue gathers)
        if (h + 1 < HH) {
#pragma unroll
            for (int p = 0; p < 8; p++) {
                int c = tid + p * 256;
                int row = c >> 4, c16 = (c & 15) * 8;
                cpasync16(&Bs2[row * SC_AST + c16],
                          &Bt[(size_t)((h + 1) * 128 + row) * K + c16]);
            }
            cp_commit();
        }

        // score epilogue for head h
        const int nBase = h * 128;
#pragma unroll
        for (int mt = 0; mt < 4; mt++) {
            int lr0 = mW + mt * 16 + g;
            int lr1 = lr0 + 8;
            int s0 = ssrc[lr0], dd0 = sdst[lr0];
            int s1 = ssrc[lr1], dd1 = sdst[lr1];
            float p0 = 0.0f, p1 = 0.0f;
#pragma unroll
            for (int nt = 0; nt < 4; nt++) {
                int cl = nW + nt * 8 + 2 * tig;
                int cg = nBase + cl;
                float at0 = satt[cg], at1 = satt[cg + 1];
                float2 xa0 = __bfloat1622float2(*(const __nv_bfloat162*)&b_xl[(size_t)s0 * HC + cg]);
                float2 xb0 = __bfloat1622float2(*(const __nv_bfloat162*)&b_xr[(size_t)dd0 * HC + cg]);
                float2 xa1 = __bfloat1622float2(*(const __nv_bfloat162*)&b_xl[(size_t)s1 * HC + cg]);
                float2 xb1 = __bfloat1622float2(*(const __nv_bfloat162*)&b_xr[(size_t)dd1 * HC + cg]);
                p0 += lreluf(acc[mt][nt][0] + xa0.x + xb0.x) * at0 +
                      lreluf(acc[mt][nt][1] + xa0.y + xb0.y) * at1;
                p1 += lreluf(acc[mt][nt][2] + xa1.x + xb1.x) * at0 +
                      lreluf(acc[mt][nt][3] + xa1.y + xb1.y) * at1;
            }
            p0 += __shfl_xor_sync(0xffffffffu, p0, 1);
            p0 += __shfl_xor_sync(0xffffffffu, p0, 2);
            p1 += __shfl_xor_sync(0xffffffffu, p1, 1);
            p1 += __shfl_xor_sync(0xffffffffu, p1, 2);
            if (tig == 0) {
                atomicAdd(&sred[lr0], p0);
                atomicAdd(&sred[lr1], p1);
            }
        }
        __syncthreads();
        if (tid < 128) {
            d_esc[(size_t)(mBase + tid) * HH + h] = sred[tid];
            sred[tid] = 0.0f;
        }
        if (h + 1 < HH) cp_wait0();
        __syncthreads();   // sred reset + next B visible
    }
}

// ---------------- per-layer kernels ----------------
// WmI[g][k] = sum_c Wm[k][c] * instr[g][c]
__global__ void k_wmI(const float* __restrict__ Wm, const float* __restrict__ instr) {
    int g = blockIdx.x, k = threadIdx.x;
    const float* wr = Wm + (size_t)k * CC;
    const float* iv = instr + (size_t)g * CC;
    float s = 0.0f;
    for (int c = 0; c < CC; c++) s += wr[c] * iv[c];
    g_WmI[g * CC + k] = s;
}

// mask + x_in (warp per node); writes bf16 x_in
__global__ void k_mask_xin(const int* __restrict__ batch) {
    int w = (blockIdx.x * blockDim.x + threadIdx.x) >> 5;
    int lane = threadIdx.x & 31;
    if (w >= NN) return;
    int g = batch[w];
    float4 hv = ((const float4*)&d_h[(size_t)w * CC])[lane];
    float4 wv = ((const float4*)&g_WmI[g * CC])[lane];
    float p = hv.x * wv.x + hv.y * wv.y + hv.z * wv.z + hv.w * wv.w;
    p = warpRedSum(p);
    float mk = 1.0f / (1.0f + expf(-p * INV_SQRT_C));
    if (lane == 0) d_mask[w] = mk;
    __nv_bfloat162* o = (__nv_bfloat162*)&b_xin[(size_t)w * CC];
    o[lane * 2] = __floats2bfloat162_rn(mk * hv.x, mk * hv.y);
    o[lane * 2 + 1] = __floats2bfloat162_rn(mk * hv.z, mk * hv.w);
}

// per-dst-node softmax: leaves UNNORMALIZED exp in d_esc, stores 1/sum to g_inv
__global__ void k_edge_softmax() {
    int w = (blockIdx.x * blockDim.x + threadIdx.x) >> 5;
    int lane = threadIdx.x & 31;
    if (w >= NN) return;
    int j0 = g_rowptr[w], j1 = g_rowptr[w + 1];
    float m0 = -1e30f, m1 = -1e30f, m2 = -1e30f, m3 = -1e30f;
    for (int j = j0 + lane; j < j1; j += 32) {
        float4 e = *(const float4*)&d_esc[(size_t)j * 4];
        m0 = fmaxf(m0, e.x); m1 = fmaxf(m1, e.y); m2 = fmaxf(m2, e.z); m3 = fmaxf(m3, e.w);
    }
    m0 = warpRedMax(m0); m1 = warpRedMax(m1); m2 = warpRedMax(m2); m3 = warpRedMax(m3);
    float s0 = 0.f, s1 = 0.f, s2 = 0.f, s3 = 0.f;
    for (int j = j0 + lane; j < j1; j += 32) {
        float4 e = *(const float4*)&d_esc[(size_t)j * 4];
        e.x = expf(e.x - m0); e.y = expf(e.y - m1);
        e.z = expf(e.z - m2); e.w = expf(e.w - m3);
        s0 += e.x; s1 += e.y; s2 += e.z; s3 += e.w;
        *(float4*)&d_esc[(size_t)j * 4] = e;
    }
    s0 = warpRedSum(s0); s1 = warpRedSum(s1); s2 = warpRedSum(s2); s3 = warpRedSum(s3);
    if (lane == 0) {
        float4 inv;
        inv.x = 1.0f / (s0 + 1e-16f);
        inv.y = 1.0f / (s1 + 1e-16f);
        inv.z = 1.0f / (s2 + 1e-16f);
        inv.w = 1.0f / (s3 + 1e-16f);
        *(float4*)&g_inv[(size_t)w * 4] = inv;
    }
}

// aggregate with deferred softmax normalization
__global__ void k_aggregate() {
    int n = blockIdx.x;
    int c = threadIdx.x;
    int j0 = g_rowptr[n], j1 = g_rowptr[n + 1];
    float a0 = 0.f, a1 = 0.f, a2 = 0.f, a3 = 0.f;
    for (int j = j0; j < j1; j++) {
        float4 wgt = *(const float4*)&d_esc[(size_t)j * 4];
        const __nv_bfloat16* xl = &b_xl[(size_t)g_esrc[j] * HC];
        a0 += wgt.x * __bfloat162float(xl[c]);
        a1 += wgt.y * __bfloat162float(xl[128 + c]);
        a2 += wgt.z * __bfloat162float(xl[256 + c]);
        a3 += wgt.w * __bfloat162float(xl[384 + c]);
    }
    float4 inv = *(const float4*)&g_inv[(size_t)n * 4];
    size_t o = (size_t)n * HC;
    b_out[o + c] = __float2bfloat16(a0 * inv.x);
    b_out[o + 128 + c] = __float2bfloat16(a1 * inv.y);
    b_out[o + 256 + c] = __float2bfloat16(a2 * inv.z);
    b_out[o + 384 + c] = __float2bfloat16(a3 * inv.w);
}

// per-layer graph-scope accumulator init
__global__ void k_init_graph() {
    int i = blockIdx.x * blockDim.x + threadIdx.x;
    if (i < GG * CC) { g_meanAcc[i] = 0.0f; g_varAcc[i] = 0.0f; }
    if (i < GG) { g_gmax[i] = -__int_as_float(0x7f800000); g_gsum[i] = 0.0f; }
}

// s[n] = dot(instr[batch[n]], cr[n]) * inv_sqrt_c ; atomicMax per graph
__global__ void k_sdpa_score(const float* __restrict__ instr, const int* __restrict__ batch) {
    int w = (blockIdx.x * blockDim.x + threadIdx.x) >> 5;
    int lane = threadIdx.x & 31;
    if (w >= NN) return;
    int g = batch[w];
    float4 iv = ((const float4*)&instr[(size_t)g * CC])[lane];
    float4 cv = ((const float4*)&g_cr[(size_t)w * CC])[lane];
    float p = iv.x * cv.x + iv.y * cv.y + iv.z * cv.z + iv.w * cv.w;
    p = warpRedSum(p) * INV_SQRT_C;
    if (lane == 0) {
        g_s[w] = p;
        atomicMaxF(&g_gmax[g], p);
    }
}
__global__ void k_sdpa_exp(const int* __restrict__ batch) {
    int n = blockIdx.x * blockDim.x + threadIdx.x;
    if (n >= NN) return;
    int g = batch[n];
    float e = expf(g_s[n] - g_gmax[g]);
    g_s[n] = e;
    atomicAdd(&g_gsum[g], e);
}

// scale cr by attention weight (normalizing inline) + accumulate per-graph mean
__global__ void k_scale_mean(const int* __restrict__ batch) {
    int c = threadIdx.x;  // 128
    int n0 = blockIdx.x * 64;
    int n1 = min(n0 + 64, NN);
    float acc = 0.0f;
    int curg = batch[n0];
    for (int n = n0; n < n1; n++) {
        int g = batch[n];
        float a = g_s[n] / (g_gsum[g] + 1e-16f);
        float v = g_cr[(size_t)n * CC + c] * a;
        g_cr[(size_t)n * CC + c] = v;
        if (g != curg) { atomicAdd(&g_meanAcc[curg * CC + c], acc); acc = 0.0f; curg = g; }
        acc += v;
    }
    atomicAdd(&g_meanAcc[curg * CC + c], acc);
}
__global__ void k_mean_div() {
    int i = blockIdx.x * blockDim.x + threadIdx.x;
    if (i < GG * CC) g_mean[i] = g_meanAcc[i] / fmaxf(g_cntf[i / CC], 1.0f);
}
__global__ void k_var_acc(const int* __restrict__ batch, const float* __restrict__ alpha) {
    int c = threadIdx.x;
    int n0 = blockIdx.x * 64;
    int n1 = min(n0 + 64, NN);
    float al = alpha[c];
    float acc = 0.0f;
    int curg = batch[n0];
    for (int n = n0; n < n1; n++) {
        int g = batch[n];
        float v = g_cr[(size_t)n * CC + c] - al * g_mean[g * CC + c];
        if (g != curg) { atomicAdd(&g_varAcc[curg * CC + c], acc); acc = 0.0f; curg = g; }
        acc += v * v;
    }
    atomicAdd(&g_varAcc[curg * CC + c], acc);
}
__global__ void k_var_div() {
    int i = blockIdx.x * blockDim.x + threadIdx.x;
    if (i < GG * CC) g_var[i] = g_varAcc[i] / fmaxf(g_cntf[i / CC], 1.0f);
}
// normalize + residual + mask gate -> dst (d_h for layers 0..2, d_out on last)
__global__ void k_norm_resid(const int* __restrict__ batch, const float* __restrict__ alpha,
                             const float* __restrict__ gamma, const float* __restrict__ beta,
                             float* __restrict__ dstp) {
    int idx = blockIdx.x * blockDim.x + threadIdx.x;
    if (idx >= NN * CC) return;
    int n = idx >> 7, c = idx & 127;
    int g = batch[n];
    float sub = g_cr[idx] - alpha[c] * g_mean[g * CC + c];
    float v = gamma[c] * sub * rsqrtf(g_var[g * CC + c] + EPSN) + beta[c];
    dstp[idx] = d_mask[n] * (v + d_h[idx]);
}

// ---------------- launch ----------------
extern "C" void kernel_launch(void* const* d_in, const int* in_sizes, int n_in,
                              void* d_out, int out_size) {
    const float* x = (const float*)d_in[0];
    const int* eidx = (const int*)d_in[1];
    const float* instr = (const float*)d_in[2];
    // d_in[3] = global_language_feats (unused by reference)
    const float* eattr = (const float*)d_in[4];
    const int* batch = (const int*)d_in[5];
    const float* Wl = (const float*)d_in[6];
    const float* Wr = (const float*)d_in[7];
    const float* We = (const float*)d_in[8];
    const float* att = (const float*)d_in[9];
    const float* Wm = (const float*)d_in[10];
    const float* p1w = (const float*)d_in[11];
    const float* p1b = (const float*)d_in[12];
    const float* p2w = (const float*)d_in[13];
    const float* p2b = (const float*)d_in[14];
    const float* gng = (const float*)d_in[15];
    const float* gnb = (const float*)d_in[16];
    const float* gna = (const float*)d_in[17];
    const int* src = eidx;
    const int* dst = eidx + EE;
    float* outp = (float*)d_out;

    cudaFuncSetAttribute(bgemm_k<0, 1>, cudaFuncAttributeMaxDynamicSharedMemorySize, BGEMM_SMEM);
    cudaFuncSetAttribute(bgemm_k<1, 1>, cudaFuncAttributeMaxDynamicSharedMemorySize, BGEMM_SMEM);
    cudaFuncSetAttribute(bgemm_k<1, 0>, cudaFuncAttributeMaxDynamicSharedMemorySize, BGEMM_SMEM);
    cudaFuncSetAttribute(bscore_k, cudaFuncAttributeMaxDynamicSharedMemorySize, SCORE_SMEM);

    int* pdeg; cudaGetSymbolAddress((void**)&pdeg, g_deg);
    int* pfill; cudaGetSymbolAddress((void**)&pfill, g_fill);
    float* pcnt; cudaGetSymbolAddress((void**)&pcnt, g_cntf);
    float* ph; cudaGetSymbolAddress((void**)&ph, d_h);

    __nv_bfloat16* pxin; cudaGetSymbolAddress((void**)&pxin, b_xin);
    __nv_bfloat16* peattr; cudaGetSymbolAddress((void**)&peattr, b_eattr);
    __nv_bfloat16* pxl; cudaGetSymbolAddress((void**)&pxl, b_xl);
    __nv_bfloat16* pxr; cudaGetSymbolAddress((void**)&pxr, b_xr);
    __nv_bfloat16* pout; cudaGetSymbolAddress((void**)&pout, b_out);
    __nv_bfloat16* pcr1; cudaGetSymbolAddress((void**)&pcr1, b_cr1);
    __nv_bfloat16* pwtl; cudaGetSymbolAddress((void**)&pwtl, b_wtl);
    __nv_bfloat16* pwtr; cudaGetSymbolAddress((void**)&pwtr, b_wtr);
    __nv_bfloat16* pwte; cudaGetSymbolAddress((void**)&pwte, b_wte);
    __nv_bfloat16* pwtp1; cudaGetSymbolAddress((void**)&pwtp1, b_wtp1);
    __nv_bfloat16* pwtp2; cudaGetSymbolAddress((void**)&pwtp2, b_wtp2);
    float* pcr; cudaGetSymbolAddress((void**)&pcr, g_cr);

    const int NB256 = (NN + 255) / 256;       // 196
    const int EB256 = (EE + 255) / 256;

    // ---- startup (runs every replay; deterministic) ----
    k_zero_int<<<NB256, 256>>>(pdeg, NN);
    k_zero_int<<<NB256, 256>>>(pfill, NN);
    k_zero_float<<<1, 64>>>(pcnt, GG);
    k_deg<<<EB256, 256>>>(dst);
    k_scanA<<<NB256, 256>>>();
    k_scanB<<<1, 32>>>(NB256);
    k_scanC<<<(NN + 255) / 256, 256>>>();
    k_scatter<<<EB256, 256>>>(src, dst);
    k_permute_eattr<<<(EE * 32 + 255) / 256, 256>>>(eattr);
    k_cnt<<<NB256, 256>>>(batch);
    k_copy4<<<((NN * CC / 4) + 255) / 256, 256>>>(ph, x, NN * CC / 4);
    // weight transpose+convert (all layers)
    k_wt<<<dim3((CC * HC + 255) / 256, LL), 256>>>(Wl, pwtl, CC, HC);
    k_wt<<<dim3((CC * HC + 255) / 256, LL), 256>>>(Wr, pwtr, CC, HC);
    k_wt<<<dim3((CC * HC + 255) / 256, LL), 256>>>(We, pwte, CC, HC);
    k_wt<<<dim3((HC * MIDD + 255) / 256, LL), 256>>>(p1w, pwtp1, HC, MIDD);
    k_wt<<<dim3((MIDD * CC + 255) / 256, LL), 256>>>(p2w, pwtp2, MIDD, CC);

    for (int i = 0; i < LL; i++) {
        const float* Wm_i = Wm + (size_t)i * CC * CC;
        const float* instr_i = instr + (size_t)i * GG * CC;
        const float* att_i = att + (size_t)i * HH * CC;
        const float* p1b_i = p1b + (size_t)i * MIDD;
        const float* p2b_i = p2b + (size_t)i * CC;
        const float* gng_i = gng + (size_t)i * CC;
        const float* gnb_i = gnb + (size_t)i * CC;
        const float* gna_i = gna + (size_t)i * CC;
        __nv_bfloat16* wtl_i = pwtl + (size_t)i * HC * CC;
        __nv_bfloat16* wtr_i = pwtr + (size_t)i * HC * CC;
        __nv_bfloat16* wte_i = pwte + (size_t)i * HC * CC;
        __nv_bfloat16* wtp1_i = pwtp1 + (size_t)i * MIDD * HC;
        __nv_bfloat16* wtp2_i = pwtp2 + (size_t)i * CC * MIDD;

        // mask + x_in (bf16)
        k_wmI<<<GG, CC>>>(Wm_i, instr_i);
        k_mask_xin<<<(NN * 32 + 255) / 256, 256>>>(batch);

        // node projections (bf16 tensor cores) -> bf16 xl/xr
        dim3 gxl(HC / 128, (NN + 127) / 128);
        bgemm_k<0, 1><<<gxl, 256, BGEMM_SMEM>>>(pxin, wtl_i, nullptr, pxl, NN, HC, CC);
        bgemm_k<0, 1><<<gxl, 256, BGEMM_SMEM>>>(pxin, wtr_i, nullptr, pxr, NN, HC, CC);

        // fused edge GEMM + attention score (A-resident, 4-head loop)
        bscore_k<<<EE / 128, 256, SCORE_SMEM>>>(peattr, wte_i, att_i);

        // attention softmax + aggregation (deferred normalization)
        k_edge_softmax<<<(NN * 32 + 255) / 256, 256>>>();
        k_aggregate<<<NN, 128>>>();

        // MLP (bf16 tensor cores); MLP2 outputs fp32 g_cr
        dim3 gp1(MIDD / 128, (NN + 127) / 128);
        bgemm_k<1, 1><<<gp1, 256, BGEMM_SMEM>>>(pout, wtp1_i, p1b_i, pcr1, NN, MIDD, HC);
        dim3 gp2(CC / 128, (NN + 127) / 128);
        bgemm_k<1, 0><<<gp2, 256, BGEMM_SMEM>>>(pcr1, wtp2_i, p2b_i, pcr, NN, CC, MIDD);

        // scatter attention + GraphNorm
        k_init_graph<<<(GG * CC + 255) / 256, 256>>>();
        k_sdpa_score<<<(NN * 32 + 255) / 256, 256>>>(instr_i, batch);
        k_sdpa_exp<<<NB256, 256>>>(batch);
        k_scale_mean<<<(NN + 63) / 64, 128>>>(batch);
        k_mean_div<<<(GG * CC + 255) / 256, 256>>>();
        k_var_acc<<<(NN + 63) / 64, 128>>>(batch, gna_i);
        k_var_div<<<(GG * CC + 255) / 256, 256>>>();
        float* dstp = (i == LL - 1) ? outp : ph;
        k_norm_resid<<<(NN * CC + 255) / 256, 256>>>(batch, gna_i, gng_i, gnb_i, dstp);
    }
    (void)in_sizes; (void)n_in; (void)out_size;
}

// round 12
// speedup vs baseline: 4.1053x; 1.0402x over previous
#include <cuda_runtime.h>
#include <cuda_bf16.h>
#include <math.h>

// Problem constants (fixed by setup_inputs)
#define NN 50000
#define EE 400000
#define CC 128
#define HH 4
#define GG 64
#define LL 4
#define HC 512   // H*C
#define MIDD 256 // C*(H/2)

#define NEG_SLOPE 0.2f
#define EPSN 1e-5f
#define INV_SQRT_C 0.08838834764831845f

// ---------------- scratch (static device globals; no allocation) ----------------
__device__ float d_h[(size_t)NN * CC];
__device__ float d_mask[NN];
__device__ float d_esc[(size_t)EE * HH];     // scores -> unnormalized exp alphas
__device__ float g_inv[(size_t)NN * HH];     // per-node 1/softmax-sum per head
__device__ float g_cr[(size_t)NN * CC];
__device__ float g_s[NN];
__device__ float g_WmI[LL * GG * CC];        // all layers, precomputed at startup
__device__ float g_gmax[GG];
__device__ float g_gsum[GG];
__device__ float g_meanAcc[GG * CC];
__device__ float g_mean[GG * CC];
__device__ float g_varAcc[GG * CC];
__device__ float g_var[GG * CC];
__device__ float g_cntf[GG];
__device__ int g_deg[NN];
__device__ int g_fill[NN];
__device__ int g_rowptr[NN + 1];
__device__ int g_esrc[EE];
__device__ int g_edst[EE];
__device__ int g_eid[EE];
__device__ int g_blocksums[256];

// bf16 activation / weight buffers
__device__ __nv_bfloat16 b_xin[(size_t)NN * CC];
__device__ __nv_bfloat16 b_eattr[(size_t)EE * CC];
__device__ __nv_bfloat16 b_xlr[(size_t)NN * 1024];   // cols 0..511 = xl, 512..1023 = xr
__device__ __nv_bfloat16 b_out[(size_t)NN * HC];
__device__ __nv_bfloat16 b_cr1[(size_t)NN * MIDD];
__device__ __nv_bfloat16 b_wtlr[(size_t)LL * 1024 * CC];  // [xl rows | xr rows] x K
__device__ __nv_bfloat16 b_wte[(size_t)LL * HC * CC];
__device__ __nv_bfloat16 b_wtp1[(size_t)LL * MIDD * HC];
__device__ __nv_bfloat16 b_wtp2[(size_t)LL * CC * MIDD];

// ---------------- helpers ----------------
__device__ __forceinline__ float warpRedSum(float v) {
#pragma unroll
    for (int o = 16; o; o >>= 1) v += __shfl_xor_sync(0xffffffffu, v, o);
    return v;
}
__device__ __forceinline__ float warpRedMax(float v) {
#pragma unroll
    for (int o = 16; o; o >>= 1) v = fmaxf(v, __shfl_xor_sync(0xffffffffu, v, o));
    return v;
}
__device__ __forceinline__ float geluf(float x) {
    float x3 = x * x * x;
    return 0.5f * x * (1.0f + tanhf(0.7978845608028654f * (x + 0.044715f * x3)));
}
__device__ __forceinline__ float lreluf(float x) {
    return x > 0.0f ? x : NEG_SLOPE * x;
}
__device__ __forceinline__ void atomicMaxF(float* a, float v) {
    if (v >= 0.0f) atomicMax((int*)a, __float_as_int(v));
    else atomicMin((unsigned int*)a, __float_as_uint(v));
}
__device__ __forceinline__ void mma_bf16(float* d, const unsigned* a, const unsigned* b) {
    asm volatile(
        "mma.sync.aligned.m16n8k16.row.col.f32.bf16.bf16.f32 "
        "{%0,%1,%2,%3}, {%4,%5,%6,%7}, {%8,%9}, {%0,%1,%2,%3};\n"
        : "+f"(d[0]), "+f"(d[1]), "+f"(d[2]), "+f"(d[3])
        : "r"(a[0]), "r"(a[1]), "r"(a[2]), "r"(a[3]), "r"(b[0]), "r"(b[1]));
}
__device__ __forceinline__ void cpasync16(void* s, const void* g) {
    unsigned saddr = (unsigned)__cvta_generic_to_shared(s);
    asm volatile("cp.async.cg.shared.global [%0], [%1], 16;\n" :: "r"(saddr), "l"(g));
}
__device__ __forceinline__ void cp_commit() {
    asm volatile("cp.async.commit_group;\n");
}
__device__ __forceinline__ void cp_wait1() {
    asm volatile("cp.async.wait_group 1;\n");
}
__device__ __forceinline__ void cp_wait0() {
    asm volatile("cp.async.wait_group 0;\n");
}

// smem tile geometry for bgemm (bf16 units)
#define BST 40                  // bf16 per row (32 k + pad 8)
#define BSTU 20                 // u32 stride
#define TILEBF (128 * BST)      // 5120 bf16 = 10240 B per tile
#define BGEMM_SMEM (4 * TILEBF * 2)           // 2 stages x (A+B) = 40960 B
#define BGEMM_SMEM_SDPA (BGEMM_SMEM + 512)    // + sred[128]

// smem geometry for bscore (full-K tiles)
#define SC_AST 136              // bf16 per row (128 k + pad 8)
#define SC_ASTU 68              // u32 stride
#define SC_TILE_BYTES (128 * SC_AST * 2)      // 34816 B
#define SCORE_SMEM (2 * SC_TILE_BYTES + 3584) // A + B + satt/ssrc/sdst/sred

// ---------------- init / utility kernels ----------------
__global__ void k_zero_int(int* p, int n) {
    int i = blockIdx.x * blockDim.x + threadIdx.x;
    if (i < n) p[i] = 0;
}
__global__ void k_zero_float(float* p, int n) {
    int i = blockIdx.x * blockDim.x + threadIdx.x;
    if (i < n) p[i] = 0.0f;
}
__global__ void k_copy4(float* __restrict__ dst, const float* __restrict__ src, int n4) {
    int i = blockIdx.x * blockDim.x + threadIdx.x;
    if (i < n4) ((float4*)dst)[i] = ((const float4*)src)[i];
}
// weight transpose+convert: B[K][N] fp32 (layer blockIdx.y) -> Bt rows [rowOff..rowOff+N) x K bf16
__global__ void k_wt2(const float* __restrict__ B, __nv_bfloat16* __restrict__ Bt,
                      int K, int N, int outLayerStride, int rowOff) {
    int i = blockIdx.x * blockDim.x + threadIdx.x;
    if (i >= K * N) return;
    const float* Bl = B + (size_t)blockIdx.y * K * N;
    __nv_bfloat16* Btl = Bt + (size_t)blockIdx.y * outLayerStride;
    int k = i / N, n = i % N;
    Btl[(size_t)(rowOff + n) * K + k] = __float2bfloat16(Bl[i]);
}

// ---------------- CSR build ----------------
__global__ void k_deg(const int* __restrict__ dst) {
    int e = blockIdx.x * blockDim.x + threadIdx.x;
    if (e < EE) atomicAdd(&g_deg[dst[e]], 1);
}
__global__ void k_scanA() {
    __shared__ float s[256];
    int tid = threadIdx.x;
    int n = blockIdx.x * 256 + tid;
    float v = (n < NN) ? (float)g_deg[n] : 0.0f;
    s[tid] = v;
    __syncthreads();
#pragma unroll
    for (int off = 1; off < 256; off <<= 1) {
        float t = (tid >= off) ? s[tid - off] : 0.0f;
        __syncthreads();
        s[tid] += t;
        __syncthreads();
    }
    if (n < NN) g_rowptr[n + 1] = (int)s[tid];
    if (tid == 255) g_blocksums[blockIdx.x] = (int)s[255];
}
__global__ void k_scanB(int nb) {
    if (threadIdx.x == 0) {
        int run = 0;
        for (int b = 0; b < nb; b++) { int t = g_blocksums[b]; g_blocksums[b] = run; run += t; }
    }
}
__global__ void k_scanC() {
    int n = blockIdx.x * blockDim.x + threadIdx.x;
    if (n < NN) g_rowptr[n + 1] += g_blocksums[n / 256];
    if (n == 0) g_rowptr[0] = 0;
}
__global__ void k_scatter(const int* __restrict__ src, const int* __restrict__ dst) {
    int e = blockIdx.x * blockDim.x + threadIdx.x;
    if (e >= EE) return;
    int d = dst[e];
    int p = g_rowptr[d] + atomicAdd(&g_fill[d], 1);
    g_esrc[p] = src[e];
    g_edst[p] = d;
    g_eid[p] = e;
}
// permute edge_attr into dst-sorted order, convert to bf16
__global__ void k_permute_eattr(const float* __restrict__ eattr) {
    int idx = blockIdx.x * blockDim.x + threadIdx.x;  // over EE*32 float4s
    if (idx >= EE * 32) return;
    int j = idx >> 5, q = idx & 31;
    float4 v = ((const float4*)eattr)[(size_t)g_eid[j] * 32 + q];
    __nv_bfloat16* o = &b_eattr[(size_t)j * CC + q * 4];
    *(__nv_bfloat162*)&o[0] = __floats2bfloat162_rn(v.x, v.y);
    *(__nv_bfloat162*)&o[2] = __floats2bfloat162_rn(v.z, v.w);
}
__global__ void k_cnt(const int* __restrict__ batch) {
    int n = blockIdx.x * blockDim.x + threadIdx.x;
    if (n < NN) atomicAdd(&g_cntf[batch[n]], 1.0f);
}
// WmI[l][g][k] = sum_c Wm[l][k][c] * instr[l][g][c]  (all layers at startup)
__global__ void k_wmI_all(const float* __restrict__ Wm, const float* __restrict__ instr) {
    int g = blockIdx.x, l = blockIdx.y, k = threadIdx.x;
    const float* wr = Wm + (size_t)l * CC * CC + (size_t)k * CC;
    const float* iv = instr + (size_t)l * GG * CC + (size_t)g * CC;
    float s = 0.0f;
    for (int c = 0; c < CC; c++) s += wr[c] * iv[c];
    g_WmI[(size_t)l * GG * CC + g * CC + k] = s;
}

// ---------------- BF16 tensor-core GEMM (cp.async double-buffered) ----------------
// SDPA=1 (requires gridDim.x==1, Nn==CC): additionally computes
// s[n] = dot(instr[batch[n]], C_row[n]) * inv_sqrt_c -> g_s, atomicMax g_gmax.
template <int ACT, int OUTBF, int SDPA>
__global__ void __launch_bounds__(256, 2)
bgemm_k(const __nv_bfloat16* __restrict__ A, const __nv_bfloat16* __restrict__ Bt,
        const float* __restrict__ bias, void* __restrict__ Cm,
        int M, int Nn, int K,
        const int* __restrict__ batch, const float* __restrict__ instr) {
    extern __shared__ char smc[];
    __nv_bfloat16* sbase = (__nv_bfloat16*)smc;
    float* sred = (float*)(smc + BGEMM_SMEM);

    const int tid = threadIdx.x;
    const int warpId = tid >> 5;
    const int lane = tid & 31;
    const int g = lane >> 2, tig = lane & 3;
    const int mBase = blockIdx.y * 128;
    const int nBase = blockIdx.x * 128;
    const int mW = (warpId >> 2) * 64;
    const int nW = (warpId & 3) * 32;

    if (SDPA && tid < 128) sred[tid] = 0.0f;

    float acc[4][4][4];
#pragma unroll
    for (int mt = 0; mt < 4; mt++)
#pragma unroll
        for (int nt = 0; nt < 4; nt++)
#pragma unroll
            for (int q = 0; q < 4; q++) acc[mt][nt][q] = 0.0f;

    const int nIter = K >> 5;

    auto prefetch = [&](int kt, int s) {
        int k0 = kt << 5;
        __nv_bfloat16* As = sbase + s * 2 * TILEBF;
        __nv_bfloat16* Bs = As + TILEBF;
#pragma unroll
        for (int p = 0; p < 2; p++) {
            int c = tid + p * 256;              // 512 16B-chunks
            int row = c >> 2, c16 = (c & 3) * 8;
            int gr = mBase + row;
            if (gr >= M) gr = M - 1;            // clamp: rows discarded in epilogue
            cpasync16(&As[row * BST + c16], &A[(size_t)gr * K + k0 + c16]);
        }
#pragma unroll
        for (int p = 0; p < 2; p++) {
            int c = tid + p * 256;
            int row = c >> 2, c16 = (c & 3) * 8;
            cpasync16(&Bs[row * BST + c16], &Bt[(size_t)(nBase + row) * K + k0 + c16]);
        }
        cp_commit();
    };

    prefetch(0, 0);
    for (int kt = 0; kt < nIter; kt++) {
        int s = kt & 1;
        if (kt + 1 < nIter) prefetch(kt + 1, (kt + 1) & 1);
        else cp_commit();
        cp_wait1();
        __syncthreads();
        const unsigned* Asu = (const unsigned*)(sbase + s * 2 * TILEBF);
        const unsigned* Bsu = (const unsigned*)(sbase + s * 2 * TILEBF + TILEBF);
#pragma unroll
        for (int ks = 0; ks < 2; ks++) {
            int k8 = ks * 8;
            unsigned bfr[4][2];
#pragma unroll
            for (int nt = 0; nt < 4; nt++) {
                int nc = nW + nt * 8 + g;
                bfr[nt][0] = Bsu[nc * BSTU + k8 + tig];
                bfr[nt][1] = Bsu[nc * BSTU + k8 + tig + 4];
            }
            unsigned afr[4][4];
#pragma unroll
            for (int mt = 0; mt < 4; mt++) {
                int m0 = mW + mt * 16 + g;
                afr[mt][0] = Asu[m0 * BSTU + k8 + tig];
                afr[mt][1] = Asu[(m0 + 8) * BSTU + k8 + tig];
                afr[mt][2] = Asu[m0 * BSTU + k8 + tig + 4];
                afr[mt][3] = Asu[(m0 + 8) * BSTU + k8 + tig + 4];
            }
#pragma unroll
            for (int mt = 0; mt < 4; mt++)
#pragma unroll
                for (int nt = 0; nt < 4; nt++)
                    mma_bf16(acc[mt][nt], afr[mt], bfr[nt]);
        }
        __syncthreads();
    }

    // epilogue
#pragma unroll
    for (int mt = 0; mt < 4; mt++) {
        int r0 = mBase + mW + mt * 16 + g;
        int r1 = r0 + 8;
        int bg0 = 0, bg1 = 0;
        if (SDPA) {
            bg0 = (r0 < M) ? batch[r0] : 0;
            bg1 = (r1 < M) ? batch[r1] : 0;
        }
        float pd0 = 0.0f, pd1 = 0.0f;
#pragma unroll
        for (int nt = 0; nt < 4; nt++) {
            int c0 = nBase + nW + nt * 8 + 2 * tig;
            float b0 = 0.f, b1 = 0.f;
            if (bias) { b0 = bias[c0]; b1 = bias[c0 + 1]; }
            float v0 = acc[mt][nt][0] + b0, v1 = acc[mt][nt][1] + b1;
            float v2 = acc[mt][nt][2] + b0, v3 = acc[mt][nt][3] + b1;
            if (ACT == 1) { v0 = geluf(v0); v1 = geluf(v1); v2 = geluf(v2); v3 = geluf(v3); }
            if (OUTBF) {
                __nv_bfloat16* C = (__nv_bfloat16*)Cm;
                if (r0 < M) *(__nv_bfloat162*)&C[(size_t)r0 * Nn + c0] = __floats2bfloat162_rn(v0, v1);
                if (r1 < M) *(__nv_bfloat162*)&C[(size_t)r1 * Nn + c0] = __floats2bfloat162_rn(v2, v3);
            } else {
                float* C = (float*)Cm;
                if (r0 < M) *(float2*)&C[(size_t)r0 * Nn + c0] = make_float2(v0, v1);
                if (r1 < M) *(float2*)&C[(size_t)r1 * Nn + c0] = make_float2(v2, v3);
            }
            if (SDPA) {
                pd0 += v0 * instr[bg0 * CC + c0] + v1 * instr[bg0 * CC + c0 + 1];
                pd1 += v2 * instr[bg1 * CC + c0] + v3 * instr[bg1 * CC + c0 + 1];
            }
        }
        if (SDPA) {
            pd0 += __shfl_xor_sync(0xffffffffu, pd0, 1);
            pd0 += __shfl_xor_sync(0xffffffffu, pd0, 2);
            pd1 += __shfl_xor_sync(0xffffffffu, pd1, 1);
            pd1 += __shfl_xor_sync(0xffffffffu, pd1, 2);
            if (tig == 0) {
                atomicAdd(&sred[mW + mt * 16 + g], pd0);
                atomicAdd(&sred[mW + mt * 16 + g + 8], pd1);
            }
        }
    }
    if (SDPA) {
        __syncthreads();
        if (tid < 128) {
            int r = mBase + tid;
            if (r < M) {
                float s = sred[tid] * INV_SQRT_C;
                g_s[r] = s;
                atomicMaxF(&g_gmax[batch[r]], s);
            }
        }
    }
}

// ---------------- fused edge GEMM + attention score (A-resident, head loop) ----------------
__global__ void __launch_bounds__(256, 2)
bscore_k(const __nv_bfloat16* __restrict__ A, const __nv_bfloat16* __restrict__ Bt,
         const float* __restrict__ att) {
    extern __shared__ char smc[];
    __nv_bfloat16* As2 = (__nv_bfloat16*)smc;                    // A tile
    __nv_bfloat16* Bs2 = (__nv_bfloat16*)(smc + SC_TILE_BYTES);  // B tile (reused per head)
    float* satt = (float*)(smc + 2 * SC_TILE_BYTES);             // 512
    int* ssrc = (int*)(satt + 512);                              // 128
    int* sdst = ssrc + 128;                                      // 128
    float* sred = (float*)(sdst + 128);                          // 128

    const int tid = threadIdx.x;
    const int warpId = tid >> 5;
    const int lane = tid & 31;
    const int g = lane >> 2, tig = lane & 3;
    const int mBase = blockIdx.x * 128;   // edge tile
    const int mW = (warpId >> 2) * 64;
    const int nW = (warpId & 3) * 32;
    const int K = CC;

    if (tid < 128) {
        ssrc[tid] = g_esrc[mBase + tid];
        sdst[tid] = g_edst[mBase + tid];
        sred[tid] = 0.0f;
    }
    if (tid < 256) {
        satt[tid] = att[tid];
        satt[tid + 256] = att[tid + 256];
    }

    // load full A tile (128 rows x 128 k bf16): 2048 16B chunks
#pragma unroll
    for (int p = 0; p < 8; p++) {
        int c = tid + p * 256;
        int row = c >> 4, c16 = (c & 15) * 8;
        cpasync16(&As2[row * SC_AST + c16], &A[(size_t)(mBase + row) * K + c16]);
    }
    cp_commit();
    // load B for head 0
#pragma unroll
    for (int p = 0; p < 8; p++) {
        int c = tid + p * 256;
        int row = c >> 4, c16 = (c & 15) * 8;
        cpasync16(&Bs2[row * SC_AST + c16], &Bt[(size_t)row * K + c16]);
    }
    cp_commit();
    cp_wait0();
    __syncthreads();

    const unsigned* Asu = (const unsigned*)As2;

    for (int h = 0; h < HH; h++) {
        const unsigned* Bsu = (const unsigned*)Bs2;
        float acc[4][4][4];
#pragma unroll
        for (int mt = 0; mt < 4; mt++)
#pragma unroll
            for (int nt = 0; nt < 4; nt++)
#pragma unroll
                for (int q = 0; q < 4; q++) acc[mt][nt][q] = 0.0f;

        // K=128 -> 8 mma k-steps of 16
#pragma unroll
        for (int ks = 0; ks < 8; ks++) {
            int k8 = ks * 8;   // u32 offset
            unsigned bfr[4][2];
#pragma unroll
            for (int nt = 0; nt < 4; nt++) {
                int nc = nW + nt * 8 + g;
                bfr[nt][0] = Bsu[nc * SC_ASTU + k8 + tig];
                bfr[nt][1] = Bsu[nc * SC_ASTU + k8 + tig + 4];
            }
            unsigned afr[4][4];
#pragma unroll
            for (int mt = 0; mt < 4; mt++) {
                int m0 = mW + mt * 16 + g;
                afr[mt][0] = Asu[m0 * SC_ASTU + k8 + tig];
                afr[mt][1] = Asu[(m0 + 8) * SC_ASTU + k8 + tig];
                afr[mt][2] = Asu[m0 * SC_ASTU + k8 + tig + 4];
                afr[mt][3] = Asu[(m0 + 8) * SC_ASTU + k8 + tig + 4];
            }
#pragma unroll
            for (int mt = 0; mt < 4; mt++)
#pragma unroll
                for (int nt = 0; nt < 4; nt++)
                    mma_bf16(acc[mt][nt], afr[mt], bfr[nt]);
        }
        __syncthreads();   // all MMA reads of B done

        // prefetch next head's B (overlaps epilogue gathers)
        if (h + 1 < HH) {
#pragma unroll
            for (int p = 0; p < 8; p++) {
                int c = tid + p * 256;
                int row = c >> 4, c16 = (c & 15) * 8;
                cpasync16(&Bs2[row * SC_AST + c16],
                          &Bt[(size_t)((h + 1) * 128 + row) * K + c16]);
            }
            cp_commit();
        }

        // score epilogue for head h (xl = b_xlr col h*128+c, xr = col 512+h*128+c)
        const int nBase = h * 128;
#pragma unroll
        for (int mt = 0; mt < 4; mt++) {
            int lr0 = mW + mt * 16 + g;
            int lr1 = lr0 + 8;
            int s0 = ssrc[lr0], dd0 = sdst[lr0];
            int s1 = ssrc[lr1], dd1 = sdst[lr1];
            float p0 = 0.0f, p1 = 0.0f;
#pragma unroll
            for (int nt = 0; nt < 4; nt++) {
                int cl = nW + nt * 8 + 2 * tig;
                int cg = nBase + cl;
                float at0 = satt[cg], at1 = satt[cg + 1];
                float2 xa0 = __bfloat1622float2(*(const __nv_bfloat162*)&b_xlr[(size_t)s0 * 1024 + cg]);
                float2 xb0 = __bfloat1622float2(*(const __nv_bfloat162*)&b_xlr[(size_t)dd0 * 1024 + 512 + cg]);
                float2 xa1 = __bfloat1622float2(*(const __nv_bfloat162*)&b_xlr[(size_t)s1 * 1024 + cg]);
                float2 xb1 = __bfloat1622float2(*(const __nv_bfloat162*)&b_xlr[(size_t)dd1 * 1024 + 512 + cg]);
                p0 += lreluf(acc[mt][nt][0] + xa0.x + xb0.x) * at0 +
                      lreluf(acc[mt][nt][1] + xa0.y + xb0.y) * at1;
                p1 += lreluf(acc[mt][nt][2] + xa1.x + xb1.x) * at0 +
                      lreluf(acc[mt][nt][3] + xa1.y + xb1.y) * at1;
            }
            p0 += __shfl_xor_sync(0xffffffffu, p0, 1);
            p0 += __shfl_xor_sync(0xffffffffu, p0, 2);
            p1 += __shfl_xor_sync(0xffffffffu, p1, 1);
            p1 += __shfl_xor_sync(0xffffffffu, p1, 2);
            if (tig == 0) {
                atomicAdd(&sred[lr0], p0);
                atomicAdd(&sred[lr1], p1);
            }
        }
        __syncthreads();
        if (tid < 128) {
            d_esc[(size_t)(mBase + tid) * HH + h] = sred[tid];
            sred[tid] = 0.0f;
        }
        if (h + 1 < HH) cp_wait0();
        __syncthreads();   // sred reset + next B visible
    }
}

// ---------------- per-layer kernels ----------------
// mask + x_in (warp per node, layer 0 only); writes bf16 x_in
__global__ void k_mask_xin(const int* __restrict__ batch, const float* __restrict__ WmI) {
    int w = (blockIdx.x * blockDim.x + threadIdx.x) >> 5;
    int lane = threadIdx.x & 31;
    if (w >= NN) return;
    int g = batch[w];
    float4 hv = ((const float4*)&d_h[(size_t)w * CC])[lane];
    float4 wv = ((const float4*)&WmI[g * CC])[lane];
    float p = hv.x * wv.x + hv.y * wv.y + hv.z * wv.z + hv.w * wv.w;
    p = warpRedSum(p);
    float mk = 1.0f / (1.0f + expf(-p * INV_SQRT_C));
    if (lane == 0) d_mask[w] = mk;
    __nv_bfloat162* o = (__nv_bfloat162*)&b_xin[(size_t)w * CC];
    o[lane * 2] = __floats2bfloat162_rn(mk * hv.x, mk * hv.y);
    o[lane * 2 + 1] = __floats2bfloat162_rn(mk * hv.z, mk * hv.w);
}

// per-dst-node softmax: leaves UNNORMALIZED exp in d_esc, stores 1/sum to g_inv
__global__ void k_edge_softmax() {
    int w = (blockIdx.x * blockDim.x + threadIdx.x) >> 5;
    int lane = threadIdx.x & 31;
    if (w >= NN) return;
    int j0 = g_rowptr[w], j1 = g_rowptr[w + 1];
    float m0 = -1e30f, m1 = -1e30f, m2 = -1e30f, m3 = -1e30f;
    for (int j = j0 + lane; j < j1; j += 32) {
        float4 e = *(const float4*)&d_esc[(size_t)j * 4];
        m0 = fmaxf(m0, e.x); m1 = fmaxf(m1, e.y); m2 = fmaxf(m2, e.z); m3 = fmaxf(m3, e.w);
    }
    m0 = warpRedMax(m0); m1 = warpRedMax(m1); m2 = warpRedMax(m2); m3 = warpRedMax(m3);
    float s0 = 0.f, s1 = 0.f, s2 = 0.f, s3 = 0.f;
    for (int j = j0 + lane; j < j1; j += 32) {
        float4 e = *(const float4*)&d_esc[(size_t)j * 4];
        e.x = expf(e.x - m0); e.y = expf(e.y - m1);
        e.z = expf(e.z - m2); e.w = expf(e.w - m3);
        s0 += e.x; s1 += e.y; s2 += e.z; s3 += e.w;
        *(float4*)&d_esc[(size_t)j * 4] = e;
    }
    s0 = warpRedSum(s0); s1 = warpRedSum(s1); s2 = warpRedSum(s2); s3 = warpRedSum(s3);
    if (lane == 0) {
        float4 inv;
        inv.x = 1.0f / (s0 + 1e-16f);
        inv.y = 1.0f / (s1 + 1e-16f);
        inv.z = 1.0f / (s2 + 1e-16f);
        inv.w = 1.0f / (s3 + 1e-16f);
        *(float4*)&g_inv[(size_t)w * 4] = inv;
    }
}

// aggregate with deferred softmax normalization (xl from b_xlr cols 0..511)
__global__ void k_aggregate() {
    int n = blockIdx.x;
    int c = threadIdx.x;
    int j0 = g_rowptr[n], j1 = g_rowptr[n + 1];
    float a0 = 0.f, a1 = 0.f, a2 = 0.f, a3 = 0.f;
    for (int j = j0; j < j1; j++) {
        float4 wgt = *(const float4*)&d_esc[(size_t)j * 4];
        const __nv_bfloat16* xl = &b_xlr[(size_t)g_esrc[j] * 1024];
        a0 += wgt.x * __bfloat162float(xl[c]);
        a1 += wgt.y * __bfloat162float(xl[128 + c]);
        a2 += wgt.z * __bfloat162float(xl[256 + c]);
        a3 += wgt.w * __bfloat162float(xl[384 + c]);
    }
    float4 inv = *(const float4*)&g_inv[(size_t)n * 4];
    size_t o = (size_t)n * HC;
    b_out[o + c] = __float2bfloat16(a0 * inv.x);
    b_out[o + 128 + c] = __float2bfloat16(a1 * inv.y);
    b_out[o + 256 + c] = __float2bfloat16(a2 * inv.z);
    b_out[o + 384 + c] = __float2bfloat16(a3 * inv.w);
}

// per-layer graph-scope accumulator init
__global__ void k_init_graph() {
    int i = blockIdx.x * blockDim.x + threadIdx.x;
    if (i < GG * CC) { g_meanAcc[i] = 0.0f; g_varAcc[i] = 0.0f; }
    if (i < GG) { g_gmax[i] = -__int_as_float(0x7f800000); g_gsum[i] = 0.0f; }
}

__global__ void k_sdpa_exp(const int* __restrict__ batch) {
    int n = blockIdx.x * blockDim.x + threadIdx.x;
    if (n >= NN) return;
    int g = batch[n];
    float e = expf(g_s[n] - g_gmax[g]);
    g_s[n] = e;
    atomicAdd(&g_gsum[g], e);
}

// scale cr by attention weight (normalizing inline) + accumulate per-graph mean
__global__ void k_scale_mean(const int* __restrict__ batch) {
    int c = threadIdx.x;  // 128
    int n0 = blockIdx.x * 64;
    int n1 = min(n0 + 64, NN);
    float acc = 0.0f;
    int curg = batch[n0];
    for (int n = n0; n < n1; n++) {
        int g = batch[n];
        float a = g_s[n] / (g_gsum[g] + 1e-16f);
        float v = g_cr[(size_t)n * CC + c] * a;
        g_cr[(size_t)n * CC + c] = v;
        if (g != curg) { atomicAdd(&g_meanAcc[curg * CC + c], acc); acc = 0.0f; curg = g; }
        acc += v;
    }
    atomicAdd(&g_meanAcc[curg * CC + c], acc);
}
__global__ void k_mean_div() {
    int i = blockIdx.x * blockDim.x + threadIdx.x;
    if (i < GG * CC) g_mean[i] = g_meanAcc[i] / fmaxf(g_cntf[i / CC], 1.0f);
}
__global__ void k_var_acc(const int* __restrict__ batch, const float* __restrict__ alpha) {
    int c = threadIdx.x;
    int n0 = blockIdx.x * 64;
    int n1 = min(n0 + 64, NN);
    float al = alpha[c];
    float acc = 0.0f;
    int curg = batch[n0];
    for (int n = n0; n < n1; n++) {
        int g = batch[n];
        float v = g_cr[(size_t)n * CC + c] - al * g_mean[g * CC + c];
        if (g != curg) { atomicAdd(&g_varAcc[curg * CC + c], acc); acc = 0.0f; curg = g; }
        acc += v * v;
    }
    atomicAdd(&g_varAcc[curg * CC + c], acc);
}
__global__ void k_var_div() {
    int i = blockIdx.x * blockDim.x + threadIdx.x;
    if (i < GG * CC) g_var[i] = g_varAcc[i] / fmaxf(g_cntf[i / CC], 1.0f);
}

// last layer: normalize + residual + mask gate -> d_out (fp32)
__global__ void k_norm_resid(const int* __restrict__ batch, const float* __restrict__ alpha,
                             const float* __restrict__ gamma, const float* __restrict__ beta,
                             float* __restrict__ dstp) {
    int idx = blockIdx.x * blockDim.x + threadIdx.x;
    if (idx >= NN * CC) return;
    int n = idx >> 7, c = idx & 127;
    int g = batch[n];
    float sub = g_cr[idx] - alpha[c] * g_mean[g * CC + c];
    float v = gamma[c] * sub * rsqrtf(g_var[g * CC + c] + EPSN) + beta[c];
    dstp[idx] = d_mask[n] * (v + d_h[idx]);
}

// layers 0..2: norm+resid fused with NEXT layer's mask + x_in (warp per node)
__global__ void k_norm_mask(const int* __restrict__ batch, const float* __restrict__ alpha,
                            const float* __restrict__ gamma, const float* __restrict__ beta,
                            const float* __restrict__ WmI_next) {
    int w = (blockIdx.x * blockDim.x + threadIdx.x) >> 5;
    int lane = threadIdx.x & 31;
    if (w >= NN) return;
    int g = batch[w];
    int c4 = lane * 4;
    float4 cv = ((const float4*)&g_cr[(size_t)w * CC])[lane];
    float4 mv = ((const float4*)&g_mean[g * CC])[lane];
    float4 vv = ((const float4*)&g_var[g * CC])[lane];
    float4 av = *(const float4*)&alpha[c4];
    float4 gv = *(const float4*)&gamma[c4];
    float4 bv = *(const float4*)&beta[c4];
    float4 hv = ((const float4*)&d_h[(size_t)w * CC])[lane];
    float mk = d_mask[w];
    float4 hn;
    hn.x = mk * (gv.x * (cv.x - av.x * mv.x) * rsqrtf(vv.x + EPSN) + bv.x + hv.x);
    hn.y = mk * (gv.y * (cv.y - av.y * mv.y) * rsqrtf(vv.y + EPSN) + bv.y + hv.y);
    hn.z = mk * (gv.z * (cv.z - av.z * mv.z) * rsqrtf(vv.z + EPSN) + bv.z + hv.z);
    hn.w = mk * (gv.w * (cv.w - av.w * mv.w) * rsqrtf(vv.w + EPSN) + bv.w + hv.w);
    // write new h
    ((float4*)&d_h[(size_t)w * CC])[lane] = hn;
    // next layer's mask
    float4 wv = ((const float4*)&WmI_next[g * CC])[lane];
    float p = hn.x * wv.x + hn.y * wv.y + hn.z * wv.z + hn.w * wv.w;
    p = warpRedSum(p);
    float mk2 = 1.0f / (1.0f + expf(-p * INV_SQRT_C));
    if (lane == 0) d_mask[w] = mk2;
    __nv_bfloat162* o = (__nv_bfloat162*)&b_xin[(size_t)w * CC];
    o[lane * 2] = __floats2bfloat162_rn(mk2 * hn.x, mk2 * hn.y);
    o[lane * 2 + 1] = __floats2bfloat162_rn(mk2 * hn.z, mk2 * hn.w);
}

// ---------------- launch ----------------
extern "C" void kernel_launch(void* const* d_in, const int* in_sizes, int n_in,
                              void* d_out, int out_size) {
    const float* x = (const float*)d_in[0];
    const int* eidx = (const int*)d_in[1];
    const float* instr = (const float*)d_in[2];
    // d_in[3] = global_language_feats (unused by reference)
    const float* eattr = (const float*)d_in[4];
    const int* batch = (const int*)d_in[5];
    const float* Wl = (const float*)d_in[6];
    const float* Wr = (const float*)d_in[7];
    const float* We = (const float*)d_in[8];
    const float* att = (const float*)d_in[9];
    const float* Wm = (const float*)d_in[10];
    const float* p1w = (const float*)d_in[11];
    const float* p1b = (const float*)d_in[12];
    const float* p2w = (const float*)d_in[13];
    const float* p2b = (const float*)d_in[14];
    const float* gng = (const float*)d_in[15];
    const float* gnb = (const float*)d_in[16];
    const float* gna = (const float*)d_in[17];
    const int* src = eidx;
    const int* dst = eidx + EE;
    float* outp = (float*)d_out;

    cudaFuncSetAttribute(bgemm_k<0, 1, 0>, cudaFuncAttributeMaxDynamicSharedMemorySize, BGEMM_SMEM_SDPA);
    cudaFuncSetAttribute(bgemm_k<1, 1, 0>, cudaFuncAttributeMaxDynamicSharedMemorySize, BGEMM_SMEM_SDPA);
    cudaFuncSetAttribute(bgemm_k<1, 0, 1>, cudaFuncAttributeMaxDynamicSharedMemorySize, BGEMM_SMEM_SDPA);
    cudaFuncSetAttribute(bscore_k, cudaFuncAttributeMaxDynamicSharedMemorySize, SCORE_SMEM);

    int* pdeg; cudaGetSymbolAddress((void**)&pdeg, g_deg);
    int* pfill; cudaGetSymbolAddress((void**)&pfill, g_fill);
    float* pcnt; cudaGetSymbolAddress((void**)&pcnt, g_cntf);
    float* ph; cudaGetSymbolAddress((void**)&ph, d_h);
    float* pWmI; cudaGetSymbolAddress((void**)&pWmI, g_WmI);

    __nv_bfloat16* pxin; cudaGetSymbolAddress((void**)&pxin, b_xin);
    __nv_bfloat16* peattr; cudaGetSymbolAddress((void**)&peattr, b_eattr);
    __nv_bfloat16* pxlr; cudaGetSymbolAddress((void**)&pxlr, b_xlr);
    __nv_bfloat16* pout; cudaGetSymbolAddress((void**)&pout, b_out);
    __nv_bfloat16* pcr1; cudaGetSymbolAddress((void**)&pcr1, b_cr1);
    __nv_bfloat16* pwtlr; cudaGetSymbolAddress((void**)&pwtlr, b_wtlr);
    __nv_bfloat16* pwte; cudaGetSymbolAddress((void**)&pwte, b_wte);
    __nv_bfloat16* pwtp1; cudaGetSymbolAddress((void**)&pwtp1, b_wtp1);
    __nv_bfloat16* pwtp2; cudaGetSymbolAddress((void**)&pwtp2, b_wtp2);
    float* pcr; cudaGetSymbolAddress((void**)&pcr, g_cr);

    const int NB256 = (NN + 255) / 256;       // 196
    const int EB256 = (EE + 255) / 256;

    // ---- startup (runs every replay; deterministic) ----
    k_zero_int<<<NB256, 256>>>(pdeg, NN);
    k_zero_int<<<NB256, 256>>>(pfill, NN);
    k_zero_float<<<1, 64>>>(pcnt, GG);
    k_deg<<<EB256, 256>>>(dst);
    k_scanA<<<NB256, 256>>>();
    k_scanB<<<1, 32>>>(NB256);
    k_scanC<<<(NN + 255) / 256, 256>>>();
    k_scatter<<<EB256, 256>>>(src, dst);
    k_permute_eattr<<<(EE * 32 + 255) / 256, 256>>>(eattr);
    k_cnt<<<NB256, 256>>>(batch);
    k_copy4<<<((NN * CC / 4) + 255) / 256, 256>>>(ph, x, NN * CC / 4);
    k_wmI_all<<<dim3(GG, LL), CC>>>(Wm, instr);
    // weight transpose+convert (all layers)
    k_wt2<<<dim3((CC * HC + 255) / 256, LL), 256>>>(Wl, pwtlr, CC, HC, 1024 * CC, 0);
    k_wt2<<<dim3((CC * HC + 255) / 256, LL), 256>>>(Wr, pwtlr, CC, HC, 1024 * CC, 512);
    k_wt2<<<dim3((CC * HC + 255) / 256, LL), 256>>>(We, pwte, CC, HC, HC * CC, 0);
    k_wt2<<<dim3((HC * MIDD + 255) / 256, LL), 256>>>(p1w, pwtp1, HC, MIDD, MIDD * HC, 0);
    k_wt2<<<dim3((MIDD * CC + 255) / 256, LL), 256>>>(p2w, pwtp2, MIDD, CC, CC * MIDD, 0);

    // layer 0 mask
    k_mask_xin<<<(NN * 32 + 255) / 256, 256>>>(batch, pWmI);

    for (int i = 0; i < LL; i++) {
        const float* instr_i = instr + (size_t)i * GG * CC;
        const float* att_i = att + (size_t)i * HH * CC;
        const float* p1b_i = p1b + (size_t)i * MIDD;
        const float* p2b_i = p2b + (size_t)i * CC;
        const float* gng_i = gng + (size_t)i * CC;
        const float* gnb_i = gnb + (size_t)i * CC;
        const float* gna_i = gna + (size_t)i * CC;
        __nv_bfloat16* wtlr_i = pwtlr + (size_t)i * 1024 * CC;
        __nv_bfloat16* wte_i = pwte + (size_t)i * HC * CC;
        __nv_bfloat16* wtp1_i = pwtp1 + (size_t)i * MIDD * HC;
        __nv_bfloat16* wtp2_i = pwtp2 + (size_t)i * CC * MIDD;

        // combined xl+xr projection (one GEMM, Nn=1024)
        dim3 gxlr(1024 / 128, (NN + 127) / 128);
        bgemm_k<0, 1, 0><<<gxlr, 256, BGEMM_SMEM_SDPA>>>(pxin, wtlr_i, nullptr, pxlr,
                                                         NN, 1024, CC, nullptr, nullptr);

        // fused edge GEMM + attention score (A-resident, 4-head loop)
        bscore_k<<<EE / 128, 256, SCORE_SMEM>>>(peattr, wte_i, att_i);

        // attention softmax + aggregation (deferred normalization)
        k_edge_softmax<<<(NN * 32 + 255) / 256, 256>>>();
        k_aggregate<<<NN, 128>>>();

        // graph-scope init BEFORE MLP2 (sdpa atomics live in its epilogue)
        k_init_graph<<<(GG * CC + 255) / 256, 256>>>();

        // MLP (bf16 tensor cores); MLP2 outputs fp32 g_cr + fused sdpa score
        dim3 gp1(MIDD / 128, (NN + 127) / 128);
        bgemm_k<1, 1, 0><<<gp1, 256, BGEMM_SMEM_SDPA>>>(pout, wtp1_i, p1b_i, pcr1,
                                                        NN, MIDD, HC, nullptr, nullptr);
        dim3 gp2(CC / 128, (NN + 127) / 128);
        bgemm_k<1, 0, 1><<<gp2, 256, BGEMM_SMEM_SDPA>>>(pcr1, wtp2_i, p2b_i, pcr,
                                                        NN, CC, MIDD, batch, instr_i);

        // scatter attention + GraphNorm
        k_sdpa_exp<<<NB256, 256>>>(batch);
        k_scale_mean<<<(NN + 63) / 64, 128>>>(batch);
        k_mean_div<<<(GG * CC + 255) / 256, 256>>>();
        k_var_acc<<<(NN + 63) / 64, 128>>>(batch, gna_i);
        k_var_div<<<(GG * CC + 255) / 256, 256>>>();

        if (i == LL - 1) {
            k_norm_resid<<<(NN * CC + 255) / 256, 256>>>(batch, gna_i, gng_i, gnb_i, outp);
        } else {
            const float* WmI_next = pWmI + (size_t)(i + 1) * GG * CC;
            k_norm_mask<<<(NN * 32 + 255) / 256, 256>>>(batch, gna_i, gng_i, gnb_i, WmI_next);
        }
    }
    (void)in_sizes; (void)n_in; (void)out_size;
}